// round 7
// baseline (speedup 1.0000x reference)
#include <cuda_runtime.h>
#include <cuda_bf16.h>
#include <math_constants.h>
#include <cstdint>

#define S_LEN  2048
#define HIDDEN 4096
#define NH     32
#define NKV    8
#define HD     96
#define GROUPS 4
#define QDIM   (NH * HD)    // 3072
#define KVDIM  (NKV * HD)   // 768
#define DFULL  128
#define ATT_SCALE 0.08838834764831845f  // 128^-0.5

// ---------------- scratch (allocation-free: device globals) ----------------
static __device__ __align__(256) float g_Q [S_LEN * QDIM];
static __device__ __align__(256) float g_K [S_LEN * KVDIM];
static __device__ __align__(256) float g_V [S_LEN * KVDIM];

// plain hi/lo bf16 splits of GEMM operands
static __device__ __align__(256) __nv_bfloat16 g_hsh[S_LEN * HIDDEN];
static __device__ __align__(256) __nv_bfloat16 g_hsl[S_LEN * HIDDEN];
static __device__ __align__(256) __nv_bfloat16 g_wqh[QDIM * HIDDEN];
static __device__ __align__(256) __nv_bfloat16 g_wql[QDIM * HIDDEN];
static __device__ __align__(256) __nv_bfloat16 g_wkh[KVDIM * HIDDEN];
static __device__ __align__(256) __nv_bfloat16 g_wkl[KVDIM * HIDDEN];
static __device__ __align__(256) __nv_bfloat16 g_wvh[KVDIM * HIDDEN];
static __device__ __align__(256) __nv_bfloat16 g_wvl[KVDIM * HIDDEN];
static __device__ __align__(256) __nv_bfloat16 g_woh[HIDDEN * QDIM];
static __device__ __align__(256) __nv_bfloat16 g_wol[HIDDEN * QDIM];
static __device__ __align__(256) __nv_bfloat16 g_aoh[S_LEN * QDIM];
static __device__ __align__(256) __nv_bfloat16 g_aol[S_LEN * QDIM];

// flash operands (hi/lo bf16 splits)
static __device__ __align__(256) __nv_bfloat16 g_Qh[S_LEN * QDIM];
static __device__ __align__(256) __nv_bfloat16 g_Ql[S_LEN * QDIM];
static __device__ __align__(256) __nv_bfloat16 g_Kh[S_LEN * KVDIM];
static __device__ __align__(256) __nv_bfloat16 g_Kl[S_LEN * KVDIM];
static __device__ __align__(256) __nv_bfloat16 g_Vh[S_LEN * KVDIM];
static __device__ __align__(256) __nv_bfloat16 g_Vl[S_LEN * KVDIM];

// ---------------------------------------------------------------------------
// PTX helpers
// ---------------------------------------------------------------------------
__device__ __forceinline__ uint32_t smem_u32(const void* p) {
    uint32_t a;
    asm("{ .reg .u64 t; cvta.to.shared.u64 t, %1; cvt.u32.u64 %0, t; }" : "=r"(a) : "l"(p));
    return a;
}
#define CP_ASYNC16(dst, src) asm volatile("cp.async.cg.shared.global [%0], [%1], 16;" :: "r"(dst), "l"(src))
#define CP_COMMIT()          asm volatile("cp.async.commit_group;" ::: "memory")
#define CP_WAIT(n)           asm volatile("cp.async.wait_group %0;" :: "n"(n) : "memory")

#define LDSM_X4(r0, r1, r2, r3, addr)                                            \
    asm volatile("ldmatrix.sync.aligned.m8n8.x4.shared.b16 {%0,%1,%2,%3}, [%4];" \
        : "=r"(r0), "=r"(r1), "=r"(r2), "=r"(r3) : "r"(addr))

#define LDSM_X4_T(r0, r1, r2, r3, addr)                                                \
    asm volatile("ldmatrix.sync.aligned.m8n8.x4.trans.shared.b16 {%0,%1,%2,%3}, [%4];" \
        : "=r"(r0), "=r"(r1), "=r"(r2), "=r"(r3) : "r"(addr))

__device__ __forceinline__ void mma_bf16(float* c, uint32_t a0, uint32_t a1,
                                         uint32_t a2, uint32_t a3,
                                         uint32_t b0, uint32_t b1) {
    asm volatile(
        "mma.sync.aligned.m16n8k16.row.col.f32.bf16.bf16.f32 "
        "{%0,%1,%2,%3}, {%4,%5,%6,%7}, {%8,%9}, {%0,%1,%2,%3};"
        : "+f"(c[0]), "+f"(c[1]), "+f"(c[2]), "+f"(c[3])
        : "r"(a0), "r"(a1), "r"(a2), "r"(a3), "r"(b0), "r"(b1));
}

// ---------------------------------------------------------------------------
// bf16 HMMA GEMM with 3-pass hi/lo compensation (no duplicated storage):
//   pass 0: Ah*Bh, pass 1: Al*Bh, pass 2: Ah*Bl  — accumulated in fp32.
// BM=256, BN=128, BK=64, 3-stage cp.async pipeline, 8 warps, warp tile 64x64.
// Register double-buffered ldmatrix across ks steps.
// Segmented over N (up to 3 B/C segments sharing A).
// ---------------------------------------------------------------------------
#define BM 256
#define BN 128
#define BKE 64
#define ROW_B 144
#define A_BYTES (BM * ROW_B)
#define B_BYTES (BN * ROW_B)
#define STAGE_BYTES (A_BYTES + B_BYTES)
#define NSTAGE 3
#define GEMM_SMEM (NSTAGE * STAGE_BYTES)   // 165888

__device__ __forceinline__ void load_tiles(uint32_t stage_base,
    const __nv_bfloat16* __restrict__ Ap, const __nv_bfloat16* __restrict__ Bp,
    int bm, int bn, int kc, int K, int tid)
{
    const char* Ag = (const char*)(Ap + (size_t)bm * K + kc * BKE);
    const char* Bg = (const char*)(Bp + (size_t)bn * K + kc * BKE);
    const size_t rowb = (size_t)K * 2;
    const uint32_t sA = stage_base;
    const uint32_t sB = stage_base + A_BYTES;
#pragma unroll
    for (int i = 0; i < 8; i++) {
        int idx = tid + i * 256;
        int row = idx >> 3, seg = idx & 7;
        CP_ASYNC16(sA + row * ROW_B + seg * 16, Ag + (size_t)row * rowb + seg * 16);
    }
#pragma unroll
    for (int i = 0; i < 4; i++) {
        int idx = tid + i * 256;
        int row = idx >> 3, seg = idx & 7;
        CP_ASYNC16(sB + row * ROW_B + seg * 16, Bg + (size_t)row * rowb + seg * 16);
    }
}

__global__ __launch_bounds__(256) void gemm_mma(
    const __nv_bfloat16* __restrict__ Ah, const __nv_bfloat16* __restrict__ Al,
    const __nv_bfloat16* __restrict__ B0h, const __nv_bfloat16* __restrict__ B0l,
    float* __restrict__ C0, int nt0, int N0,
    const __nv_bfloat16* __restrict__ B1h, const __nv_bfloat16* __restrict__ B1l,
    float* __restrict__ C1, int nt1, int N1,
    const __nv_bfloat16* __restrict__ B2h, const __nv_bfloat16* __restrict__ B2l,
    float* __restrict__ C2, int N2,
    int K)
{
    extern __shared__ char smem[];
    const uint32_t sbase = smem_u32(smem);
    const int tid  = threadIdx.x;
    const int wid  = tid >> 5;
    const int lane = tid & 31;
    const int bm   = blockIdx.y * BM;
    const int NCK  = K / BKE;          // chunks per pass
    const int NC   = 3 * NCK;          // total chunks

    int bnt = blockIdx.x;
    const __nv_bfloat16 *Bh, *Bl;
    float* C; int N;
    if (bnt < nt0)            { Bh = B0h; Bl = B0l; C = C0; N = N0; }
    else if (bnt < nt0 + nt1) { Bh = B1h; Bl = B1l; C = C1; N = N1; bnt -= nt0; }
    else                      { Bh = B2h; Bl = B2l; C = C2; N = N2; bnt -= nt0 + nt1; }
    const int bn = bnt * BN;

    const int wm = (wid >> 1) * 64;
    const int wn = (wid & 1) * 64;

    float acc[4][8][4];
#pragma unroll
    for (int t = 0; t < 4; t++)
#pragma unroll
        for (int j = 0; j < 8; j++)
#pragma unroll
            for (int q = 0; q < 4; q++) acc[t][j][q] = 0.f;

    const int a_row    = ((lane >> 3) & 1) * 8 + (lane & 7);
    const int a_cshift = ((lane >> 4) & 1) * 16;
    const int b_row    = ((lane >> 4) & 1) * 8 + (lane & 7);
    const int b_cshift = ((lane >> 3) & 1) * 16;

    // chunk -> (pass, kc) pointer select
    auto selA = [&](int c) { return (c >= NCK && c < 2 * NCK) ? Al : Ah; };
    auto selB = [&](int c) { return (c >= 2 * NCK) ? Bl : Bh; };
    auto kcof = [&](int c) { int p = c / NCK; return c - p * NCK; };

    load_tiles(sbase,               selA(0), selB(0), bm, bn, kcof(0), K, tid); CP_COMMIT();
    load_tiles(sbase + STAGE_BYTES, selA(1), selB(1), bm, bn, kcof(1), K, tid); CP_COMMIT();

    for (int c = 0; c < NC; c++) {
        CP_WAIT(1);
        __syncthreads();

        if (c + 2 < NC)
            load_tiles(sbase + ((c + 2) % NSTAGE) * STAGE_BYTES,
                       selA(c + 2), selB(c + 2), bm, bn, kcof(c + 2), K, tid);
        CP_COMMIT();

        const uint32_t sA = sbase + (c % NSTAGE) * STAGE_BYTES;
        const uint32_t sB = sA + A_BYTES;

        // register double-buffered ks pipeline
        uint32_t af[2][4][4], bfr[2][4][4];
#pragma unroll
        for (int t = 0; t < 4; t++)
            LDSM_X4(af[0][t][0], af[0][t][1], af[0][t][2], af[0][t][3],
                    sA + (wm + t * 16 + a_row) * ROW_B + a_cshift);
#pragma unroll
        for (int p = 0; p < 4; p++)
            LDSM_X4(bfr[0][p][0], bfr[0][p][1], bfr[0][p][2], bfr[0][p][3],
                    sB + (wn + p * 16 + b_row) * ROW_B + b_cshift);

#pragma unroll
        for (int ks = 0; ks < 4; ks++) {
            const int cur = ks & 1, nxt = cur ^ 1;
            if (ks < 3) {
#pragma unroll
                for (int t = 0; t < 4; t++)
                    LDSM_X4(af[nxt][t][0], af[nxt][t][1], af[nxt][t][2], af[nxt][t][3],
                            sA + (wm + t * 16 + a_row) * ROW_B + (ks + 1) * 32 + a_cshift);
#pragma unroll
                for (int p = 0; p < 4; p++)
                    LDSM_X4(bfr[nxt][p][0], bfr[nxt][p][1], bfr[nxt][p][2], bfr[nxt][p][3],
                            sB + (wn + p * 16 + b_row) * ROW_B + (ks + 1) * 32 + b_cshift);
            }
#pragma unroll
            for (int p = 0; p < 4; p++)
#pragma unroll
                for (int t = 0; t < 4; t++) {
                    mma_bf16(acc[t][2 * p],     af[cur][t][0], af[cur][t][1],
                             af[cur][t][2], af[cur][t][3], bfr[cur][p][0], bfr[cur][p][1]);
                    mma_bf16(acc[t][2 * p + 1], af[cur][t][0], af[cur][t][1],
                             af[cur][t][2], af[cur][t][3], bfr[cur][p][2], bfr[cur][p][3]);
                }
        }
    }

#pragma unroll
    for (int t = 0; t < 4; t++) {
        const int r0 = bm + wm + t * 16 + (lane >> 2);
#pragma unroll
        for (int j = 0; j < 8; j++) {
            const int col = bn + wn + j * 8 + (lane & 3) * 2;
            float* c0 = C + (size_t)r0 * N + col;
            float* c1 = C + (size_t)(r0 + 8) * N + col;
            *(float2*)c0 = make_float2(acc[t][j][0], acc[t][j][1]);
            *(float2*)c1 = make_float2(acc[t][j][2], acc[t][j][3]);
        }
    }
}

// ---------------------------------------------------------------------------
// fp32 -> plain hi/lo bf16 split, pair-vectorized.
// ---------------------------------------------------------------------------
__global__ void split2v(const float* __restrict__ X,
                        __nv_bfloat16* __restrict__ Xh, __nv_bfloat16* __restrict__ Xl,
                        int totalPairs)
{
    int t = blockIdx.x * blockDim.x + threadIdx.x;
    if (t >= totalPairs) return;
    float2 x = ((const float2*)X)[t];
    __nv_bfloat162 h = __floats2bfloat162_rn(x.x, x.y);
    __nv_bfloat162 l = __floats2bfloat162_rn(x.x - __bfloat162float(h.x),
                                             x.y - __bfloat162float(h.y));
    ((uint32_t*)Xh)[t] = *(uint32_t*)&h;
    ((uint32_t*)Xl)[t] = *(uint32_t*)&l;
}

// ---------------------------------------------------------------------------
// Indexed RoPE + hi/lo bf16 split (for flash operands). X: [S, nheads*HD] fp32.
// ---------------------------------------------------------------------------
__global__ void rope_split(const float* __restrict__ X,
                           __nv_bfloat16* __restrict__ Xh, __nv_bfloat16* __restrict__ Xl,
                           const float* __restrict__ cosT, const float* __restrict__ sinT,
                           const int* __restrict__ idx,
                           int nheads, int group, float scale, int total)
{
    int t = blockIdx.x * blockDim.x + threadIdx.x;
    if (t >= total) return;
    int d = t % 48;
    int h = (t / 48) % nheads;
    int s = t / (48 * nheads);
    int hk = h / group;

    const float* base = X + (size_t)s * (nheads * HD) + h * HD;
    float x1 = base[d];
    float x2 = base[d + 48];

    int i1 = idx[hk * HD + d];
    int i2 = idx[hk * HD + d + 48];
    float c1 = cosT[s * DFULL + i1], s1 = sinT[s * DFULL + i1];
    float c2 = cosT[s * DFULL + i2], s2 = sinT[s * DFULL + i2];

    float lo = (x1 * c1 - x2 * s1) * scale;
    float hi = (x2 * c2 + x1 * s2) * scale;

    size_t o = (size_t)s * (nheads * HD) + h * HD;
    __nv_bfloat16 bh = __float2bfloat16(lo);
    Xh[o + d] = bh;
    Xl[o + d] = __float2bfloat16(lo - __bfloat162float(bh));
    bh = __float2bfloat16(hi);
    Xh[o + d + 48] = bh;
    Xl[o + d + 48] = __float2bfloat16(hi - __bfloat162float(bh));
}

// ---------------------------------------------------------------------------
// HMMA flash attention, causal GQA. CTA = 128 q-rows x 1 head, 8 warps.
// 64-key blocks, double-buffered cp.async KV stages.
// 3-term split MMAs: S = QhKh + QlKh + QhKl;  O += PhVh + PlVh + PhVl.
// Epilogue writes plain AOh / AOl bf16.
// ---------------------------------------------------------------------------
#define FD   96
#define FBM  128
#define FBN  64
#define FROW 208
#define FQ_BYTES  (FBM * FROW)
#define FKV_BYTES (FBN * FROW)
#define STG_BYTES (4 * FKV_BYTES)
#define FLASH_SMEM (2 * FQ_BYTES + 2 * STG_BYTES)

__device__ __forceinline__ void flash_load_kv(uint32_t st_base,
    const __nv_bfloat16* Kh, const __nv_bfloat16* Kl,
    const __nv_bfloat16* Vh, const __nv_bfloat16* Vl,
    int key0, int hk, int tid)
{
    const size_t goff = (size_t)key0 * (KVDIM * 2) + hk * (FD * 2);
    const char* g0 = (const char*)Kh + goff;
    const char* g1 = (const char*)Kl + goff;
    const char* g2 = (const char*)Vh + goff;
    const char* g3 = (const char*)Vl + goff;
#pragma unroll
    for (int i = 0; i < 3; i++) {
        int idx = tid + i * 256;
        int row = idx / 12, seg = idx - row * 12;
        uint32_t d = st_base + row * FROW + seg * 16;
        size_t go = (size_t)row * (KVDIM * 2) + seg * 16;
        CP_ASYNC16(d,                 g0 + go);
        CP_ASYNC16(d +     FKV_BYTES, g1 + go);
        CP_ASYNC16(d + 2 * FKV_BYTES, g2 + go);
        CP_ASYNC16(d + 3 * FKV_BYTES, g3 + go);
    }
}

__global__ __launch_bounds__(256, 1) void flash_mma(
    const __nv_bfloat16* __restrict__ Qh, const __nv_bfloat16* __restrict__ Ql,
    const __nv_bfloat16* __restrict__ Kh, const __nv_bfloat16* __restrict__ Kl,
    const __nv_bfloat16* __restrict__ Vh, const __nv_bfloat16* __restrict__ Vl,
    __nv_bfloat16* __restrict__ AOh, __nv_bfloat16* __restrict__ AOl)
{
    extern __shared__ char smem[];
    const uint32_t sb = smem_u32(smem);
    const int tid = threadIdx.x, wid = tid >> 5, lane = tid & 31;
    const int h = blockIdx.y, hk = h / GROUPS;
    const int qbase = ((int)gridDim.x - 1 - (int)blockIdx.x) * FBM;  // heavy first
    const int nb = qbase / FBN + 2;

    const uint32_t sQh_ = sb, sQl_ = sb + FQ_BYTES;
    const uint32_t st0 = sb + 2 * FQ_BYTES;

    {
        const char* gqh = (const char*)(Qh + (size_t)qbase * QDIM + h * FD);
        const char* gql = (const char*)(Ql + (size_t)qbase * QDIM + h * FD);
#pragma unroll
        for (int i = 0; i < 6; i++) {
            int idx = tid + i * 256;
            int row = idx / 12, seg = idx - row * 12;
            uint32_t d = row * FROW + seg * 16;
            size_t go = (size_t)row * (QDIM * 2) + seg * 16;
            CP_ASYNC16(sQh_ + d, gqh + go);
            CP_ASYNC16(sQl_ + d, gql + go);
        }
        flash_load_kv(st0, Kh, Kl, Vh, Vl, 0, hk, tid);
        CP_COMMIT();
    }

    float oacc[12][4];
#pragma unroll
    for (int j = 0; j < 12; j++)
#pragma unroll
        for (int q = 0; q < 4; q++) oacc[j][q] = 0.f;
    float m0 = -CUDART_INF_F, m1 = -CUDART_INF_F, l0 = 0.f, l1 = 0.f;

    const int a_row = (lane & 7) + ((lane >> 3) & 1) * 8;
    const int a_cs  = ((lane >> 4) & 1) * 16;
    const int b_row = (lane & 7) + ((lane >> 4) & 1) * 8;
    const int b_cs  = ((lane >> 3) & 1) * 16;
    const int t_row = (lane & 7) + ((lane >> 3) & 1) * 8;
    const int t_cs  = ((lane >> 4) & 1) * 16;

    const int qr_lo = qbase + wid * 16;
    const int row0  = qr_lo + (lane >> 2);

    for (int kb = 0; kb < nb; kb++) {
        if (kb + 1 < nb) {
            flash_load_kv(st0 + ((kb + 1) & 1) * STG_BYTES, Kh, Kl, Vh, Vl,
                          (kb + 1) * FBN, hk, tid);
            CP_COMMIT();
            CP_WAIT(1);
        } else {
            CP_WAIT(0);
        }
        __syncthreads();

        const int key0 = kb * FBN;
        if (key0 <= qr_lo + 15) {
            const uint32_t sKh_ = st0 + (kb & 1) * STG_BYTES;
            const uint32_t sKl_ = sKh_ + FKV_BYTES;
            const uint32_t sVh_ = sKh_ + 2 * FKV_BYTES;
            const uint32_t sVl_ = sKh_ + 3 * FKV_BYTES;

            float sacc[8][4];
#pragma unroll
            for (int j = 0; j < 8; j++)
#pragma unroll
                for (int q = 0; q < 4; q++) sacc[j][q] = 0.f;

#pragma unroll
            for (int pass = 0; pass < 3; pass++) {
                const uint32_t sa = (pass == 1) ? sQl_ : sQh_;
                const uint32_t sk = (pass == 2) ? sKl_ : sKh_;
#pragma unroll
                for (int ks = 0; ks < 6; ks++) {
                    uint32_t a0, a1, a2, a3;
                    LDSM_X4(a0, a1, a2, a3,
                            sa + (wid * 16 + a_row) * FROW + ks * 32 + a_cs);
#pragma unroll
                    for (int p = 0; p < 4; p++) {
                        uint32_t b0, b1, b2, b3;
                        LDSM_X4(b0, b1, b2, b3,
                                sk + (p * 16 + b_row) * FROW + ks * 32 + b_cs);
                        mma_bf16(sacc[2 * p],     a0, a1, a2, a3, b0, b1);
                        mma_bf16(sacc[2 * p + 1], a0, a1, a2, a3, b2, b3);
                    }
                }
            }

            if (key0 + FBN - 1 > qr_lo) {
#pragma unroll
                for (int j = 0; j < 8; j++) {
                    int kcol = key0 + 8 * j + (lane & 3) * 2;
                    if (kcol     > row0)     sacc[j][0] = -CUDART_INF_F;
                    if (kcol + 1 > row0)     sacc[j][1] = -CUDART_INF_F;
                    if (kcol     > row0 + 8) sacc[j][2] = -CUDART_INF_F;
                    if (kcol + 1 > row0 + 8) sacc[j][3] = -CUDART_INF_F;
                }
            }

            float mx0 = sacc[0][0], mx1 = sacc[0][2];
#pragma unroll
            for (int j = 0; j < 8; j++) {
                mx0 = fmaxf(mx0, fmaxf(sacc[j][0], sacc[j][1]));
                mx1 = fmaxf(mx1, fmaxf(sacc[j][2], sacc[j][3]));
            }
            mx0 = fmaxf(mx0, __shfl_xor_sync(0xffffffffu, mx0, 1));
            mx0 = fmaxf(mx0, __shfl_xor_sync(0xffffffffu, mx0, 2));
            mx1 = fmaxf(mx1, __shfl_xor_sync(0xffffffffu, mx1, 1));
            mx1 = fmaxf(mx1, __shfl_xor_sync(0xffffffffu, mx1, 2));

            float mn0 = fmaxf(m0, mx0), mn1 = fmaxf(m1, mx1);
            float al0 = __expf(m0 - mn0), al1 = __expf(m1 - mn1);

            uint32_t ph[8][2], pl[8][2];
            float sum0 = 0.f, sum1 = 0.f;
#pragma unroll
            for (int j = 0; j < 8; j++) {
                float p0 = __expf(sacc[j][0] - mn0), p1 = __expf(sacc[j][1] - mn0);
                float p2 = __expf(sacc[j][2] - mn1), p3 = __expf(sacc[j][3] - mn1);
                sum0 += p0 + p1; sum1 += p2 + p3;
                __nv_bfloat162 h01 = __floats2bfloat162_rn(p0, p1);
                __nv_bfloat162 h23 = __floats2bfloat162_rn(p2, p3);
                ph[j][0] = *(uint32_t*)&h01;
                ph[j][1] = *(uint32_t*)&h23;
                __nv_bfloat162 l01 = __floats2bfloat162_rn(p0 - __bfloat162float(h01.x),
                                                           p1 - __bfloat162float(h01.y));
                __nv_bfloat162 l23 = __floats2bfloat162_rn(p2 - __bfloat162float(h23.x),
                                                           p3 - __bfloat162float(h23.y));
                pl[j][0] = *(uint32_t*)&l01;
                pl[j][1] = *(uint32_t*)&l23;
            }
            sum0 += __shfl_xor_sync(0xffffffffu, sum0, 1);
            sum0 += __shfl_xor_sync(0xffffffffu, sum0, 2);
            sum1 += __shfl_xor_sync(0xffffffffu, sum1, 1);
            sum1 += __shfl_xor_sync(0xffffffffu, sum1, 2);

            l0 = l0 * al0 + sum0;  l1 = l1 * al1 + sum1;
            m0 = mn0;              m1 = mn1;
#pragma unroll
            for (int j = 0; j < 12; j++) {
                oacc[j][0] *= al0; oacc[j][1] *= al0;
                oacc[j][2] *= al1; oacc[j][3] *= al1;
            }

#pragma unroll
            for (int kk = 0; kk < 4; kk++) {
                uint32_t a0 = ph[2 * kk][0], a1 = ph[2 * kk][1];
                uint32_t a2 = ph[2 * kk + 1][0], a3 = ph[2 * kk + 1][1];
                uint32_t c0 = pl[2 * kk][0], c1 = pl[2 * kk][1];
                uint32_t c2 = pl[2 * kk + 1][0], c3 = pl[2 * kk + 1][1];
#pragma unroll
                for (int p = 0; p < 6; p++) {
                    uint32_t vaddr = (16 * kk + t_row) * FROW + p * 32 + t_cs;
                    uint32_t b0, b1, b2, b3;
                    LDSM_X4_T(b0, b1, b2, b3, sVh_ + vaddr);
                    mma_bf16(oacc[2 * p],     a0, a1, a2, a3, b0, b1);
                    mma_bf16(oacc[2 * p + 1], a0, a1, a2, a3, b2, b3);
                    mma_bf16(oacc[2 * p],     c0, c1, c2, c3, b0, b1);
                    mma_bf16(oacc[2 * p + 1], c0, c1, c2, c3, b2, b3);
                    LDSM_X4_T(b0, b1, b2, b3, sVl_ + vaddr);
                    mma_bf16(oacc[2 * p],     a0, a1, a2, a3, b0, b1);
                    mma_bf16(oacc[2 * p + 1], a0, a1, a2, a3, b2, b3);
                }
            }
        }
        __syncthreads();
    }

    // epilogue: normalize + hi/lo split into plain AOh/AOl
    const float inv0 = 1.f / l0, inv1 = 1.f / l1;
    const size_t o0 = (size_t)row0 * QDIM + h * FD + (lane & 3) * 2;
    const size_t o1 = (size_t)(row0 + 8) * QDIM + h * FD + (lane & 3) * 2;
#pragma unroll
    for (int j = 0; j < 12; j++) {
        float v0 = oacc[j][0] * inv0, v1 = oacc[j][1] * inv0;
        float v2 = oacc[j][2] * inv1, v3 = oacc[j][3] * inv1;
        __nv_bfloat162 h01 = __floats2bfloat162_rn(v0, v1);
        __nv_bfloat162 l01 = __floats2bfloat162_rn(v0 - __bfloat162float(h01.x),
                                                   v1 - __bfloat162float(h01.y));
        __nv_bfloat162 h23 = __floats2bfloat162_rn(v2, v3);
        __nv_bfloat162 l23 = __floats2bfloat162_rn(v2 - __bfloat162float(h23.x),
                                                   v3 - __bfloat162float(h23.y));
        *(__nv_bfloat162*)(AOh + o0 + j * 8) = h01;
        *(__nv_bfloat162*)(AOl + o0 + j * 8) = l01;
        *(__nv_bfloat162*)(AOh + o1 + j * 8) = h23;
        *(__nv_bfloat162*)(AOl + o1 + j * 8) = l23;
    }
}

// ---------------------------------------------------------------------------
extern "C" void kernel_launch(void* const* d_in, const int* in_sizes, int n_in,
                              void* d_out, int out_size)
{
    const float* hs  = (const float*)d_in[0];
    const float* cs  = (const float*)d_in[1];
    const float* sn  = (const float*)d_in[2];
    const int*   idx = (const int*)  d_in[3];
    const float* Wq  = (const float*)d_in[4];
    const float* Wk  = (const float*)d_in[5];
    const float* Wv  = (const float*)d_in[6];
    const float* Wo  = (const float*)d_in[7];
    float* out = (float*)d_out;

    float *Qb, *Kb, *Vb;
    __nv_bfloat16 *hsh, *hsl, *wqh, *wql, *wkh, *wkl, *wvh, *wvl, *woh, *wol, *aoh, *aol;
    __nv_bfloat16 *qh, *ql, *kh, *kl, *vh, *vl;
    cudaGetSymbolAddress((void**)&Qb,  g_Q);
    cudaGetSymbolAddress((void**)&Kb,  g_K);
    cudaGetSymbolAddress((void**)&Vb,  g_V);
    cudaGetSymbolAddress((void**)&hsh, g_hsh);
    cudaGetSymbolAddress((void**)&hsl, g_hsl);
    cudaGetSymbolAddress((void**)&wqh, g_wqh);
    cudaGetSymbolAddress((void**)&wql, g_wql);
    cudaGetSymbolAddress((void**)&wkh, g_wkh);
    cudaGetSymbolAddress((void**)&wkl, g_wkl);
    cudaGetSymbolAddress((void**)&wvh, g_wvh);
    cudaGetSymbolAddress((void**)&wvl, g_wvl);
    cudaGetSymbolAddress((void**)&woh, g_woh);
    cudaGetSymbolAddress((void**)&wol, g_wol);
    cudaGetSymbolAddress((void**)&aoh, g_aoh);
    cudaGetSymbolAddress((void**)&aol, g_aol);
    cudaGetSymbolAddress((void**)&qh,  g_Qh);
    cudaGetSymbolAddress((void**)&ql,  g_Ql);
    cudaGetSymbolAddress((void**)&kh,  g_Kh);
    cudaGetSymbolAddress((void**)&kl,  g_Kl);
    cudaGetSymbolAddress((void**)&vh,  g_Vh);
    cudaGetSymbolAddress((void**)&vl,  g_Vl);

    static bool attr_set = false;
    if (!attr_set) {
        cudaFuncSetAttribute(gemm_mma,  cudaFuncAttributeMaxDynamicSharedMemorySize, GEMM_SMEM);
        cudaFuncSetAttribute(flash_mma, cudaFuncAttributeMaxDynamicSharedMemorySize, FLASH_SMEM);
        attr_set = true;
    }

    // plain hi/lo splits (pair-vectorized)
    {
        int t;
        t = S_LEN * HIDDEN / 2; split2v<<<(t + 255) / 256, 256>>>(hs, hsh, hsl, t);
        t = QDIM  * HIDDEN / 2; split2v<<<(t + 255) / 256, 256>>>(Wq, wqh, wql, t);
        t = KVDIM * HIDDEN / 2; split2v<<<(t + 255) / 256, 256>>>(Wk, wkh, wkl, t);
        t = KVDIM * HIDDEN / 2; split2v<<<(t + 255) / 256, 256>>>(Wv, wvh, wvl, t);
        t = HIDDEN * QDIM  / 2; split2v<<<(t + 255) / 256, 256>>>(Wo, woh, wol, t);
    }

    // fused QKV projection (3-pass compensated bf16)
    gemm_mma<<<dim3(36, S_LEN / BM), 256, GEMM_SMEM>>>(
        hsh, hsl,
        wqh, wql, Qb, QDIM / BN,  QDIM,
        wkh, wkl, Kb, KVDIM / BN, KVDIM,
        wvh, wvl, Vb,             KVDIM,
        HIDDEN);

    // RoPE + hi/lo split for flash operands (Q pre-scaled by 1/sqrt(128))
    const int totQ = S_LEN * NH  * 48;
    const int totK = S_LEN * NKV * 48;
    rope_split<<<(totQ + 255) / 256, 256>>>(Qb, qh, ql, cs, sn, idx, NH,  GROUPS, ATT_SCALE, totQ);
    rope_split<<<(totK + 255) / 256, 256>>>(Kb, kh, kl, cs, sn, idx, NKV, 1,      1.0f,      totK);
    {
        int t = S_LEN * KVDIM / 2;
        split2v<<<(t + 255) / 256, 256>>>(Vb, vh, vl, t);
    }

    // causal GQA attention (HMMA) — writes AOh/AOl directly
    flash_mma<<<dim3(S_LEN / FBM, NH), 256, FLASH_SMEM>>>(qh, ql, kh, kl, vh, vl, aoh, aol);

    // output projection -> d_out
    gemm_mma<<<dim3(HIDDEN / BN, S_LEN / BM), 256, GEMM_SMEM>>>(
        aoh, aol,
        woh, wol, out, HIDDEN / BN, HIDDEN,
        woh, wol, out, 0,           HIDDEN,
        woh, wol, out,              HIDDEN,
        QDIM);
}

// round 8
// speedup vs baseline: 1.0036x; 1.0036x over previous
#include <cuda_runtime.h>
#include <cuda_bf16.h>
#include <math_constants.h>
#include <cstdint>

#define S_LEN  2048
#define HIDDEN 4096
#define NH     32
#define NKV    8
#define HD     96
#define GROUPS 4
#define QDIM   (NH * HD)    // 3072
#define KVDIM  (NKV * HD)   // 768
#define DFULL  128
#define ATT_SCALE 0.08838834764831845f  // 128^-0.5

// ---------------- scratch (allocation-free: device globals) ----------------
static __device__ __align__(256) float g_Q [S_LEN * QDIM];
static __device__ __align__(256) float g_K [S_LEN * KVDIM];
static __device__ __align__(256) float g_V [S_LEN * KVDIM];

// plain hi/lo bf16 splits of GEMM operands
static __device__ __align__(256) __nv_bfloat16 g_hsh[S_LEN * HIDDEN];
static __device__ __align__(256) __nv_bfloat16 g_hsl[S_LEN * HIDDEN];
static __device__ __align__(256) __nv_bfloat16 g_wqh[QDIM * HIDDEN];
static __device__ __align__(256) __nv_bfloat16 g_wql[QDIM * HIDDEN];
static __device__ __align__(256) __nv_bfloat16 g_wkh[KVDIM * HIDDEN];
static __device__ __align__(256) __nv_bfloat16 g_wkl[KVDIM * HIDDEN];
static __device__ __align__(256) __nv_bfloat16 g_wvh[KVDIM * HIDDEN];
static __device__ __align__(256) __nv_bfloat16 g_wvl[KVDIM * HIDDEN];
static __device__ __align__(256) __nv_bfloat16 g_woh[HIDDEN * QDIM];
static __device__ __align__(256) __nv_bfloat16 g_wol[HIDDEN * QDIM];
static __device__ __align__(256) __nv_bfloat16 g_aoh[S_LEN * QDIM];
static __device__ __align__(256) __nv_bfloat16 g_aol[S_LEN * QDIM];

// flash operands (hi/lo bf16 splits)
static __device__ __align__(256) __nv_bfloat16 g_Qh[S_LEN * QDIM];
static __device__ __align__(256) __nv_bfloat16 g_Ql[S_LEN * QDIM];
static __device__ __align__(256) __nv_bfloat16 g_Kh[S_LEN * KVDIM];
static __device__ __align__(256) __nv_bfloat16 g_Kl[S_LEN * KVDIM];
static __device__ __align__(256) __nv_bfloat16 g_Vh[S_LEN * KVDIM];
static __device__ __align__(256) __nv_bfloat16 g_Vl[S_LEN * KVDIM];

// ---------------------------------------------------------------------------
// PTX helpers
// ---------------------------------------------------------------------------
__device__ __forceinline__ uint32_t smem_u32(const void* p) {
    uint32_t a;
    asm("{ .reg .u64 t; cvta.to.shared.u64 t, %1; cvt.u32.u64 %0, t; }" : "=r"(a) : "l"(p));
    return a;
}
#define CP_ASYNC16(dst, src) asm volatile("cp.async.cg.shared.global [%0], [%1], 16;" :: "r"(dst), "l"(src))
#define CP_COMMIT()          asm volatile("cp.async.commit_group;" ::: "memory")
#define CP_WAIT(n)           asm volatile("cp.async.wait_group %0;" :: "n"(n) : "memory")

#define LDSM_X4(r0, r1, r2, r3, addr)                                            \
    asm volatile("ldmatrix.sync.aligned.m8n8.x4.shared.b16 {%0,%1,%2,%3}, [%4];" \
        : "=r"(r0), "=r"(r1), "=r"(r2), "=r"(r3) : "r"(addr))

#define LDSM_X4_T(r0, r1, r2, r3, addr)                                                \
    asm volatile("ldmatrix.sync.aligned.m8n8.x4.trans.shared.b16 {%0,%1,%2,%3}, [%4];" \
        : "=r"(r0), "=r"(r1), "=r"(r2), "=r"(r3) : "r"(addr))

__device__ __forceinline__ void mma_bf16(float* c, uint32_t a0, uint32_t a1,
                                         uint32_t a2, uint32_t a3,
                                         uint32_t b0, uint32_t b1) {
    asm volatile(
        "mma.sync.aligned.m16n8k16.row.col.f32.bf16.bf16.f32 "
        "{%0,%1,%2,%3}, {%4,%5,%6,%7}, {%8,%9}, {%0,%1,%2,%3};"
        : "+f"(c[0]), "+f"(c[1]), "+f"(c[2]), "+f"(c[3])
        : "r"(a0), "r"(a1), "r"(a2), "r"(a3), "r"(b0), "r"(b1));
}

// ---------------------------------------------------------------------------
// bf16 HMMA GEMM with 3-pass hi/lo compensation (no duplicated storage):
//   pass 0: Ah*Bh, pass 1: Al*Bh, pass 2: Ah*Bl  — accumulated in fp32.
// BM=256, BN=128, BK=64, 3-stage cp.async pipeline, 8 warps, warp tile 64x64.
// Segmented over N (up to 3 B/C segments sharing A).
// ---------------------------------------------------------------------------
#define BM 256
#define BN 128
#define BKE 64
#define ROW_B 144
#define A_BYTES (BM * ROW_B)
#define B_BYTES (BN * ROW_B)
#define STAGE_BYTES (A_BYTES + B_BYTES)
#define NSTAGE 3
#define GEMM_SMEM (NSTAGE * STAGE_BYTES)   // 165888

__device__ __forceinline__ void load_tiles(uint32_t stage_base,
    const __nv_bfloat16* __restrict__ Ap, const __nv_bfloat16* __restrict__ Bp,
    int bm, int bn, int kc, int K, int tid)
{
    const char* Ag = (const char*)(Ap + (size_t)bm * K + kc * BKE);
    const char* Bg = (const char*)(Bp + (size_t)bn * K + kc * BKE);
    const size_t rowb = (size_t)K * 2;
    const uint32_t sA = stage_base;
    const uint32_t sB = stage_base + A_BYTES;
#pragma unroll
    for (int i = 0; i < 8; i++) {
        int idx = tid + i * 256;
        int row = idx >> 3, seg = idx & 7;
        CP_ASYNC16(sA + row * ROW_B + seg * 16, Ag + (size_t)row * rowb + seg * 16);
    }
#pragma unroll
    for (int i = 0; i < 4; i++) {
        int idx = tid + i * 256;
        int row = idx >> 3, seg = idx & 7;
        CP_ASYNC16(sB + row * ROW_B + seg * 16, Bg + (size_t)row * rowb + seg * 16);
    }
}

__global__ __launch_bounds__(256) void gemm_mma(
    const __nv_bfloat16* __restrict__ Ah, const __nv_bfloat16* __restrict__ Al,
    const __nv_bfloat16* __restrict__ B0h, const __nv_bfloat16* __restrict__ B0l,
    float* __restrict__ C0, int nt0, int N0,
    const __nv_bfloat16* __restrict__ B1h, const __nv_bfloat16* __restrict__ B1l,
    float* __restrict__ C1, int nt1, int N1,
    const __nv_bfloat16* __restrict__ B2h, const __nv_bfloat16* __restrict__ B2l,
    float* __restrict__ C2, int N2,
    int K)
{
    extern __shared__ char smem[];
    const uint32_t sbase = smem_u32(smem);
    const int tid  = threadIdx.x;
    const int wid  = tid >> 5;
    const int lane = tid & 31;
    const int bm   = blockIdx.y * BM;
    const int NCK  = K / BKE;          // chunks per pass
    const int NC   = 3 * NCK;          // total chunks

    int bnt = blockIdx.x;
    const __nv_bfloat16 *Bh, *Bl;
    float* C; int N;
    if (bnt < nt0)            { Bh = B0h; Bl = B0l; C = C0; N = N0; }
    else if (bnt < nt0 + nt1) { Bh = B1h; Bl = B1l; C = C1; N = N1; bnt -= nt0; }
    else                      { Bh = B2h; Bl = B2l; C = C2; N = N2; bnt -= nt0 + nt1; }
    const int bn = bnt * BN;

    const int wm = (wid >> 1) * 64;
    const int wn = (wid & 1) * 64;

    float acc[4][8][4];
#pragma unroll
    for (int t = 0; t < 4; t++)
#pragma unroll
        for (int j = 0; j < 8; j++)
#pragma unroll
            for (int q = 0; q < 4; q++) acc[t][j][q] = 0.f;

    const int a_row    = ((lane >> 3) & 1) * 8 + (lane & 7);
    const int a_cshift = ((lane >> 4) & 1) * 16;
    const int b_row    = ((lane >> 4) & 1) * 8 + (lane & 7);
    const int b_cshift = ((lane >> 3) & 1) * 16;

    // chunk -> (pass, kc) pointer select
    auto selA = [&](int c) { return (c >= NCK && c < 2 * NCK) ? Al : Ah; };
    auto selB = [&](int c) { return (c >= 2 * NCK) ? Bl : Bh; };
    auto kcof = [&](int c) { int p = c / NCK; return c - p * NCK; };

    load_tiles(sbase,               selA(0), selB(0), bm, bn, kcof(0), K, tid); CP_COMMIT();
    load_tiles(sbase + STAGE_BYTES, selA(1), selB(1), bm, bn, kcof(1), K, tid); CP_COMMIT();

    for (int c = 0; c < NC; c++) {
        CP_WAIT(1);
        __syncthreads();

        if (c + 2 < NC)
            load_tiles(sbase + ((c + 2) % NSTAGE) * STAGE_BYTES,
                       selA(c + 2), selB(c + 2), bm, bn, kcof(c + 2), K, tid);
        CP_COMMIT();

        const uint32_t sA = sbase + (c % NSTAGE) * STAGE_BYTES;
        const uint32_t sB = sA + A_BYTES;
#pragma unroll
        for (int ks = 0; ks < 4; ks++) {
            uint32_t a[4][4];
#pragma unroll
            for (int t = 0; t < 4; t++) {
                uint32_t addr = sA + (wm + t * 16 + a_row) * ROW_B + ks * 32 + a_cshift;
                LDSM_X4(a[t][0], a[t][1], a[t][2], a[t][3], addr);
            }
#pragma unroll
            for (int p = 0; p < 4; p++) {
                uint32_t b0, b1, b2, b3;
                uint32_t addr = sB + (wn + p * 16 + b_row) * ROW_B + ks * 32 + b_cshift;
                LDSM_X4(b0, b1, b2, b3, addr);
#pragma unroll
                for (int t = 0; t < 4; t++) {
                    mma_bf16(acc[t][2 * p],     a[t][0], a[t][1], a[t][2], a[t][3], b0, b1);
                    mma_bf16(acc[t][2 * p + 1], a[t][0], a[t][1], a[t][2], a[t][3], b2, b3);
                }
            }
        }
    }

#pragma unroll
    for (int t = 0; t < 4; t++) {
        const int r0 = bm + wm + t * 16 + (lane >> 2);
#pragma unroll
        for (int j = 0; j < 8; j++) {
            const int col = bn + wn + j * 8 + (lane & 3) * 2;
            float* c0 = C + (size_t)r0 * N + col;
            float* c1 = C + (size_t)(r0 + 8) * N + col;
            *(float2*)c0 = make_float2(acc[t][j][0], acc[t][j][1]);
            *(float2*)c1 = make_float2(acc[t][j][2], acc[t][j][3]);
        }
    }
}

// ---------------------------------------------------------------------------
// Fused fp32 -> hi/lo bf16 split over up to 5 source regions, pair-vectorized.
// ---------------------------------------------------------------------------
struct SplitJob { const float* x; __nv_bfloat16* xh; __nv_bfloat16* xl; int pairs; };

__global__ void split_all(const float* __restrict__ x0, __nv_bfloat16* xh0, __nv_bfloat16* xl0, int n0,
                          const float* __restrict__ x1, __nv_bfloat16* xh1, __nv_bfloat16* xl1, int n1,
                          const float* __restrict__ x2, __nv_bfloat16* xh2, __nv_bfloat16* xl2, int n2,
                          const float* __restrict__ x3, __nv_bfloat16* xh3, __nv_bfloat16* xl3, int n3,
                          const float* __restrict__ x4, __nv_bfloat16* xh4, __nv_bfloat16* xl4, int n4)
{
    int t = blockIdx.x * blockDim.x + threadIdx.x;
    const float* X; __nv_bfloat16 *Xh, *Xl;
    if      (t < n0)                     { X = x0; Xh = xh0; Xl = xl0; }
    else if ((t -= n0) < n1)             { X = x1; Xh = xh1; Xl = xl1; }
    else if ((t -= n1) < n2)             { X = x2; Xh = xh2; Xl = xl2; }
    else if ((t -= n2) < n3)             { X = x3; Xh = xh3; Xl = xl3; }
    else if ((t -= n3) < n4)             { X = x4; Xh = xh4; Xl = xl4; }
    else return;
    float2 x = ((const float2*)X)[t];
    __nv_bfloat162 h = __floats2bfloat162_rn(x.x, x.y);
    __nv_bfloat162 l = __floats2bfloat162_rn(x.x - __bfloat162float(h.x),
                                             x.y - __bfloat162float(h.y));
    ((uint32_t*)Xh)[t] = *(uint32_t*)&h;
    ((uint32_t*)Xl)[t] = *(uint32_t*)&l;
}

// plain hi/lo split (V)
__global__ void split2v(const float* __restrict__ X,
                        __nv_bfloat16* __restrict__ Xh, __nv_bfloat16* __restrict__ Xl,
                        int totalPairs)
{
    int t = blockIdx.x * blockDim.x + threadIdx.x;
    if (t >= totalPairs) return;
    float2 x = ((const float2*)X)[t];
    __nv_bfloat162 h = __floats2bfloat162_rn(x.x, x.y);
    __nv_bfloat162 l = __floats2bfloat162_rn(x.x - __bfloat162float(h.x),
                                             x.y - __bfloat162float(h.y));
    ((uint32_t*)Xh)[t] = *(uint32_t*)&h;
    ((uint32_t*)Xl)[t] = *(uint32_t*)&l;
}

// ---------------------------------------------------------------------------
// Indexed RoPE + hi/lo bf16 split (for flash operands). X: [S, nheads*HD] fp32.
// ---------------------------------------------------------------------------
__global__ void rope_split(const float* __restrict__ X,
                           __nv_bfloat16* __restrict__ Xh, __nv_bfloat16* __restrict__ Xl,
                           const float* __restrict__ cosT, const float* __restrict__ sinT,
                           const int* __restrict__ idx,
                           int nheads, int group, float scale, int total)
{
    int t = blockIdx.x * blockDim.x + threadIdx.x;
    if (t >= total) return;
    int d = t % 48;
    int h = (t / 48) % nheads;
    int s = t / (48 * nheads);
    int hk = h / group;

    const float* base = X + (size_t)s * (nheads * HD) + h * HD;
    float x1 = base[d];
    float x2 = base[d + 48];

    int i1 = idx[hk * HD + d];
    int i2 = idx[hk * HD + d + 48];
    float c1 = cosT[s * DFULL + i1], s1 = sinT[s * DFULL + i1];
    float c2 = cosT[s * DFULL + i2], s2 = sinT[s * DFULL + i2];

    float lo = (x1 * c1 - x2 * s1) * scale;
    float hi = (x2 * c2 + x1 * s2) * scale;

    size_t o = (size_t)s * (nheads * HD) + h * HD;
    __nv_bfloat16 bh = __float2bfloat16(lo);
    Xh[o + d] = bh;
    Xl[o + d] = __float2bfloat16(lo - __bfloat162float(bh));
    bh = __float2bfloat16(hi);
    Xh[o + d + 48] = bh;
    Xl[o + d + 48] = __float2bfloat16(hi - __bfloat162float(bh));
}

// ---------------------------------------------------------------------------
// HMMA flash attention, causal GQA. CTA = 128 q-rows x 1 head, 8 warps.
// 64-key blocks, double-buffered cp.async KV stages.
// 3-term split MMAs: S = QhKh + QlKh + QhKl;  O += PhVh + PlVh + PhVl.
// Epilogue writes plain AOh / AOl bf16.
// ---------------------------------------------------------------------------
#define FD   96
#define FBM  128
#define FBN  64
#define FROW 208
#define FQ_BYTES  (FBM * FROW)
#define FKV_BYTES (FBN * FROW)
#define STG_BYTES (4 * FKV_BYTES)
#define FLASH_SMEM (2 * FQ_BYTES + 2 * STG_BYTES)

__device__ __forceinline__ void flash_load_kv(uint32_t st_base,
    const __nv_bfloat16* Kh, const __nv_bfloat16* Kl,
    const __nv_bfloat16* Vh, const __nv_bfloat16* Vl,
    int key0, int hk, int tid)
{
    const size_t goff = (size_t)key0 * (KVDIM * 2) + hk * (FD * 2);
    const char* g0 = (const char*)Kh + goff;
    const char* g1 = (const char*)Kl + goff;
    const char* g2 = (const char*)Vh + goff;
    const char* g3 = (const char*)Vl + goff;
#pragma unroll
    for (int i = 0; i < 3; i++) {
        int idx = tid + i * 256;
        int row = idx / 12, seg = idx - row * 12;
        uint32_t d = st_base + row * FROW + seg * 16;
        size_t go = (size_t)row * (KVDIM * 2) + seg * 16;
        CP_ASYNC16(d,                 g0 + go);
        CP_ASYNC16(d +     FKV_BYTES, g1 + go);
        CP_ASYNC16(d + 2 * FKV_BYTES, g2 + go);
        CP_ASYNC16(d + 3 * FKV_BYTES, g3 + go);
    }
}

__global__ __launch_bounds__(256, 1) void flash_mma(
    const __nv_bfloat16* __restrict__ Qh, const __nv_bfloat16* __restrict__ Ql,
    const __nv_bfloat16* __restrict__ Kh, const __nv_bfloat16* __restrict__ Kl,
    const __nv_bfloat16* __restrict__ Vh, const __nv_bfloat16* __restrict__ Vl,
    __nv_bfloat16* __restrict__ AOh, __nv_bfloat16* __restrict__ AOl)
{
    extern __shared__ char smem[];
    const uint32_t sb = smem_u32(smem);
    const int tid = threadIdx.x, wid = tid >> 5, lane = tid & 31;
    const int h = blockIdx.y, hk = h / GROUPS;
    const int qbase = ((int)gridDim.x - 1 - (int)blockIdx.x) * FBM;  // heavy first
    const int nb = qbase / FBN + 2;

    const uint32_t sQh_ = sb, sQl_ = sb + FQ_BYTES;
    const uint32_t st0 = sb + 2 * FQ_BYTES;

    {
        const char* gqh = (const char*)(Qh + (size_t)qbase * QDIM + h * FD);
        const char* gql = (const char*)(Ql + (size_t)qbase * QDIM + h * FD);
#pragma unroll
        for (int i = 0; i < 6; i++) {
            int idx = tid + i * 256;
            int row = idx / 12, seg = idx - row * 12;
            uint32_t d = row * FROW + seg * 16;
            size_t go = (size_t)row * (QDIM * 2) + seg * 16;
            CP_ASYNC16(sQh_ + d, gqh + go);
            CP_ASYNC16(sQl_ + d, gql + go);
        }
        flash_load_kv(st0, Kh, Kl, Vh, Vl, 0, hk, tid);
        CP_COMMIT();
    }

    float oacc[12][4];
#pragma unroll
    for (int j = 0; j < 12; j++)
#pragma unroll
        for (int q = 0; q < 4; q++) oacc[j][q] = 0.f;
    float m0 = -CUDART_INF_F, m1 = -CUDART_INF_F, l0 = 0.f, l1 = 0.f;

    const int a_row = (lane & 7) + ((lane >> 3) & 1) * 8;
    const int a_cs  = ((lane >> 4) & 1) * 16;
    const int b_row = (lane & 7) + ((lane >> 4) & 1) * 8;
    const int b_cs  = ((lane >> 3) & 1) * 16;
    const int t_row = (lane & 7) + ((lane >> 3) & 1) * 8;
    const int t_cs  = ((lane >> 4) & 1) * 16;

    const int qr_lo = qbase + wid * 16;
    const int row0  = qr_lo + (lane >> 2);

    for (int kb = 0; kb < nb; kb++) {
        if (kb + 1 < nb) {
            flash_load_kv(st0 + ((kb + 1) & 1) * STG_BYTES, Kh, Kl, Vh, Vl,
                          (kb + 1) * FBN, hk, tid);
            CP_COMMIT();
            CP_WAIT(1);
        } else {
            CP_WAIT(0);
        }
        __syncthreads();

        const int key0 = kb * FBN;
        if (key0 <= qr_lo + 15) {
            const uint32_t sKh_ = st0 + (kb & 1) * STG_BYTES;
            const uint32_t sKl_ = sKh_ + FKV_BYTES;
            const uint32_t sVh_ = sKh_ + 2 * FKV_BYTES;
            const uint32_t sVl_ = sKh_ + 3 * FKV_BYTES;

            float sacc[8][4];
#pragma unroll
            for (int j = 0; j < 8; j++)
#pragma unroll
                for (int q = 0; q < 4; q++) sacc[j][q] = 0.f;

#pragma unroll
            for (int pass = 0; pass < 3; pass++) {
                const uint32_t sa = (pass == 1) ? sQl_ : sQh_;
                const uint32_t sk = (pass == 2) ? sKl_ : sKh_;
#pragma unroll
                for (int ks = 0; ks < 6; ks++) {
                    uint32_t a0, a1, a2, a3;
                    LDSM_X4(a0, a1, a2, a3,
                            sa + (wid * 16 + a_row) * FROW + ks * 32 + a_cs);
#pragma unroll
                    for (int p = 0; p < 4; p++) {
                        uint32_t b0, b1, b2, b3;
                        LDSM_X4(b0, b1, b2, b3,
                                sk + (p * 16 + b_row) * FROW + ks * 32 + b_cs);
                        mma_bf16(sacc[2 * p],     a0, a1, a2, a3, b0, b1);
                        mma_bf16(sacc[2 * p + 1], a0, a1, a2, a3, b2, b3);
                    }
                }
            }

            if (key0 + FBN - 1 > qr_lo) {
#pragma unroll
                for (int j = 0; j < 8; j++) {
                    int kcol = key0 + 8 * j + (lane & 3) * 2;
                    if (kcol     > row0)     sacc[j][0] = -CUDART_INF_F;
                    if (kcol + 1 > row0)     sacc[j][1] = -CUDART_INF_F;
                    if (kcol     > row0 + 8) sacc[j][2] = -CUDART_INF_F;
                    if (kcol + 1 > row0 + 8) sacc[j][3] = -CUDART_INF_F;
                }
            }

            float mx0 = sacc[0][0], mx1 = sacc[0][2];
#pragma unroll
            for (int j = 0; j < 8; j++) {
                mx0 = fmaxf(mx0, fmaxf(sacc[j][0], sacc[j][1]));
                mx1 = fmaxf(mx1, fmaxf(sacc[j][2], sacc[j][3]));
            }
            mx0 = fmaxf(mx0, __shfl_xor_sync(0xffffffffu, mx0, 1));
            mx0 = fmaxf(mx0, __shfl_xor_sync(0xffffffffu, mx0, 2));
            mx1 = fmaxf(mx1, __shfl_xor_sync(0xffffffffu, mx1, 1));
            mx1 = fmaxf(mx1, __shfl_xor_sync(0xffffffffu, mx1, 2));

            float mn0 = fmaxf(m0, mx0), mn1 = fmaxf(m1, mx1);
            float al0 = __expf(m0 - mn0), al1 = __expf(m1 - mn1);

            uint32_t ph[8][2], pl[8][2];
            float sum0 = 0.f, sum1 = 0.f;
#pragma unroll
            for (int j = 0; j < 8; j++) {
                float p0 = __expf(sacc[j][0] - mn0), p1 = __expf(sacc[j][1] - mn0);
                float p2 = __expf(sacc[j][2] - mn1), p3 = __expf(sacc[j][3] - mn1);
                sum0 += p0 + p1; sum1 += p2 + p3;
                __nv_bfloat162 h01 = __floats2bfloat162_rn(p0, p1);
                __nv_bfloat162 h23 = __floats2bfloat162_rn(p2, p3);
                ph[j][0] = *(uint32_t*)&h01;
                ph[j][1] = *(uint32_t*)&h23;
                __nv_bfloat162 l01 = __floats2bfloat162_rn(p0 - __bfloat162float(h01.x),
                                                           p1 - __bfloat162float(h01.y));
                __nv_bfloat162 l23 = __floats2bfloat162_rn(p2 - __bfloat162float(h23.x),
                                                           p3 - __bfloat162float(h23.y));
                pl[j][0] = *(uint32_t*)&l01;
                pl[j][1] = *(uint32_t*)&l23;
            }
            sum0 += __shfl_xor_sync(0xffffffffu, sum0, 1);
            sum0 += __shfl_xor_sync(0xffffffffu, sum0, 2);
            sum1 += __shfl_xor_sync(0xffffffffu, sum1, 1);
            sum1 += __shfl_xor_sync(0xffffffffu, sum1, 2);

            l0 = l0 * al0 + sum0;  l1 = l1 * al1 + sum1;
            m0 = mn0;              m1 = mn1;
#pragma unroll
            for (int j = 0; j < 12; j++) {
                oacc[j][0] *= al0; oacc[j][1] *= al0;
                oacc[j][2] *= al1; oacc[j][3] *= al1;
            }

#pragma unroll
            for (int kk = 0; kk < 4; kk++) {
                uint32_t a0 = ph[2 * kk][0], a1 = ph[2 * kk][1];
                uint32_t a2 = ph[2 * kk + 1][0], a3 = ph[2 * kk + 1][1];
                uint32_t c0 = pl[2 * kk][0], c1 = pl[2 * kk][1];
                uint32_t c2 = pl[2 * kk + 1][0], c3 = pl[2 * kk + 1][1];
#pragma unroll
                for (int p = 0; p < 6; p++) {
                    uint32_t vaddr = (16 * kk + t_row) * FROW + p * 32 + t_cs;
                    uint32_t b0, b1, b2, b3;
                    LDSM_X4_T(b0, b1, b2, b3, sVh_ + vaddr);
                    mma_bf16(oacc[2 * p],     a0, a1, a2, a3, b0, b1);
                    mma_bf16(oacc[2 * p + 1], a0, a1, a2, a3, b2, b3);
                    mma_bf16(oacc[2 * p],     c0, c1, c2, c3, b0, b1);
                    mma_bf16(oacc[2 * p + 1], c0, c1, c2, c3, b2, b3);
                    LDSM_X4_T(b0, b1, b2, b3, sVl_ + vaddr);
                    mma_bf16(oacc[2 * p],     a0, a1, a2, a3, b0, b1);
                    mma_bf16(oacc[2 * p + 1], a0, a1, a2, a3, b2, b3);
                }
            }
        }
        __syncthreads();
    }

    // epilogue: normalize + hi/lo split into plain AOh/AOl
    const float inv0 = 1.f / l0, inv1 = 1.f / l1;
    const size_t o0 = (size_t)row0 * QDIM + h * FD + (lane & 3) * 2;
    const size_t o1 = (size_t)(row0 + 8) * QDIM + h * FD + (lane & 3) * 2;
#pragma unroll
    for (int j = 0; j < 12; j++) {
        float v0 = oacc[j][0] * inv0, v1 = oacc[j][1] * inv0;
        float v2 = oacc[j][2] * inv1, v3 = oacc[j][3] * inv1;
        __nv_bfloat162 h01 = __floats2bfloat162_rn(v0, v1);
        __nv_bfloat162 l01 = __floats2bfloat162_rn(v0 - __bfloat162float(h01.x),
                                                   v1 - __bfloat162float(h01.y));
        __nv_bfloat162 h23 = __floats2bfloat162_rn(v2, v3);
        __nv_bfloat162 l23 = __floats2bfloat162_rn(v2 - __bfloat162float(h23.x),
                                                   v3 - __bfloat162float(h23.y));
        *(__nv_bfloat162*)(AOh + o0 + j * 8) = h01;
        *(__nv_bfloat162*)(AOl + o0 + j * 8) = l01;
        *(__nv_bfloat162*)(AOh + o1 + j * 8) = h23;
        *(__nv_bfloat162*)(AOl + o1 + j * 8) = l23;
    }
}

// ---------------------------------------------------------------------------
extern "C" void kernel_launch(void* const* d_in, const int* in_sizes, int n_in,
                              void* d_out, int out_size)
{
    const float* hs  = (const float*)d_in[0];
    const float* cs  = (const float*)d_in[1];
    const float* sn  = (const float*)d_in[2];
    const int*   idx = (const int*)  d_in[3];
    const float* Wq  = (const float*)d_in[4];
    const float* Wk  = (const float*)d_in[5];
    const float* Wv  = (const float*)d_in[6];
    const float* Wo  = (const float*)d_in[7];
    float* out = (float*)d_out;

    float *Qb, *Kb, *Vb;
    __nv_bfloat16 *hsh, *hsl, *wqh, *wql, *wkh, *wkl, *wvh, *wvl, *woh, *wol, *aoh, *aol;
    __nv_bfloat16 *qh, *ql, *kh, *kl, *vh, *vl;
    cudaGetSymbolAddress((void**)&Qb,  g_Q);
    cudaGetSymbolAddress((void**)&Kb,  g_K);
    cudaGetSymbolAddress((void**)&Vb,  g_V);
    cudaGetSymbolAddress((void**)&hsh, g_hsh);
    cudaGetSymbolAddress((void**)&hsl, g_hsl);
    cudaGetSymbolAddress((void**)&wqh, g_wqh);
    cudaGetSymbolAddress((void**)&wql, g_wql);
    cudaGetSymbolAddress((void**)&wkh, g_wkh);
    cudaGetSymbolAddress((void**)&wkl, g_wkl);
    cudaGetSymbolAddress((void**)&wvh, g_wvh);
    cudaGetSymbolAddress((void**)&wvl, g_wvl);
    cudaGetSymbolAddress((void**)&woh, g_woh);
    cudaGetSymbolAddress((void**)&wol, g_wol);
    cudaGetSymbolAddress((void**)&aoh, g_aoh);
    cudaGetSymbolAddress((void**)&aol, g_aol);
    cudaGetSymbolAddress((void**)&qh,  g_Qh);
    cudaGetSymbolAddress((void**)&ql,  g_Ql);
    cudaGetSymbolAddress((void**)&kh,  g_Kh);
    cudaGetSymbolAddress((void**)&kl,  g_Kl);
    cudaGetSymbolAddress((void**)&vh,  g_Vh);
    cudaGetSymbolAddress((void**)&vl,  g_Vl);

    static bool attr_set = false;
    if (!attr_set) {
        cudaFuncSetAttribute(gemm_mma,  cudaFuncAttributeMaxDynamicSharedMemorySize, GEMM_SMEM);
        cudaFuncSetAttribute(flash_mma, cudaFuncAttributeMaxDynamicSharedMemorySize, FLASH_SMEM);
        attr_set = true;
    }

    // fused hi/lo splits (one launch for hs + 4 weights)
    {
        const int n0 = S_LEN * HIDDEN / 2;
        const int n1 = QDIM  * HIDDEN / 2;
        const int n2 = KVDIM * HIDDEN / 2;
        const int n3 = KVDIM * HIDDEN / 2;
        const int n4 = HIDDEN * QDIM  / 2;
        const int tot = n0 + n1 + n2 + n3 + n4;
        split_all<<<(tot + 255) / 256, 256>>>(
            hs, hsh, hsl, n0,
            Wq, wqh, wql, n1,
            Wk, wkh, wkl, n2,
            Wv, wvh, wvl, n3,
            Wo, woh, wol, n4);
    }

    // fused QKV projection (3-pass compensated bf16)
    gemm_mma<<<dim3(36, S_LEN / BM), 256, GEMM_SMEM>>>(
        hsh, hsl,
        wqh, wql, Qb, QDIM / BN,  QDIM,
        wkh, wkl, Kb, KVDIM / BN, KVDIM,
        wvh, wvl, Vb,             KVDIM,
        HIDDEN);

    // RoPE + hi/lo split for flash operands (Q pre-scaled by 1/sqrt(128))
    const int totQ = S_LEN * NH  * 48;
    const int totK = S_LEN * NKV * 48;
    rope_split<<<(totQ + 255) / 256, 256>>>(Qb, qh, ql, cs, sn, idx, NH,  GROUPS, ATT_SCALE, totQ);
    rope_split<<<(totK + 255) / 256, 256>>>(Kb, kh, kl, cs, sn, idx, NKV, 1,      1.0f,      totK);
    {
        int t = S_LEN * KVDIM / 2;
        split2v<<<(t + 255) / 256, 256>>>(Vb, vh, vl, t);
    }

    // causal GQA attention (HMMA) — writes AOh/AOl directly
    flash_mma<<<dim3(S_LEN / FBM, NH), 256, FLASH_SMEM>>>(qh, ql, kh, kl, vh, vl, aoh, aol);

    // output projection -> d_out
    gemm_mma<<<dim3(HIDDEN / BN, S_LEN / BM), 256, GEMM_SMEM>>>(
        aoh, aol,
        woh, wol, out, HIDDEN / BN, HIDDEN,
        woh, wol, out, 0,           HIDDEN,
        woh, wol, out,              HIDDEN,
        QDIM);
}

// round 9
// speedup vs baseline: 1.0869x; 1.0830x over previous
#include <cuda_runtime.h>
#include <cuda_bf16.h>
#include <math_constants.h>
#include <cstdint>

#define S_LEN  2048
#define HIDDEN 4096
#define NH     32
#define NKV    8
#define HD     96
#define GROUPS 4
#define QDIM   (NH * HD)    // 3072
#define KVDIM  (NKV * HD)   // 768
#define DFULL  128
#define ATT_SCALE 0.08838834764831845f  // 128^-0.5

#define KP_QKV (3 * HIDDEN)   // 12288
#define KP_O   (3 * QDIM)     // 9216

// ---------------- scratch (allocation-free: device globals) ----------------
static __device__ __align__(256) float g_Q [S_LEN * QDIM];
static __device__ __align__(256) float g_K [S_LEN * KVDIM];
static __device__ __align__(256) float g_V [S_LEN * KVDIM];

static __device__ __align__(256) __nv_bfloat16 g_hsb[S_LEN * KP_QKV];   // [Ah|Al|Ah]
static __device__ __align__(256) __nv_bfloat16 g_wqb[QDIM * KP_QKV];    // [Bh|Bh|Bl]
static __device__ __align__(256) __nv_bfloat16 g_wkb[KVDIM * KP_QKV];
static __device__ __align__(256) __nv_bfloat16 g_wvb[KVDIM * KP_QKV];
static __device__ __align__(256) __nv_bfloat16 g_aob[S_LEN * KP_O];     // [hi|lo|hi]
static __device__ __align__(256) __nv_bfloat16 g_wob[HIDDEN * KP_O];

// flash operands (hi/lo bf16 splits)
static __device__ __align__(256) __nv_bfloat16 g_Qh[S_LEN * QDIM];
static __device__ __align__(256) __nv_bfloat16 g_Ql[S_LEN * QDIM];
static __device__ __align__(256) __nv_bfloat16 g_Kh[S_LEN * KVDIM];
static __device__ __align__(256) __nv_bfloat16 g_Kl[S_LEN * KVDIM];
static __device__ __align__(256) __nv_bfloat16 g_Vh[S_LEN * KVDIM];
static __device__ __align__(256) __nv_bfloat16 g_Vl[S_LEN * KVDIM];

// ---------------------------------------------------------------------------
// PTX helpers
// ---------------------------------------------------------------------------
__device__ __forceinline__ uint32_t smem_u32(const void* p) {
    uint32_t a;
    asm("{ .reg .u64 t; cvta.to.shared.u64 t, %1; cvt.u32.u64 %0, t; }" : "=r"(a) : "l"(p));
    return a;
}
#define CP_ASYNC16(dst, src) asm volatile("cp.async.cg.shared.global [%0], [%1], 16;" :: "r"(dst), "l"(src))
#define CP_COMMIT()          asm volatile("cp.async.commit_group;" ::: "memory")
#define CP_WAIT(n)           asm volatile("cp.async.wait_group %0;" :: "n"(n) : "memory")

#define LDSM_X4(r0, r1, r2, r3, addr)                                            \
    asm volatile("ldmatrix.sync.aligned.m8n8.x4.shared.b16 {%0,%1,%2,%3}, [%4];" \
        : "=r"(r0), "=r"(r1), "=r"(r2), "=r"(r3) : "r"(addr))

#define LDSM_X4_T(r0, r1, r2, r3, addr)                                                \
    asm volatile("ldmatrix.sync.aligned.m8n8.x4.trans.shared.b16 {%0,%1,%2,%3}, [%4];" \
        : "=r"(r0), "=r"(r1), "=r"(r2), "=r"(r3) : "r"(addr))

__device__ __forceinline__ void mma_bf16(float* c, uint32_t a0, uint32_t a1,
                                         uint32_t a2, uint32_t a3,
                                         uint32_t b0, uint32_t b1) {
    asm volatile(
        "mma.sync.aligned.m16n8k16.row.col.f32.bf16.bf16.f32 "
        "{%0,%1,%2,%3}, {%4,%5,%6,%7}, {%8,%9}, {%0,%1,%2,%3};"
        : "+f"(c[0]), "+f"(c[1]), "+f"(c[2]), "+f"(c[3])
        : "r"(a0), "r"(a1), "r"(a2), "r"(a3), "r"(b0), "r"(b1));
}

// ---------------------------------------------------------------------------
// bf16 HMMA GEMM over tripled-K layout (R5-proven configuration).
// BM=128, BN=128, BK=64, 3-stage cp.async pipeline, 4 warps, warp tile 64x64.
// Segmented over N (up to 3 B/C segments sharing A).
// ---------------------------------------------------------------------------
#define BM 128
#define BN 128
#define BKE 64
#define ROW_B 144
#define TILE_BYTES (128 * ROW_B)
#define STAGE_BYTES (2 * TILE_BYTES)
#define NSTAGE 3
#define GEMM_SMEM (NSTAGE * STAGE_BYTES)   // 110592

__device__ __forceinline__ void load_tiles(uint32_t stage_base,
    const __nv_bfloat16* __restrict__ A, const __nv_bfloat16* __restrict__ B,
    int bm, int bn, int kc, int Kp, int tid)
{
    const char* Ag = (const char*)(A + (size_t)bm * Kp + kc * BKE);
    const char* Bg = (const char*)(B + (size_t)bn * Kp + kc * BKE);
    const size_t rowb = (size_t)Kp * 2;
    const uint32_t sA = stage_base;
    const uint32_t sB = stage_base + TILE_BYTES;
#pragma unroll
    for (int i = 0; i < 8; i++) {
        int idx = tid + i * 128;
        int row = idx >> 3, seg = idx & 7;
        CP_ASYNC16(sA + row * ROW_B + seg * 16, Ag + (size_t)row * rowb + seg * 16);
    }
#pragma unroll
    for (int i = 0; i < 8; i++) {
        int idx = tid + i * 128;
        int row = idx >> 3, seg = idx & 7;
        CP_ASYNC16(sB + row * ROW_B + seg * 16, Bg + (size_t)row * rowb + seg * 16);
    }
}

__global__ __launch_bounds__(128) void gemm_mma(
    const __nv_bfloat16* __restrict__ A,
    const __nv_bfloat16* __restrict__ B0, float* __restrict__ C0, int nt0, int N0,
    const __nv_bfloat16* __restrict__ B1, float* __restrict__ C1, int nt1, int N1,
    const __nv_bfloat16* __restrict__ B2, float* __restrict__ C2, int N2,
    int Kp)
{
    extern __shared__ char smem[];
    const uint32_t sbase = smem_u32(smem);
    const int tid  = threadIdx.x;
    const int wid  = tid >> 5;
    const int lane = tid & 31;
    const int bm   = blockIdx.y * BM;
    const int NC   = Kp / BKE;

    int bnt = blockIdx.x;
    const __nv_bfloat16* B;
    float* C; int N;
    if (bnt < nt0)            { B = B0; C = C0; N = N0; }
    else if (bnt < nt0 + nt1) { B = B1; C = C1; N = N1; bnt -= nt0; }
    else                      { B = B2; C = C2; N = N2; bnt -= nt0 + nt1; }
    const int bn = bnt * BN;

    const int wm = (wid >> 1) * 64;
    const int wn = (wid & 1) * 64;

    float acc[4][8][4];
#pragma unroll
    for (int t = 0; t < 4; t++)
#pragma unroll
        for (int j = 0; j < 8; j++)
#pragma unroll
            for (int q = 0; q < 4; q++) acc[t][j][q] = 0.f;

    const int a_row    = ((lane >> 3) & 1) * 8 + (lane & 7);
    const int a_cshift = ((lane >> 4) & 1) * 16;
    const int b_row    = ((lane >> 4) & 1) * 8 + (lane & 7);
    const int b_cshift = ((lane >> 3) & 1) * 16;

    load_tiles(sbase,               A, B, bm, bn, 0, Kp, tid); CP_COMMIT();
    load_tiles(sbase + STAGE_BYTES, A, B, bm, bn, 1, Kp, tid); CP_COMMIT();

    for (int c = 0; c < NC; c++) {
        CP_WAIT(1);
        __syncthreads();

        if (c + 2 < NC)
            load_tiles(sbase + ((c + 2) % NSTAGE) * STAGE_BYTES, A, B, bm, bn, c + 2, Kp, tid);
        CP_COMMIT();

        const uint32_t sA = sbase + (c % NSTAGE) * STAGE_BYTES;
        const uint32_t sB = sA + TILE_BYTES;
#pragma unroll
        for (int ks = 0; ks < 4; ks++) {
            uint32_t a[4][4];
#pragma unroll
            for (int t = 0; t < 4; t++) {
                uint32_t addr = sA + (wm + t * 16 + a_row) * ROW_B + ks * 32 + a_cshift;
                LDSM_X4(a[t][0], a[t][1], a[t][2], a[t][3], addr);
            }
#pragma unroll
            for (int p = 0; p < 4; p++) {
                uint32_t b0, b1, b2, b3;
                uint32_t addr = sB + (wn + p * 16 + b_row) * ROW_B + ks * 32 + b_cshift;
                LDSM_X4(b0, b1, b2, b3, addr);
#pragma unroll
                for (int t = 0; t < 4; t++) {
                    mma_bf16(acc[t][2 * p],     a[t][0], a[t][1], a[t][2], a[t][3], b0, b1);
                    mma_bf16(acc[t][2 * p + 1], a[t][0], a[t][1], a[t][2], a[t][3], b2, b3);
                }
            }
        }
    }

#pragma unroll
    for (int t = 0; t < 4; t++) {
        const int r0 = bm + wm + t * 16 + (lane >> 2);
#pragma unroll
        for (int j = 0; j < 8; j++) {
            const int col = bn + wn + j * 8 + (lane & 3) * 2;
            float* c0 = C + (size_t)r0 * N + col;
            float* c1 = C + (size_t)(r0 + 8) * N + col;
            *(float2*)c0 = make_float2(acc[t][j][0], acc[t][j][1]);
            *(float2*)c1 = make_float2(acc[t][j][2], acc[t][j][3]);
        }
    }
}

// ---------------------------------------------------------------------------
// Fused fp32 -> tripled bf16 split over 5 regions, pair-vectorized.
// mode 0 (A side): [hi | lo | hi]; mode 1 (B side): [hi | hi | lo]
// ---------------------------------------------------------------------------
__device__ __forceinline__ void do_split(const float* X, __nv_bfloat16* Y,
                                         int t, int Cpairs, int mode)
{
    int r = t / Cpairs, c = t - r * Cpairs;
    float2 x = ((const float2*)X)[t];
    __nv_bfloat162 h = __floats2bfloat162_rn(x.x, x.y);
    __nv_bfloat162 l = __floats2bfloat162_rn(x.x - __bfloat162float(h.x),
                                             x.y - __bfloat162float(h.y));
    uint32_t* row = (uint32_t*)(Y + (size_t)r * 6 * Cpairs);
    uint32_t hv = *(uint32_t*)&h, lv = *(uint32_t*)&l;
    if (mode == 0) { row[c] = hv; row[Cpairs + c] = lv; row[2 * Cpairs + c] = hv; }
    else           { row[c] = hv; row[Cpairs + c] = hv; row[2 * Cpairs + c] = lv; }
}

__global__ void split_all(const float* __restrict__ x0, __nv_bfloat16* y0, int n0, int c0,
                          const float* __restrict__ x1, __nv_bfloat16* y1, int n1, int c1,
                          const float* __restrict__ x2, __nv_bfloat16* y2, int n2, int c2,
                          const float* __restrict__ x3, __nv_bfloat16* y3, int n3, int c3,
                          const float* __restrict__ x4, __nv_bfloat16* y4, int n4, int c4)
{
    int t = blockIdx.x * blockDim.x + threadIdx.x;
    if      (t < n0)         { do_split(x0, y0, t, c0, 0); }
    else if ((t -= n0) < n1) { do_split(x1, y1, t, c1, 1); }
    else if ((t -= n1) < n2) { do_split(x2, y2, t, c2, 1); }
    else if ((t -= n2) < n3) { do_split(x3, y3, t, c3, 1); }
    else if ((t -= n3) < n4) { do_split(x4, y4, t, c4, 1); }
}

// ---------------------------------------------------------------------------
// Fused indexed RoPE + hi/lo split for Q and K, plus V hi/lo split, one launch.
// ---------------------------------------------------------------------------
__device__ __forceinline__ void do_rope(const float* X,
                                        __nv_bfloat16* Xh, __nv_bfloat16* Xl,
                                        const float* cosT, const float* sinT,
                                        const int* idx, int nheads, int group,
                                        float scale, int t)
{
    int d = t % 48;
    int h = (t / 48) % nheads;
    int s = t / (48 * nheads);
    int hk = h / group;

    const float* base = X + (size_t)s * (nheads * HD) + h * HD;
    float x1 = base[d];
    float x2 = base[d + 48];

    int i1 = idx[hk * HD + d];
    int i2 = idx[hk * HD + d + 48];
    float c1 = cosT[s * DFULL + i1], s1 = sinT[s * DFULL + i1];
    float c2 = cosT[s * DFULL + i2], s2 = sinT[s * DFULL + i2];

    float lo = (x1 * c1 - x2 * s1) * scale;
    float hi = (x2 * c2 + x1 * s2) * scale;

    size_t o = (size_t)s * (nheads * HD) + h * HD;
    __nv_bfloat16 bh = __float2bfloat16(lo);
    Xh[o + d] = bh;
    Xl[o + d] = __float2bfloat16(lo - __bfloat162float(bh));
    bh = __float2bfloat16(hi);
    Xh[o + d + 48] = bh;
    Xl[o + d + 48] = __float2bfloat16(hi - __bfloat162float(bh));
}

__global__ void rope_split_all(
    const float* __restrict__ Qs, __nv_bfloat16* Qh, __nv_bfloat16* Ql,
    const float* __restrict__ Ks, __nv_bfloat16* Kh, __nv_bfloat16* Kl,
    const float* __restrict__ Vs, __nv_bfloat16* Vh, __nv_bfloat16* Vl,
    const float* __restrict__ cosT, const float* __restrict__ sinT,
    const int* __restrict__ idx, int totQ, int totK, int totVpairs)
{
    int t = blockIdx.x * blockDim.x + threadIdx.x;
    if (t < totQ) {
        do_rope(Qs, Qh, Ql, cosT, sinT, idx, NH, GROUPS, ATT_SCALE, t);
        return;
    }
    t -= totQ;
    if (t < totK) {
        do_rope(Ks, Kh, Kl, cosT, sinT, idx, NKV, 1, 1.0f, t);
        return;
    }
    t -= totK;
    if (t < totVpairs) {
        float2 x = ((const float2*)Vs)[t];
        __nv_bfloat162 h = __floats2bfloat162_rn(x.x, x.y);
        __nv_bfloat162 l = __floats2bfloat162_rn(x.x - __bfloat162float(h.x),
                                                 x.y - __bfloat162float(h.y));
        ((uint32_t*)Vh)[t] = *(uint32_t*)&h;
        ((uint32_t*)Vl)[t] = *(uint32_t*)&l;
    }
}

// ---------------------------------------------------------------------------
// HMMA flash attention, causal GQA. CTA = 128 q-rows x 1 head, 8 warps.
// 64-key blocks, double-buffered cp.async KV stages.
// 3-term split MMAs: S = QhKh + QlKh + QhKl;  O += PhVh + PlVh + PhVl.
// Epilogue writes AO directly in GEMM-A tripled layout [hi|lo|hi] bf16.
// ---------------------------------------------------------------------------
#define FD   96
#define FBM  128
#define FBN  64
#define FROW 208
#define FQ_BYTES  (FBM * FROW)
#define FKV_BYTES (FBN * FROW)
#define STG_BYTES (4 * FKV_BYTES)
#define FLASH_SMEM (2 * FQ_BYTES + 2 * STG_BYTES)

__device__ __forceinline__ void flash_load_kv(uint32_t st_base,
    const __nv_bfloat16* Kh, const __nv_bfloat16* Kl,
    const __nv_bfloat16* Vh, const __nv_bfloat16* Vl,
    int key0, int hk, int tid)
{
    const size_t goff = (size_t)key0 * (KVDIM * 2) + hk * (FD * 2);
    const char* g0 = (const char*)Kh + goff;
    const char* g1 = (const char*)Kl + goff;
    const char* g2 = (const char*)Vh + goff;
    const char* g3 = (const char*)Vl + goff;
#pragma unroll
    for (int i = 0; i < 3; i++) {
        int idx = tid + i * 256;
        int row = idx / 12, seg = idx - row * 12;
        uint32_t d = st_base + row * FROW + seg * 16;
        size_t go = (size_t)row * (KVDIM * 2) + seg * 16;
        CP_ASYNC16(d,                 g0 + go);
        CP_ASYNC16(d +     FKV_BYTES, g1 + go);
        CP_ASYNC16(d + 2 * FKV_BYTES, g2 + go);
        CP_ASYNC16(d + 3 * FKV_BYTES, g3 + go);
    }
}

__global__ __launch_bounds__(256, 1) void flash_mma(
    const __nv_bfloat16* __restrict__ Qh, const __nv_bfloat16* __restrict__ Ql,
    const __nv_bfloat16* __restrict__ Kh, const __nv_bfloat16* __restrict__ Kl,
    const __nv_bfloat16* __restrict__ Vh, const __nv_bfloat16* __restrict__ Vl,
    __nv_bfloat16* __restrict__ AOs)
{
    extern __shared__ char smem[];
    const uint32_t sb = smem_u32(smem);
    const int tid = threadIdx.x, wid = tid >> 5, lane = tid & 31;
    const int h = blockIdx.y, hk = h / GROUPS;
    const int qbase = ((int)gridDim.x - 1 - (int)blockIdx.x) * FBM;  // heavy first
    const int nb = qbase / FBN + 2;

    const uint32_t sQh_ = sb, sQl_ = sb + FQ_BYTES;
    const uint32_t st0 = sb + 2 * FQ_BYTES;

    {
        const char* gqh = (const char*)(Qh + (size_t)qbase * QDIM + h * FD);
        const char* gql = (const char*)(Ql + (size_t)qbase * QDIM + h * FD);
#pragma unroll
        for (int i = 0; i < 6; i++) {
            int idx = tid + i * 256;
            int row = idx / 12, seg = idx - row * 12;
            uint32_t d = row * FROW + seg * 16;
            size_t go = (size_t)row * (QDIM * 2) + seg * 16;
            CP_ASYNC16(sQh_ + d, gqh + go);
            CP_ASYNC16(sQl_ + d, gql + go);
        }
        flash_load_kv(st0, Kh, Kl, Vh, Vl, 0, hk, tid);
        CP_COMMIT();
    }

    float oacc[12][4];
#pragma unroll
    for (int j = 0; j < 12; j++)
#pragma unroll
        for (int q = 0; q < 4; q++) oacc[j][q] = 0.f;
    float m0 = -CUDART_INF_F, m1 = -CUDART_INF_F, l0 = 0.f, l1 = 0.f;

    const int a_row = (lane & 7) + ((lane >> 3) & 1) * 8;
    const int a_cs  = ((lane >> 4) & 1) * 16;
    const int b_row = (lane & 7) + ((lane >> 4) & 1) * 8;
    const int b_cs  = ((lane >> 3) & 1) * 16;
    const int t_row = (lane & 7) + ((lane >> 3) & 1) * 8;
    const int t_cs  = ((lane >> 4) & 1) * 16;

    const int qr_lo = qbase + wid * 16;
    const int row0  = qr_lo + (lane >> 2);

    for (int kb = 0; kb < nb; kb++) {
        if (kb + 1 < nb) {
            flash_load_kv(st0 + ((kb + 1) & 1) * STG_BYTES, Kh, Kl, Vh, Vl,
                          (kb + 1) * FBN, hk, tid);
            CP_COMMIT();
            CP_WAIT(1);
        } else {
            CP_WAIT(0);
        }
        __syncthreads();

        const int key0 = kb * FBN;
        if (key0 <= qr_lo + 15) {
            const uint32_t sKh_ = st0 + (kb & 1) * STG_BYTES;
            const uint32_t sKl_ = sKh_ + FKV_BYTES;
            const uint32_t sVh_ = sKh_ + 2 * FKV_BYTES;
            const uint32_t sVl_ = sKh_ + 3 * FKV_BYTES;

            float sacc[8][4];
#pragma unroll
            for (int j = 0; j < 8; j++)
#pragma unroll
                for (int q = 0; q < 4; q++) sacc[j][q] = 0.f;

#pragma unroll
            for (int pass = 0; pass < 3; pass++) {
                const uint32_t sa = (pass == 1) ? sQl_ : sQh_;
                const uint32_t sk = (pass == 2) ? sKl_ : sKh_;
#pragma unroll
                for (int ks = 0; ks < 6; ks++) {
                    uint32_t a0, a1, a2, a3;
                    LDSM_X4(a0, a1, a2, a3,
                            sa + (wid * 16 + a_row) * FROW + ks * 32 + a_cs);
#pragma unroll
                    for (int p = 0; p < 4; p++) {
                        uint32_t b0, b1, b2, b3;
                        LDSM_X4(b0, b1, b2, b3,
                                sk + (p * 16 + b_row) * FROW + ks * 32 + b_cs);
                        mma_bf16(sacc[2 * p],     a0, a1, a2, a3, b0, b1);
                        mma_bf16(sacc[2 * p + 1], a0, a1, a2, a3, b2, b3);
                    }
                }
            }

            if (key0 + FBN - 1 > qr_lo) {
#pragma unroll
                for (int j = 0; j < 8; j++) {
                    int kcol = key0 + 8 * j + (lane & 3) * 2;
                    if (kcol     > row0)     sacc[j][0] = -CUDART_INF_F;
                    if (kcol + 1 > row0)     sacc[j][1] = -CUDART_INF_F;
                    if (kcol     > row0 + 8) sacc[j][2] = -CUDART_INF_F;
                    if (kcol + 1 > row0 + 8) sacc[j][3] = -CUDART_INF_F;
                }
            }

            float mx0 = sacc[0][0], mx1 = sacc[0][2];
#pragma unroll
            for (int j = 0; j < 8; j++) {
                mx0 = fmaxf(mx0, fmaxf(sacc[j][0], sacc[j][1]));
                mx1 = fmaxf(mx1, fmaxf(sacc[j][2], sacc[j][3]));
            }
            mx0 = fmaxf(mx0, __shfl_xor_sync(0xffffffffu, mx0, 1));
            mx0 = fmaxf(mx0, __shfl_xor_sync(0xffffffffu, mx0, 2));
            mx1 = fmaxf(mx1, __shfl_xor_sync(0xffffffffu, mx1, 1));
            mx1 = fmaxf(mx1, __shfl_xor_sync(0xffffffffu, mx1, 2));

            float mn0 = fmaxf(m0, mx0), mn1 = fmaxf(m1, mx1);
            float al0 = __expf(m0 - mn0), al1 = __expf(m1 - mn1);

            uint32_t ph[8][2], pl[8][2];
            float sum0 = 0.f, sum1 = 0.f;
#pragma unroll
            for (int j = 0; j < 8; j++) {
                float p0 = __expf(sacc[j][0] - mn0), p1 = __expf(sacc[j][1] - mn0);
                float p2 = __expf(sacc[j][2] - mn1), p3 = __expf(sacc[j][3] - mn1);
                sum0 += p0 + p1; sum1 += p2 + p3;
                __nv_bfloat162 h01 = __floats2bfloat162_rn(p0, p1);
                __nv_bfloat162 h23 = __floats2bfloat162_rn(p2, p3);
                ph[j][0] = *(uint32_t*)&h01;
                ph[j][1] = *(uint32_t*)&h23;
                __nv_bfloat162 l01 = __floats2bfloat162_rn(p0 - __bfloat162float(h01.x),
                                                           p1 - __bfloat162float(h01.y));
                __nv_bfloat162 l23 = __floats2bfloat162_rn(p2 - __bfloat162float(h23.x),
                                                           p3 - __bfloat162float(h23.y));
                pl[j][0] = *(uint32_t*)&l01;
                pl[j][1] = *(uint32_t*)&l23;
            }
            sum0 += __shfl_xor_sync(0xffffffffu, sum0, 1);
            sum0 += __shfl_xor_sync(0xffffffffu, sum0, 2);
            sum1 += __shfl_xor_sync(0xffffffffu, sum1, 1);
            sum1 += __shfl_xor_sync(0xffffffffu, sum1, 2);

            l0 = l0 * al0 + sum0;  l1 = l1 * al1 + sum1;
            m0 = mn0;              m1 = mn1;
#pragma unroll
            for (int j = 0; j < 12; j++) {
                oacc[j][0] *= al0; oacc[j][1] *= al0;
                oacc[j][2] *= al1; oacc[j][3] *= al1;
            }

#pragma unroll
            for (int kk = 0; kk < 4; kk++) {
                uint32_t a0 = ph[2 * kk][0], a1 = ph[2 * kk][1];
                uint32_t a2 = ph[2 * kk + 1][0], a3 = ph[2 * kk + 1][1];
                uint32_t c0 = pl[2 * kk][0], c1 = pl[2 * kk][1];
                uint32_t c2 = pl[2 * kk + 1][0], c3 = pl[2 * kk + 1][1];
#pragma unroll
                for (int p = 0; p < 6; p++) {
                    uint32_t vaddr = (16 * kk + t_row) * FROW + p * 32 + t_cs;
                    uint32_t b0, b1, b2, b3;
                    LDSM_X4_T(b0, b1, b2, b3, sVh_ + vaddr);
                    mma_bf16(oacc[2 * p],     a0, a1, a2, a3, b0, b1);
                    mma_bf16(oacc[2 * p + 1], a0, a1, a2, a3, b2, b3);
                    mma_bf16(oacc[2 * p],     c0, c1, c2, c3, b0, b1);
                    mma_bf16(oacc[2 * p + 1], c0, c1, c2, c3, b2, b3);
                    LDSM_X4_T(b0, b1, b2, b3, sVl_ + vaddr);
                    mma_bf16(oacc[2 * p],     a0, a1, a2, a3, b0, b1);
                    mma_bf16(oacc[2 * p + 1], a0, a1, a2, a3, b2, b3);
                }
            }
        }
        __syncthreads();
    }

    // epilogue: normalize + hi/lo split directly into [hi|lo|hi] layout
    const float inv0 = 1.f / l0, inv1 = 1.f / l1;
    __nv_bfloat16* ob0 = AOs + (size_t)row0 * KP_O + h * FD + (lane & 3) * 2;
    __nv_bfloat16* ob1 = AOs + (size_t)(row0 + 8) * KP_O + h * FD + (lane & 3) * 2;
#pragma unroll
    for (int j = 0; j < 12; j++) {
        float v0 = oacc[j][0] * inv0, v1 = oacc[j][1] * inv0;
        float v2 = oacc[j][2] * inv1, v3 = oacc[j][3] * inv1;
        __nv_bfloat162 h01 = __floats2bfloat162_rn(v0, v1);
        __nv_bfloat162 l01 = __floats2bfloat162_rn(v0 - __bfloat162float(h01.x),
                                                   v1 - __bfloat162float(h01.y));
        __nv_bfloat162 h23 = __floats2bfloat162_rn(v2, v3);
        __nv_bfloat162 l23 = __floats2bfloat162_rn(v2 - __bfloat162float(h23.x),
                                                   v3 - __bfloat162float(h23.y));
        *(__nv_bfloat162*)(ob0 + j * 8)            = h01;
        *(__nv_bfloat162*)(ob0 + QDIM + j * 8)     = l01;
        *(__nv_bfloat162*)(ob0 + 2 * QDIM + j * 8) = h01;
        *(__nv_bfloat162*)(ob1 + j * 8)            = h23;
        *(__nv_bfloat162*)(ob1 + QDIM + j * 8)     = l23;
        *(__nv_bfloat162*)(ob1 + 2 * QDIM + j * 8) = h23;
    }
}

// ---------------------------------------------------------------------------
extern "C" void kernel_launch(void* const* d_in, const int* in_sizes, int n_in,
                              void* d_out, int out_size)
{
    const float* hs  = (const float*)d_in[0];
    const float* cs  = (const float*)d_in[1];
    const float* sn  = (const float*)d_in[2];
    const int*   idx = (const int*)  d_in[3];
    const float* Wq  = (const float*)d_in[4];
    const float* Wk  = (const float*)d_in[5];
    const float* Wv  = (const float*)d_in[6];
    const float* Wo  = (const float*)d_in[7];
    float* out = (float*)d_out;

    float *Qb, *Kb, *Vb;
    __nv_bfloat16 *hsb, *wqb, *wkb, *wvb, *aob, *wob;
    __nv_bfloat16 *qh, *ql, *kh, *kl, *vh, *vl;
    cudaGetSymbolAddress((void**)&Qb,  g_Q);
    cudaGetSymbolAddress((void**)&Kb,  g_K);
    cudaGetSymbolAddress((void**)&Vb,  g_V);
    cudaGetSymbolAddress((void**)&hsb, g_hsb);
    cudaGetSymbolAddress((void**)&wqb, g_wqb);
    cudaGetSymbolAddress((void**)&wkb, g_wkb);
    cudaGetSymbolAddress((void**)&wvb, g_wvb);
    cudaGetSymbolAddress((void**)&aob, g_aob);
    cudaGetSymbolAddress((void**)&wob, g_wob);
    cudaGetSymbolAddress((void**)&qh,  g_Qh);
    cudaGetSymbolAddress((void**)&ql,  g_Ql);
    cudaGetSymbolAddress((void**)&kh,  g_Kh);
    cudaGetSymbolAddress((void**)&kl,  g_Kl);
    cudaGetSymbolAddress((void**)&vh,  g_Vh);
    cudaGetSymbolAddress((void**)&vl,  g_Vl);

    static bool attr_set = false;
    if (!attr_set) {
        cudaFuncSetAttribute(gemm_mma,  cudaFuncAttributeMaxDynamicSharedMemorySize, GEMM_SMEM);
        cudaFuncSetAttribute(flash_mma, cudaFuncAttributeMaxDynamicSharedMemorySize, FLASH_SMEM);
        attr_set = true;
    }

    // fused tripled-layout splits (one launch: hs + 4 weights)
    {
        const int n0 = S_LEN * HIDDEN / 2, c0 = HIDDEN / 2;
        const int n1 = QDIM  * HIDDEN / 2, c1 = HIDDEN / 2;
        const int n2 = KVDIM * HIDDEN / 2, c2 = HIDDEN / 2;
        const int n3 = KVDIM * HIDDEN / 2, c3 = HIDDEN / 2;
        const int n4 = HIDDEN * QDIM  / 2, c4 = QDIM / 2;
        const int tot = n0 + n1 + n2 + n3 + n4;
        split_all<<<(tot + 255) / 256, 256>>>(
            hs, hsb, n0, c0,
            Wq, wqb, n1, c1,
            Wk, wkb, n2, c2,
            Wv, wvb, n3, c3,
            Wo, wob, n4, c4);
    }

    // fused QKV projection (tripled-K layout, R5-proven GEMM)
    gemm_mma<<<dim3(36, S_LEN / BM), 128, GEMM_SMEM>>>(
        hsb,
        wqb, Qb, QDIM / BN,  QDIM,
        wkb, Kb, KVDIM / BN, KVDIM,
        wvb, Vb,             KVDIM,
        KP_QKV);

    // fused RoPE+split (Q, K) + V split in one launch
    {
        const int totQ = S_LEN * NH  * 48;
        const int totK = S_LEN * NKV * 48;
        const int totV = S_LEN * KVDIM / 2;
        const int tot = totQ + totK + totV;
        rope_split_all<<<(tot + 255) / 256, 256>>>(
            Qb, qh, ql, Kb, kh, kl, Vb, vh, vl, cs, sn, idx, totQ, totK, totV);
    }

    // causal GQA attention (HMMA) — writes tripled AO layout directly
    flash_mma<<<dim3(S_LEN / FBM, NH), 256, FLASH_SMEM>>>(qh, ql, kh, kl, vh, vl, aob);

    // output projection -> d_out
    gemm_mma<<<dim3(HIDDEN / BN, S_LEN / BM), 128, GEMM_SMEM>>>(
        aob,
        wob, out, HIDDEN / BN, HIDDEN,
        wob, out, 0,           HIDDEN,
        wob, out,              HIDDEN,
        KP_O);
}

// round 10
// speedup vs baseline: 1.1169x; 1.0276x over previous
#include <cuda_runtime.h>
#include <cuda_bf16.h>
#include <math_constants.h>
#include <cstdint>

#define S_LEN  2048
#define HIDDEN 4096
#define NH     32
#define NKV    8
#define HD     96
#define GROUPS 4
#define QDIM   (NH * HD)    // 3072
#define KVDIM  (NKV * HD)   // 768
#define DFULL  128
#define ATT_SCALE 0.08838834764831845f  // 128^-0.5

#define KP_QKV (3 * HIDDEN)   // 12288
#define KP_O   (3 * QDIM)     // 9216

// ---------------- scratch (allocation-free: device globals) ----------------
static __device__ __align__(256) float g_Q [S_LEN * QDIM];
static __device__ __align__(256) float g_K [S_LEN * KVDIM];
static __device__ __align__(256) float g_V [S_LEN * KVDIM];

static __device__ __align__(256) __nv_bfloat16 g_hsb[S_LEN * KP_QKV];   // [Ah|Al|Ah]
static __device__ __align__(256) __nv_bfloat16 g_wqb[QDIM * KP_QKV];    // [Bh|Bh|Bl]
static __device__ __align__(256) __nv_bfloat16 g_wkb[KVDIM * KP_QKV];
static __device__ __align__(256) __nv_bfloat16 g_wvb[KVDIM * KP_QKV];
static __device__ __align__(256) __nv_bfloat16 g_aob[S_LEN * KP_O];     // [hi|lo|hi]
static __device__ __align__(256) __nv_bfloat16 g_wob[HIDDEN * KP_O];

// flash operands (hi/lo bf16 splits)
static __device__ __align__(256) __nv_bfloat16 g_Qh[S_LEN * QDIM];
static __device__ __align__(256) __nv_bfloat16 g_Ql[S_LEN * QDIM];
static __device__ __align__(256) __nv_bfloat16 g_Kh[S_LEN * KVDIM];
static __device__ __align__(256) __nv_bfloat16 g_Kl[S_LEN * KVDIM];
static __device__ __align__(256) __nv_bfloat16 g_Vh[S_LEN * KVDIM];
static __device__ __align__(256) __nv_bfloat16 g_Vl[S_LEN * KVDIM];

// ---------------------------------------------------------------------------
// PTX helpers
// ---------------------------------------------------------------------------
__device__ __forceinline__ uint32_t smem_u32(const void* p) {
    uint32_t a;
    asm("{ .reg .u64 t; cvta.to.shared.u64 t, %1; cvt.u32.u64 %0, t; }" : "=r"(a) : "l"(p));
    return a;
}
#define CP_ASYNC16(dst, src) asm volatile("cp.async.cg.shared.global [%0], [%1], 16;" :: "r"(dst), "l"(src))
#define CP_COMMIT()          asm volatile("cp.async.commit_group;" ::: "memory")
#define CP_WAIT(n)           asm volatile("cp.async.wait_group %0;" :: "n"(n) : "memory")

#define LDSM_X4(r0, r1, r2, r3, addr)                                            \
    asm volatile("ldmatrix.sync.aligned.m8n8.x4.shared.b16 {%0,%1,%2,%3}, [%4];" \
        : "=r"(r0), "=r"(r1), "=r"(r2), "=r"(r3) : "r"(addr))

#define LDSM_X4_T(r0, r1, r2, r3, addr)                                                \
    asm volatile("ldmatrix.sync.aligned.m8n8.x4.trans.shared.b16 {%0,%1,%2,%3}, [%4];" \
        : "=r"(r0), "=r"(r1), "=r"(r2), "=r"(r3) : "r"(addr))

__device__ __forceinline__ void mma_bf16(float* c, uint32_t a0, uint32_t a1,
                                         uint32_t a2, uint32_t a3,
                                         uint32_t b0, uint32_t b1) {
    asm volatile(
        "mma.sync.aligned.m16n8k16.row.col.f32.bf16.bf16.f32 "
        "{%0,%1,%2,%3}, {%4,%5,%6,%7}, {%8,%9}, {%0,%1,%2,%3};"
        : "+f"(c[0]), "+f"(c[1]), "+f"(c[2]), "+f"(c[3])
        : "r"(a0), "r"(a1), "r"(a2), "r"(a3), "r"(b0), "r"(b1));
}

// ---------------------------------------------------------------------------
// bf16 HMMA GEMM over tripled-K layout.
// BM=128, BN=128, BK=64, 2-stage cp.async pipeline, 4 warps, warp tile 64x64.
// NSTAGE=2 (72KB smem) + launch_bounds(128,3) -> 3 CTAs/SM, 12 warps/SM.
// Segmented over N (up to 3 B/C segments sharing A).
// ---------------------------------------------------------------------------
#define BM 128
#define BN 128
#define BKE 64
#define ROW_B 144
#define TILE_BYTES (128 * ROW_B)
#define STAGE_BYTES (2 * TILE_BYTES)
#define NSTAGE 2
#define GEMM_SMEM (NSTAGE * STAGE_BYTES)   // 73728

__device__ __forceinline__ void load_tiles(uint32_t stage_base,
    const __nv_bfloat16* __restrict__ A, const __nv_bfloat16* __restrict__ B,
    int bm, int bn, int kc, int Kp, int tid)
{
    const char* Ag = (const char*)(A + (size_t)bm * Kp + kc * BKE);
    const char* Bg = (const char*)(B + (size_t)bn * Kp + kc * BKE);
    const size_t rowb = (size_t)Kp * 2;
    const uint32_t sA = stage_base;
    const uint32_t sB = stage_base + TILE_BYTES;
#pragma unroll
    for (int i = 0; i < 8; i++) {
        int idx = tid + i * 128;
        int row = idx >> 3, seg = idx & 7;
        CP_ASYNC16(sA + row * ROW_B + seg * 16, Ag + (size_t)row * rowb + seg * 16);
    }
#pragma unroll
    for (int i = 0; i < 8; i++) {
        int idx = tid + i * 128;
        int row = idx >> 3, seg = idx & 7;
        CP_ASYNC16(sB + row * ROW_B + seg * 16, Bg + (size_t)row * rowb + seg * 16);
    }
}

__global__ __launch_bounds__(128, 3) void gemm_mma(
    const __nv_bfloat16* __restrict__ A,
    const __nv_bfloat16* __restrict__ B0, float* __restrict__ C0, int nt0, int N0,
    const __nv_bfloat16* __restrict__ B1, float* __restrict__ C1, int nt1, int N1,
    const __nv_bfloat16* __restrict__ B2, float* __restrict__ C2, int N2,
    int Kp)
{
    extern __shared__ char smem[];
    const uint32_t sbase = smem_u32(smem);
    const int tid  = threadIdx.x;
    const int wid  = tid >> 5;
    const int lane = tid & 31;
    const int bm   = blockIdx.y * BM;
    const int NC   = Kp / BKE;

    int bnt = blockIdx.x;
    const __nv_bfloat16* B;
    float* C; int N;
    if (bnt < nt0)            { B = B0; C = C0; N = N0; }
    else if (bnt < nt0 + nt1) { B = B1; C = C1; N = N1; bnt -= nt0; }
    else                      { B = B2; C = C2; N = N2; bnt -= nt0 + nt1; }
    const int bn = bnt * BN;

    const int wm = (wid >> 1) * 64;
    const int wn = (wid & 1) * 64;

    float acc[4][8][4];
#pragma unroll
    for (int t = 0; t < 4; t++)
#pragma unroll
        for (int j = 0; j < 8; j++)
#pragma unroll
            for (int q = 0; q < 4; q++) acc[t][j][q] = 0.f;

    const int a_row    = ((lane >> 3) & 1) * 8 + (lane & 7);
    const int a_cshift = ((lane >> 4) & 1) * 16;
    const int b_row    = ((lane >> 4) & 1) * 8 + (lane & 7);
    const int b_cshift = ((lane >> 3) & 1) * 16;

    // prologue: stage 0 <- chunk 0 (prefetch distance 1)
    load_tiles(sbase, A, B, bm, bn, 0, Kp, tid); CP_COMMIT();

    for (int c = 0; c < NC; c++) {
        CP_WAIT(0);            // chunk c arrived
        __syncthreads();       // all warps done computing chunk c-1 -> buffer free

        if (c + 1 < NC) {
            load_tiles(sbase + ((c + 1) & 1) * STAGE_BYTES, A, B, bm, bn, c + 1, Kp, tid);
            CP_COMMIT();
        }

        const uint32_t sA = sbase + (c & 1) * STAGE_BYTES;
        const uint32_t sB = sA + TILE_BYTES;
#pragma unroll
        for (int ks = 0; ks < 4; ks++) {
            uint32_t a[4][4];
#pragma unroll
            for (int t = 0; t < 4; t++) {
                uint32_t addr = sA + (wm + t * 16 + a_row) * ROW_B + ks * 32 + a_cshift;
                LDSM_X4(a[t][0], a[t][1], a[t][2], a[t][3], addr);
            }
#pragma unroll
            for (int p = 0; p < 4; p++) {
                uint32_t b0, b1, b2, b3;
                uint32_t addr = sB + (wn + p * 16 + b_row) * ROW_B + ks * 32 + b_cshift;
                LDSM_X4(b0, b1, b2, b3, addr);
#pragma unroll
                for (int t = 0; t < 4; t++) {
                    mma_bf16(acc[t][2 * p],     a[t][0], a[t][1], a[t][2], a[t][3], b0, b1);
                    mma_bf16(acc[t][2 * p + 1], a[t][0], a[t][1], a[t][2], a[t][3], b2, b3);
                }
            }
        }
    }

#pragma unroll
    for (int t = 0; t < 4; t++) {
        const int r0 = bm + wm + t * 16 + (lane >> 2);
#pragma unroll
        for (int j = 0; j < 8; j++) {
            const int col = bn + wn + j * 8 + (lane & 3) * 2;
            float* c0 = C + (size_t)r0 * N + col;
            float* c1 = C + (size_t)(r0 + 8) * N + col;
            *(float2*)c0 = make_float2(acc[t][j][0], acc[t][j][1]);
            *(float2*)c1 = make_float2(acc[t][j][2], acc[t][j][3]);
        }
    }
}

// ---------------------------------------------------------------------------
// Fused fp32 -> tripled bf16 split over 5 regions, pair-vectorized.
// mode 0 (A side): [hi | lo | hi]; mode 1 (B side): [hi | hi | lo]
// ---------------------------------------------------------------------------
__device__ __forceinline__ void do_split(const float* X, __nv_bfloat16* Y,
                                         int t, int Cpairs, int mode)
{
    int r = t / Cpairs, c = t - r * Cpairs;
    float2 x = ((const float2*)X)[t];
    __nv_bfloat162 h = __floats2bfloat162_rn(x.x, x.y);
    __nv_bfloat162 l = __floats2bfloat162_rn(x.x - __bfloat162float(h.x),
                                             x.y - __bfloat162float(h.y));
    uint32_t* row = (uint32_t*)(Y + (size_t)r * 6 * Cpairs);
    uint32_t hv = *(uint32_t*)&h, lv = *(uint32_t*)&l;
    if (mode == 0) { row[c] = hv; row[Cpairs + c] = lv; row[2 * Cpairs + c] = hv; }
    else           { row[c] = hv; row[Cpairs + c] = hv; row[2 * Cpairs + c] = lv; }
}

__global__ void split_all(const float* __restrict__ x0, __nv_bfloat16* y0, int n0, int c0,
                          const float* __restrict__ x1, __nv_bfloat16* y1, int n1, int c1,
                          const float* __restrict__ x2, __nv_bfloat16* y2, int n2, int c2,
                          const float* __restrict__ x3, __nv_bfloat16* y3, int n3, int c3,
                          const float* __restrict__ x4, __nv_bfloat16* y4, int n4, int c4)
{
    int t = blockIdx.x * blockDim.x + threadIdx.x;
    if      (t < n0)         { do_split(x0, y0, t, c0, 0); }
    else if ((t -= n0) < n1) { do_split(x1, y1, t, c1, 1); }
    else if ((t -= n1) < n2) { do_split(x2, y2, t, c2, 1); }
    else if ((t -= n2) < n3) { do_split(x3, y3, t, c3, 1); }
    else if ((t -= n3) < n4) { do_split(x4, y4, t, c4, 1); }
}

// ---------------------------------------------------------------------------
// Fused indexed RoPE + hi/lo split for Q and K, plus V hi/lo split, one launch.
// ---------------------------------------------------------------------------
__device__ __forceinline__ void do_rope(const float* X,
                                        __nv_bfloat16* Xh, __nv_bfloat16* Xl,
                                        const float* cosT, const float* sinT,
                                        const int* idx, int nheads, int group,
                                        float scale, int t)
{
    int d = t % 48;
    int h = (t / 48) % nheads;
    int s = t / (48 * nheads);
    int hk = h / group;

    const float* base = X + (size_t)s * (nheads * HD) + h * HD;
    float x1 = base[d];
    float x2 = base[d + 48];

    int i1 = idx[hk * HD + d];
    int i2 = idx[hk * HD + d + 48];
    float c1 = cosT[s * DFULL + i1], s1 = sinT[s * DFULL + i1];
    float c2 = cosT[s * DFULL + i2], s2 = sinT[s * DFULL + i2];

    float lo = (x1 * c1 - x2 * s1) * scale;
    float hi = (x2 * c2 + x1 * s2) * scale;

    size_t o = (size_t)s * (nheads * HD) + h * HD;
    __nv_bfloat16 bh = __float2bfloat16(lo);
    Xh[o + d] = bh;
    Xl[o + d] = __float2bfloat16(lo - __bfloat162float(bh));
    bh = __float2bfloat16(hi);
    Xh[o + d + 48] = bh;
    Xl[o + d + 48] = __float2bfloat16(hi - __bfloat162float(bh));
}

__global__ void rope_split_all(
    const float* __restrict__ Qs, __nv_bfloat16* Qh, __nv_bfloat16* Ql,
    const float* __restrict__ Ks, __nv_bfloat16* Kh, __nv_bfloat16* Kl,
    const float* __restrict__ Vs, __nv_bfloat16* Vh, __nv_bfloat16* Vl,
    const float* __restrict__ cosT, const float* __restrict__ sinT,
    const int* __restrict__ idx, int totQ, int totK, int totVpairs)
{
    int t = blockIdx.x * blockDim.x + threadIdx.x;
    if (t < totQ) {
        do_rope(Qs, Qh, Ql, cosT, sinT, idx, NH, GROUPS, ATT_SCALE, t);
        return;
    }
    t -= totQ;
    if (t < totK) {
        do_rope(Ks, Kh, Kl, cosT, sinT, idx, NKV, 1, 1.0f, t);
        return;
    }
    t -= totK;
    if (t < totVpairs) {
        float2 x = ((const float2*)Vs)[t];
        __nv_bfloat162 h = __floats2bfloat162_rn(x.x, x.y);
        __nv_bfloat162 l = __floats2bfloat162_rn(x.x - __bfloat162float(h.x),
                                                 x.y - __bfloat162float(h.y));
        ((uint32_t*)Vh)[t] = *(uint32_t*)&h;
        ((uint32_t*)Vl)[t] = *(uint32_t*)&l;
    }
}

// ---------------------------------------------------------------------------
// HMMA flash attention, causal GQA. CTA = 128 q-rows x 1 head, 8 warps.
// 64-key blocks, double-buffered cp.async KV stages.
// 3-term split MMAs: S = QhKh + QlKh + QhKl;  O += PhVh + PlVh + PhVl.
// Epilogue writes AO directly in GEMM-A tripled layout [hi|lo|hi] bf16.
// ---------------------------------------------------------------------------
#define FD   96
#define FBM  128
#define FBN  64
#define FROW 208
#define FQ_BYTES  (FBM * FROW)
#define FKV_BYTES (FBN * FROW)
#define STG_BYTES (4 * FKV_BYTES)
#define FLASH_SMEM (2 * FQ_BYTES + 2 * STG_BYTES)

__device__ __forceinline__ void flash_load_kv(uint32_t st_base,
    const __nv_bfloat16* Kh, const __nv_bfloat16* Kl,
    const __nv_bfloat16* Vh, const __nv_bfloat16* Vl,
    int key0, int hk, int tid)
{
    const size_t goff = (size_t)key0 * (KVDIM * 2) + hk * (FD * 2);
    const char* g0 = (const char*)Kh + goff;
    const char* g1 = (const char*)Kl + goff;
    const char* g2 = (const char*)Vh + goff;
    const char* g3 = (const char*)Vl + goff;
#pragma unroll
    for (int i = 0; i < 3; i++) {
        int idx = tid + i * 256;
        int row = idx / 12, seg = idx - row * 12;
        uint32_t d = st_base + row * FROW + seg * 16;
        size_t go = (size_t)row * (KVDIM * 2) + seg * 16;
        CP_ASYNC16(d,                 g0 + go);
        CP_ASYNC16(d +     FKV_BYTES, g1 + go);
        CP_ASYNC16(d + 2 * FKV_BYTES, g2 + go);
        CP_ASYNC16(d + 3 * FKV_BYTES, g3 + go);
    }
}

__global__ __launch_bounds__(256, 1) void flash_mma(
    const __nv_bfloat16* __restrict__ Qh, const __nv_bfloat16* __restrict__ Ql,
    const __nv_bfloat16* __restrict__ Kh, const __nv_bfloat16* __restrict__ Kl,
    const __nv_bfloat16* __restrict__ Vh, const __nv_bfloat16* __restrict__ Vl,
    __nv_bfloat16* __restrict__ AOs)
{
    extern __shared__ char smem[];
    const uint32_t sb = smem_u32(smem);
    const int tid = threadIdx.x, wid = tid >> 5, lane = tid & 31;
    const int h = blockIdx.y, hk = h / GROUPS;
    const int qbase = ((int)gridDim.x - 1 - (int)blockIdx.x) * FBM;  // heavy first
    const int nb = qbase / FBN + 2;

    const uint32_t sQh_ = sb, sQl_ = sb + FQ_BYTES;
    const uint32_t st0 = sb + 2 * FQ_BYTES;

    {
        const char* gqh = (const char*)(Qh + (size_t)qbase * QDIM + h * FD);
        const char* gql = (const char*)(Ql + (size_t)qbase * QDIM + h * FD);
#pragma unroll
        for (int i = 0; i < 6; i++) {
            int idx = tid + i * 256;
            int row = idx / 12, seg = idx - row * 12;
            uint32_t d = row * FROW + seg * 16;
            size_t go = (size_t)row * (QDIM * 2) + seg * 16;
            CP_ASYNC16(sQh_ + d, gqh + go);
            CP_ASYNC16(sQl_ + d, gql + go);
        }
        flash_load_kv(st0, Kh, Kl, Vh, Vl, 0, hk, tid);
        CP_COMMIT();
    }

    float oacc[12][4];
#pragma unroll
    for (int j = 0; j < 12; j++)
#pragma unroll
        for (int q = 0; q < 4; q++) oacc[j][q] = 0.f;
    float m0 = -CUDART_INF_F, m1 = -CUDART_INF_F, l0 = 0.f, l1 = 0.f;

    const int a_row = (lane & 7) + ((lane >> 3) & 1) * 8;
    const int a_cs  = ((lane >> 4) & 1) * 16;
    const int b_row = (lane & 7) + ((lane >> 4) & 1) * 8;
    const int b_cs  = ((lane >> 3) & 1) * 16;
    const int t_row = (lane & 7) + ((lane >> 3) & 1) * 8;
    const int t_cs  = ((lane >> 4) & 1) * 16;

    const int qr_lo = qbase + wid * 16;
    const int row0  = qr_lo + (lane >> 2);

    for (int kb = 0; kb < nb; kb++) {
        if (kb + 1 < nb) {
            flash_load_kv(st0 + ((kb + 1) & 1) * STG_BYTES, Kh, Kl, Vh, Vl,
                          (kb + 1) * FBN, hk, tid);
            CP_COMMIT();
            CP_WAIT(1);
        } else {
            CP_WAIT(0);
        }
        __syncthreads();

        const int key0 = kb * FBN;
        if (key0 <= qr_lo + 15) {
            const uint32_t sKh_ = st0 + (kb & 1) * STG_BYTES;
            const uint32_t sKl_ = sKh_ + FKV_BYTES;
            const uint32_t sVh_ = sKh_ + 2 * FKV_BYTES;
            const uint32_t sVl_ = sKh_ + 3 * FKV_BYTES;

            float sacc[8][4];
#pragma unroll
            for (int j = 0; j < 8; j++)
#pragma unroll
                for (int q = 0; q < 4; q++) sacc[j][q] = 0.f;

#pragma unroll
            for (int pass = 0; pass < 3; pass++) {
                const uint32_t sa = (pass == 1) ? sQl_ : sQh_;
                const uint32_t sk = (pass == 2) ? sKl_ : sKh_;
#pragma unroll
                for (int ks = 0; ks < 6; ks++) {
                    uint32_t a0, a1, a2, a3;
                    LDSM_X4(a0, a1, a2, a3,
                            sa + (wid * 16 + a_row) * FROW + ks * 32 + a_cs);
#pragma unroll
                    for (int p = 0; p < 4; p++) {
                        uint32_t b0, b1, b2, b3;
                        LDSM_X4(b0, b1, b2, b3,
                                sk + (p * 16 + b_row) * FROW + ks * 32 + b_cs);
                        mma_bf16(sacc[2 * p],     a0, a1, a2, a3, b0, b1);
                        mma_bf16(sacc[2 * p + 1], a0, a1, a2, a3, b2, b3);
                    }
                }
            }

            if (key0 + FBN - 1 > qr_lo) {
#pragma unroll
                for (int j = 0; j < 8; j++) {
                    int kcol = key0 + 8 * j + (lane & 3) * 2;
                    if (kcol     > row0)     sacc[j][0] = -CUDART_INF_F;
                    if (kcol + 1 > row0)     sacc[j][1] = -CUDART_INF_F;
                    if (kcol     > row0 + 8) sacc[j][2] = -CUDART_INF_F;
                    if (kcol + 1 > row0 + 8) sacc[j][3] = -CUDART_INF_F;
                }
            }

            float mx0 = sacc[0][0], mx1 = sacc[0][2];
#pragma unroll
            for (int j = 0; j < 8; j++) {
                mx0 = fmaxf(mx0, fmaxf(sacc[j][0], sacc[j][1]));
                mx1 = fmaxf(mx1, fmaxf(sacc[j][2], sacc[j][3]));
            }
            mx0 = fmaxf(mx0, __shfl_xor_sync(0xffffffffu, mx0, 1));
            mx0 = fmaxf(mx0, __shfl_xor_sync(0xffffffffu, mx0, 2));
            mx1 = fmaxf(mx1, __shfl_xor_sync(0xffffffffu, mx1, 1));
            mx1 = fmaxf(mx1, __shfl_xor_sync(0xffffffffu, mx1, 2));

            float mn0 = fmaxf(m0, mx0), mn1 = fmaxf(m1, mx1);
            float al0 = __expf(m0 - mn0), al1 = __expf(m1 - mn1);

            uint32_t ph[8][2], pl[8][2];
            float sum0 = 0.f, sum1 = 0.f;
#pragma unroll
            for (int j = 0; j < 8; j++) {
                float p0 = __expf(sacc[j][0] - mn0), p1 = __expf(sacc[j][1] - mn0);
                float p2 = __expf(sacc[j][2] - mn1), p3 = __expf(sacc[j][3] - mn1);
                sum0 += p0 + p1; sum1 += p2 + p3;
                __nv_bfloat162 h01 = __floats2bfloat162_rn(p0, p1);
                __nv_bfloat162 h23 = __floats2bfloat162_rn(p2, p3);
                ph[j][0] = *(uint32_t*)&h01;
                ph[j][1] = *(uint32_t*)&h23;
                __nv_bfloat162 l01 = __floats2bfloat162_rn(p0 - __bfloat162float(h01.x),
                                                           p1 - __bfloat162float(h01.y));
                __nv_bfloat162 l23 = __floats2bfloat162_rn(p2 - __bfloat162float(h23.x),
                                                           p3 - __bfloat162float(h23.y));
                pl[j][0] = *(uint32_t*)&l01;
                pl[j][1] = *(uint32_t*)&l23;
            }
            sum0 += __shfl_xor_sync(0xffffffffu, sum0, 1);
            sum0 += __shfl_xor_sync(0xffffffffu, sum0, 2);
            sum1 += __shfl_xor_sync(0xffffffffu, sum1, 1);
            sum1 += __shfl_xor_sync(0xffffffffu, sum1, 2);

            l0 = l0 * al0 + sum0;  l1 = l1 * al1 + sum1;
            m0 = mn0;              m1 = mn1;
#pragma unroll
            for (int j = 0; j < 12; j++) {
                oacc[j][0] *= al0; oacc[j][1] *= al0;
                oacc[j][2] *= al1; oacc[j][3] *= al1;
            }

#pragma unroll
            for (int kk = 0; kk < 4; kk++) {
                uint32_t a0 = ph[2 * kk][0], a1 = ph[2 * kk][1];
                uint32_t a2 = ph[2 * kk + 1][0], a3 = ph[2 * kk + 1][1];
                uint32_t c0 = pl[2 * kk][0], c1 = pl[2 * kk][1];
                uint32_t c2 = pl[2 * kk + 1][0], c3 = pl[2 * kk + 1][1];
#pragma unroll
                for (int p = 0; p < 6; p++) {
                    uint32_t vaddr = (16 * kk + t_row) * FROW + p * 32 + t_cs;
                    uint32_t b0, b1, b2, b3;
                    LDSM_X4_T(b0, b1, b2, b3, sVh_ + vaddr);
                    mma_bf16(oacc[2 * p],     a0, a1, a2, a3, b0, b1);
                    mma_bf16(oacc[2 * p + 1], a0, a1, a2, a3, b2, b3);
                    mma_bf16(oacc[2 * p],     c0, c1, c2, c3, b0, b1);
                    mma_bf16(oacc[2 * p + 1], c0, c1, c2, c3, b2, b3);
                    LDSM_X4_T(b0, b1, b2, b3, sVl_ + vaddr);
                    mma_bf16(oacc[2 * p],     a0, a1, a2, a3, b0, b1);
                    mma_bf16(oacc[2 * p + 1], a0, a1, a2, a3, b2, b3);
                }
            }
        }
        __syncthreads();
    }

    // epilogue: normalize + hi/lo split directly into [hi|lo|hi] layout
    const float inv0 = 1.f / l0, inv1 = 1.f / l1;
    __nv_bfloat16* ob0 = AOs + (size_t)row0 * KP_O + h * FD + (lane & 3) * 2;
    __nv_bfloat16* ob1 = AOs + (size_t)(row0 + 8) * KP_O + h * FD + (lane & 3) * 2;
#pragma unroll
    for (int j = 0; j < 12; j++) {
        float v0 = oacc[j][0] * inv0, v1 = oacc[j][1] * inv0;
        float v2 = oacc[j][2] * inv1, v3 = oacc[j][3] * inv1;
        __nv_bfloat162 h01 = __floats2bfloat162_rn(v0, v1);
        __nv_bfloat162 l01 = __floats2bfloat162_rn(v0 - __bfloat162float(h01.x),
                                                   v1 - __bfloat162float(h01.y));
        __nv_bfloat162 h23 = __floats2bfloat162_rn(v2, v3);
        __nv_bfloat162 l23 = __floats2bfloat162_rn(v2 - __bfloat162float(h23.x),
                                                   v3 - __bfloat162float(h23.y));
        *(__nv_bfloat162*)(ob0 + j * 8)            = h01;
        *(__nv_bfloat162*)(ob0 + QDIM + j * 8)     = l01;
        *(__nv_bfloat162*)(ob0 + 2 * QDIM + j * 8) = h01;
        *(__nv_bfloat162*)(ob1 + j * 8)            = h23;
        *(__nv_bfloat162*)(ob1 + QDIM + j * 8)     = l23;
        *(__nv_bfloat162*)(ob1 + 2 * QDIM + j * 8) = h23;
    }
}

// ---------------------------------------------------------------------------
extern "C" void kernel_launch(void* const* d_in, const int* in_sizes, int n_in,
                              void* d_out, int out_size)
{
    const float* hs  = (const float*)d_in[0];
    const float* cs  = (const float*)d_in[1];
    const float* sn  = (const float*)d_in[2];
    const int*   idx = (const int*)  d_in[3];
    const float* Wq  = (const float*)d_in[4];
    const float* Wk  = (const float*)d_in[5];
    const float* Wv  = (const float*)d_in[6];
    const float* Wo  = (const float*)d_in[7];
    float* out = (float*)d_out;

    float *Qb, *Kb, *Vb;
    __nv_bfloat16 *hsb, *wqb, *wkb, *wvb, *aob, *wob;
    __nv_bfloat16 *qh, *ql, *kh, *kl, *vh, *vl;
    cudaGetSymbolAddress((void**)&Qb,  g_Q);
    cudaGetSymbolAddress((void**)&Kb,  g_K);
    cudaGetSymbolAddress((void**)&Vb,  g_V);
    cudaGetSymbolAddress((void**)&hsb, g_hsb);
    cudaGetSymbolAddress((void**)&wqb, g_wqb);
    cudaGetSymbolAddress((void**)&wkb, g_wkb);
    cudaGetSymbolAddress((void**)&wvb, g_wvb);
    cudaGetSymbolAddress((void**)&aob, g_aob);
    cudaGetSymbolAddress((void**)&wob, g_wob);
    cudaGetSymbolAddress((void**)&qh,  g_Qh);
    cudaGetSymbolAddress((void**)&ql,  g_Ql);
    cudaGetSymbolAddress((void**)&kh,  g_Kh);
    cudaGetSymbolAddress((void**)&kl,  g_Kl);
    cudaGetSymbolAddress((void**)&vh,  g_Vh);
    cudaGetSymbolAddress((void**)&vl,  g_Vl);

    static bool attr_set = false;
    if (!attr_set) {
        cudaFuncSetAttribute(gemm_mma,  cudaFuncAttributeMaxDynamicSharedMemorySize, GEMM_SMEM);
        cudaFuncSetAttribute(flash_mma, cudaFuncAttributeMaxDynamicSharedMemorySize, FLASH_SMEM);
        attr_set = true;
    }

    // fused tripled-layout splits (one launch: hs + 4 weights)
    {
        const int n0 = S_LEN * HIDDEN / 2, c0 = HIDDEN / 2;
        const int n1 = QDIM  * HIDDEN / 2, c1 = HIDDEN / 2;
        const int n2 = KVDIM * HIDDEN / 2, c2 = HIDDEN / 2;
        const int n3 = KVDIM * HIDDEN / 2, c3 = HIDDEN / 2;
        const int n4 = HIDDEN * QDIM  / 2, c4 = QDIM / 2;
        const int tot = n0 + n1 + n2 + n3 + n4;
        split_all<<<(tot + 255) / 256, 256>>>(
            hs, hsb, n0, c0,
            Wq, wqb, n1, c1,
            Wk, wkb, n2, c2,
            Wv, wvb, n3, c3,
            Wo, wob, n4, c4);
    }

    // fused QKV projection (tripled-K layout)
    gemm_mma<<<dim3(36, S_LEN / BM), 128, GEMM_SMEM>>>(
        hsb,
        wqb, Qb, QDIM / BN,  QDIM,
        wkb, Kb, KVDIM / BN, KVDIM,
        wvb, Vb,             KVDIM,
        KP_QKV);

    // fused RoPE+split (Q, K) + V split in one launch
    {
        const int totQ = S_LEN * NH  * 48;
        const int totK = S_LEN * NKV * 48;
        const int totV = S_LEN * KVDIM / 2;
        const int tot = totQ + totK + totV;
        rope_split_all<<<(tot + 255) / 256, 256>>>(
            Qb, qh, ql, Kb, kh, kl, Vb, vh, vl, cs, sn, idx, totQ, totK, totV);
    }

    // causal GQA attention (HMMA) — writes tripled AO layout directly
    flash_mma<<<dim3(S_LEN / FBM, NH), 256, FLASH_SMEM>>>(qh, ql, kh, kl, vh, vl, aob);

    // output projection -> d_out
    gemm_mma<<<dim3(HIDDEN / BN, S_LEN / BM), 128, GEMM_SMEM>>>(
        aob,
        wob, out, HIDDEN / BN, HIDDEN,
        wob, out, 0,           HIDDEN,
        wob, out,              HIDDEN,
        KP_O);
}

// round 11
// speedup vs baseline: 1.2918x; 1.1566x over previous
#include <cuda_runtime.h>
#include <cuda_bf16.h>
#include <cuda_fp16.h>
#include <math_constants.h>
#include <cstdint>

#define S_LEN  2048
#define HIDDEN 4096
#define NH     32
#define NKV    8
#define HD     96
#define GROUPS 4
#define QDIM   (NH * HD)    // 3072
#define KVDIM  (NKV * HD)   // 768
#define DFULL  128
#define ATT_SCALE 0.08838834764831845f  // 128^-0.5

#define KP_QKV (3 * HIDDEN)   // 12288 (bf16 3-term)
#define KP_O   (2 * QDIM)     // 6144  (fp16 2-term)

// ---------------- scratch (allocation-free: device globals) ----------------
static __device__ __align__(256) float g_Q [S_LEN * QDIM];
static __device__ __align__(256) float g_K [S_LEN * KVDIM];
static __device__ __align__(256) float g_V [S_LEN * KVDIM];

static __device__ __align__(256) __nv_bfloat16 g_hsb[S_LEN * KP_QKV];   // [Ah|Al|Ah]
static __device__ __align__(256) __nv_bfloat16 g_wqb[QDIM * KP_QKV];    // [Bh|Bh|Bl]
static __device__ __align__(256) __nv_bfloat16 g_wkb[KVDIM * KP_QKV];
static __device__ __align__(256) __nv_bfloat16 g_wvb[KVDIM * KP_QKV];
static __device__ __align__(256) __half        g_aob[S_LEN * KP_O];     // fp16 [h|l]
static __device__ __align__(256) __half        g_wob[HIDDEN * KP_O];    // fp16 [h|h]

// flash operands
static __device__ __align__(256) __nv_bfloat16 g_Qh[S_LEN * QDIM];
static __device__ __align__(256) __nv_bfloat16 g_Ql[S_LEN * QDIM];
static __device__ __align__(256) __nv_bfloat16 g_Kh[S_LEN * KVDIM];
static __device__ __align__(256) __nv_bfloat16 g_Kl[S_LEN * KVDIM];
static __device__ __align__(256) __half        g_Vh[S_LEN * KVDIM];     // fp16 single

// ---------------------------------------------------------------------------
// PTX helpers
// ---------------------------------------------------------------------------
__device__ __forceinline__ uint32_t smem_u32(const void* p) {
    uint32_t a;
    asm("{ .reg .u64 t; cvta.to.shared.u64 t, %1; cvt.u32.u64 %0, t; }" : "=r"(a) : "l"(p));
    return a;
}
#define CP_ASYNC16(dst, src) asm volatile("cp.async.cg.shared.global [%0], [%1], 16;" :: "r"(dst), "l"(src))
#define CP_COMMIT()          asm volatile("cp.async.commit_group;" ::: "memory")
#define CP_WAIT(n)           asm volatile("cp.async.wait_group %0;" :: "n"(n) : "memory")

#define LDSM_X4(r0, r1, r2, r3, addr)                                            \
    asm volatile("ldmatrix.sync.aligned.m8n8.x4.shared.b16 {%0,%1,%2,%3}, [%4];" \
        : "=r"(r0), "=r"(r1), "=r"(r2), "=r"(r3) : "r"(addr))

#define LDSM_X4_T(r0, r1, r2, r3, addr)                                                \
    asm volatile("ldmatrix.sync.aligned.m8n8.x4.trans.shared.b16 {%0,%1,%2,%3}, [%4];" \
        : "=r"(r0), "=r"(r1), "=r"(r2), "=r"(r3) : "r"(addr))

__device__ __forceinline__ void mma_bf16(float* c, uint32_t a0, uint32_t a1,
                                         uint32_t a2, uint32_t a3,
                                         uint32_t b0, uint32_t b1) {
    asm volatile(
        "mma.sync.aligned.m16n8k16.row.col.f32.bf16.bf16.f32 "
        "{%0,%1,%2,%3}, {%4,%5,%6,%7}, {%8,%9}, {%0,%1,%2,%3};"
        : "+f"(c[0]), "+f"(c[1]), "+f"(c[2]), "+f"(c[3])
        : "r"(a0), "r"(a1), "r"(a2), "r"(a3), "r"(b0), "r"(b1));
}
__device__ __forceinline__ void mma_f16(float* c, uint32_t a0, uint32_t a1,
                                        uint32_t a2, uint32_t a3,
                                        uint32_t b0, uint32_t b1) {
    asm volatile(
        "mma.sync.aligned.m16n8k16.row.col.f32.f16.f16.f32 "
        "{%0,%1,%2,%3}, {%4,%5,%6,%7}, {%8,%9}, {%0,%1,%2,%3};"
        : "+f"(c[0]), "+f"(c[1]), "+f"(c[2]), "+f"(c[3])
        : "r"(a0), "r"(a1), "r"(a2), "r"(a3), "r"(b0), "r"(b1));
}
template <int F16>
__device__ __forceinline__ void mma16(float* c, uint32_t a0, uint32_t a1,
                                      uint32_t a2, uint32_t a3,
                                      uint32_t b0, uint32_t b1) {
    if (F16) mma_f16(c, a0, a1, a2, a3, b0, b1);
    else     mma_bf16(c, a0, a1, a2, a3, b0, b1);
}

// ---------------------------------------------------------------------------
// 16-bit HMMA GEMM over concatenated-K layout (dtype via template).
// BM=128, BN=128, BK=64, 2-stage cp.async pipeline, 4 warps, warp tile 64x64.
// launch_bounds(128,3) -> 3 CTAs/SM. Segmented over N (up to 3 segments).
// ---------------------------------------------------------------------------
#define BM 128
#define BN 128
#define BKE 64
#define ROW_B 144
#define TILE_BYTES (128 * ROW_B)
#define STAGE_BYTES (2 * TILE_BYTES)
#define NSTAGE 2
#define GEMM_SMEM (NSTAGE * STAGE_BYTES)   // 73728

__device__ __forceinline__ void load_tiles(uint32_t stage_base,
    const __nv_bfloat16* __restrict__ A, const __nv_bfloat16* __restrict__ B,
    int bm, int bn, int kc, int Kp, int tid)
{
    const char* Ag = (const char*)(A + (size_t)bm * Kp + kc * BKE);
    const char* Bg = (const char*)(B + (size_t)bn * Kp + kc * BKE);
    const size_t rowb = (size_t)Kp * 2;
    const uint32_t sA = stage_base;
    const uint32_t sB = stage_base + TILE_BYTES;
#pragma unroll
    for (int i = 0; i < 8; i++) {
        int idx = tid + i * 128;
        int row = idx >> 3, seg = idx & 7;
        CP_ASYNC16(sA + row * ROW_B + seg * 16, Ag + (size_t)row * rowb + seg * 16);
    }
#pragma unroll
    for (int i = 0; i < 8; i++) {
        int idx = tid + i * 128;
        int row = idx >> 3, seg = idx & 7;
        CP_ASYNC16(sB + row * ROW_B + seg * 16, Bg + (size_t)row * rowb + seg * 16);
    }
}

template <int F16>
__global__ __launch_bounds__(128, 3) void gemm_mma(
    const __nv_bfloat16* __restrict__ A,
    const __nv_bfloat16* __restrict__ B0, float* __restrict__ C0, int nt0, int N0,
    const __nv_bfloat16* __restrict__ B1, float* __restrict__ C1, int nt1, int N1,
    const __nv_bfloat16* __restrict__ B2, float* __restrict__ C2, int N2,
    int Kp)
{
    extern __shared__ char smem[];
    const uint32_t sbase = smem_u32(smem);
    const int tid  = threadIdx.x;
    const int wid  = tid >> 5;
    const int lane = tid & 31;
    const int bm   = blockIdx.y * BM;
    const int NC   = Kp / BKE;

    int bnt = blockIdx.x;
    const __nv_bfloat16* B;
    float* C; int N;
    if (bnt < nt0)            { B = B0; C = C0; N = N0; }
    else if (bnt < nt0 + nt1) { B = B1; C = C1; N = N1; bnt -= nt0; }
    else                      { B = B2; C = C2; N = N2; bnt -= nt0 + nt1; }
    const int bn = bnt * BN;

    const int wm = (wid >> 1) * 64;
    const int wn = (wid & 1) * 64;

    float acc[4][8][4];
#pragma unroll
    for (int t = 0; t < 4; t++)
#pragma unroll
        for (int j = 0; j < 8; j++)
#pragma unroll
            for (int q = 0; q < 4; q++) acc[t][j][q] = 0.f;

    const int a_row    = ((lane >> 3) & 1) * 8 + (lane & 7);
    const int a_cshift = ((lane >> 4) & 1) * 16;
    const int b_row    = ((lane >> 4) & 1) * 8 + (lane & 7);
    const int b_cshift = ((lane >> 3) & 1) * 16;

    load_tiles(sbase, A, B, bm, bn, 0, Kp, tid); CP_COMMIT();

    for (int c = 0; c < NC; c++) {
        CP_WAIT(0);
        __syncthreads();

        if (c + 1 < NC) {
            load_tiles(sbase + ((c + 1) & 1) * STAGE_BYTES, A, B, bm, bn, c + 1, Kp, tid);
            CP_COMMIT();
        }

        const uint32_t sA = sbase + (c & 1) * STAGE_BYTES;
        const uint32_t sB = sA + TILE_BYTES;
#pragma unroll
        for (int ks = 0; ks < 4; ks++) {
            uint32_t a[4][4];
#pragma unroll
            for (int t = 0; t < 4; t++) {
                uint32_t addr = sA + (wm + t * 16 + a_row) * ROW_B + ks * 32 + a_cshift;
                LDSM_X4(a[t][0], a[t][1], a[t][2], a[t][3], addr);
            }
#pragma unroll
            for (int p = 0; p < 4; p++) {
                uint32_t b0, b1, b2, b3;
                uint32_t addr = sB + (wn + p * 16 + b_row) * ROW_B + ks * 32 + b_cshift;
                LDSM_X4(b0, b1, b2, b3, addr);
#pragma unroll
                for (int t = 0; t < 4; t++) {
                    mma16<F16>(acc[t][2 * p],     a[t][0], a[t][1], a[t][2], a[t][3], b0, b1);
                    mma16<F16>(acc[t][2 * p + 1], a[t][0], a[t][1], a[t][2], a[t][3], b2, b3);
                }
            }
        }
    }

#pragma unroll
    for (int t = 0; t < 4; t++) {
        const int r0 = bm + wm + t * 16 + (lane >> 2);
#pragma unroll
        for (int j = 0; j < 8; j++) {
            const int col = bn + wn + j * 8 + (lane & 3) * 2;
            float* c0 = C + (size_t)r0 * N + col;
            float* c1 = C + (size_t)(r0 + 8) * N + col;
            *(float2*)c0 = make_float2(acc[t][j][0], acc[t][j][1]);
            *(float2*)c1 = make_float2(acc[t][j][2], acc[t][j][3]);
        }
    }
}

// ---------------------------------------------------------------------------
// Fused splits (one launch): regions 0-3 -> bf16 tripled; region 4 (Wo) ->
// fp16 duplicated [h|h].
// ---------------------------------------------------------------------------
__device__ __forceinline__ void do_split(const float* X, __nv_bfloat16* Y,
                                         int t, int Cpairs, int mode)
{
    int r = t / Cpairs, c = t - r * Cpairs;
    float2 x = ((const float2*)X)[t];
    __nv_bfloat162 h = __floats2bfloat162_rn(x.x, x.y);
    __nv_bfloat162 l = __floats2bfloat162_rn(x.x - __bfloat162float(h.x),
                                             x.y - __bfloat162float(h.y));
    uint32_t* row = (uint32_t*)(Y + (size_t)r * 6 * Cpairs);
    uint32_t hv = *(uint32_t*)&h, lv = *(uint32_t*)&l;
    if (mode == 0) { row[c] = hv; row[Cpairs + c] = lv; row[2 * Cpairs + c] = hv; }
    else           { row[c] = hv; row[Cpairs + c] = hv; row[2 * Cpairs + c] = lv; }
}

__device__ __forceinline__ void do_split_h2dup(const float* X, __half* Y,
                                               int t, int Cpairs)
{
    int r = t / Cpairs, c = t - r * Cpairs;
    float2 x = ((const float2*)X)[t];
    __half2 h = __floats2half2_rn(x.x, x.y);
    uint32_t* row = (uint32_t*)(Y + (size_t)r * 4 * Cpairs);  // 2 segments of 2*Cpairs halves
    uint32_t hv = *(uint32_t*)&h;
    row[c] = hv; row[Cpairs + c] = hv;
}

__global__ void split_all(const float* __restrict__ x0, __nv_bfloat16* y0, int n0, int c0,
                          const float* __restrict__ x1, __nv_bfloat16* y1, int n1, int c1,
                          const float* __restrict__ x2, __nv_bfloat16* y2, int n2, int c2,
                          const float* __restrict__ x3, __nv_bfloat16* y3, int n3, int c3,
                          const float* __restrict__ x4, __half* y4, int n4, int c4)
{
    int t = blockIdx.x * blockDim.x + threadIdx.x;
    if      (t < n0)         { do_split(x0, y0, t, c0, 0); }
    else if ((t -= n0) < n1) { do_split(x1, y1, t, c1, 1); }
    else if ((t -= n1) < n2) { do_split(x2, y2, t, c2, 1); }
    else if ((t -= n2) < n3) { do_split(x3, y3, t, c3, 1); }
    else if ((t -= n3) < n4) { do_split_h2dup(x4, y4, t, c4); }
}

// ---------------------------------------------------------------------------
// Fused indexed RoPE + bf16 hi/lo split for Q,K + V fp16 convert, one launch.
// ---------------------------------------------------------------------------
__device__ __forceinline__ void do_rope(const float* X,
                                        __nv_bfloat16* Xh, __nv_bfloat16* Xl,
                                        const float* cosT, const float* sinT,
                                        const int* idx, int nheads, int group,
                                        float scale, int t)
{
    int d = t % 48;
    int h = (t / 48) % nheads;
    int s = t / (48 * nheads);
    int hk = h / group;

    const float* base = X + (size_t)s * (nheads * HD) + h * HD;
    float x1 = base[d];
    float x2 = base[d + 48];

    int i1 = idx[hk * HD + d];
    int i2 = idx[hk * HD + d + 48];
    float c1 = cosT[s * DFULL + i1], s1 = sinT[s * DFULL + i1];
    float c2 = cosT[s * DFULL + i2], s2 = sinT[s * DFULL + i2];

    float lo = (x1 * c1 - x2 * s1) * scale;
    float hi = (x2 * c2 + x1 * s2) * scale;

    size_t o = (size_t)s * (nheads * HD) + h * HD;
    __nv_bfloat16 bh = __float2bfloat16(lo);
    Xh[o + d] = bh;
    Xl[o + d] = __float2bfloat16(lo - __bfloat162float(bh));
    bh = __float2bfloat16(hi);
    Xh[o + d + 48] = bh;
    Xl[o + d + 48] = __float2bfloat16(hi - __bfloat162float(bh));
}

__global__ void rope_split_all(
    const float* __restrict__ Qs, __nv_bfloat16* Qh, __nv_bfloat16* Ql,
    const float* __restrict__ Ks, __nv_bfloat16* Kh, __nv_bfloat16* Kl,
    const float* __restrict__ Vs, __half* Vh,
    const float* __restrict__ cosT, const float* __restrict__ sinT,
    const int* __restrict__ idx, int totQ, int totK, int totVpairs)
{
    int t = blockIdx.x * blockDim.x + threadIdx.x;
    if (t < totQ) {
        do_rope(Qs, Qh, Ql, cosT, sinT, idx, NH, GROUPS, ATT_SCALE, t);
        return;
    }
    t -= totQ;
    if (t < totK) {
        do_rope(Ks, Kh, Kl, cosT, sinT, idx, NKV, 1, 1.0f, t);
        return;
    }
    t -= totK;
    if (t < totVpairs) {
        float2 x = ((const float2*)Vs)[t];
        __half2 h = __floats2half2_rn(x.x, x.y);
        ((uint32_t*)Vh)[t] = *(uint32_t*)&h;
    }
}

// ---------------------------------------------------------------------------
// HMMA flash attention, causal GQA. CTA = 128 q-rows x 1 head, 8 warps.
// 64-key blocks, double-buffered cp.async KV stages (Kh,Kl bf16 + Vh fp16).
// S = QhKh + QlKh + QhKl (bf16);  O += PhVh + PlVh (fp16).
// Epilogue writes AO in fp16 [h|l] layout (KP_O = 2*QDIM).
// ---------------------------------------------------------------------------
#define FD   96
#define FBM  128
#define FBN  64
#define FROW 208
#define FQ_BYTES  (FBM * FROW)
#define FKV_BYTES (FBN * FROW)
#define STG_BYTES (3 * FKV_BYTES)
#define FLASH_SMEM (2 * FQ_BYTES + 2 * STG_BYTES)   // 133120

__device__ __forceinline__ void flash_load_kv(uint32_t st_base,
    const __nv_bfloat16* Kh, const __nv_bfloat16* Kl, const __half* Vh,
    int key0, int hk, int tid)
{
    const size_t goff = (size_t)key0 * (KVDIM * 2) + hk * (FD * 2);
    const char* g0 = (const char*)Kh + goff;
    const char* g1 = (const char*)Kl + goff;
    const char* g2 = (const char*)Vh + goff;
#pragma unroll
    for (int i = 0; i < 3; i++) {
        int idx = tid + i * 256;
        int row = idx / 12, seg = idx - row * 12;
        uint32_t d = st_base + row * FROW + seg * 16;
        size_t go = (size_t)row * (KVDIM * 2) + seg * 16;
        CP_ASYNC16(d,                 g0 + go);
        CP_ASYNC16(d +     FKV_BYTES, g1 + go);
        CP_ASYNC16(d + 2 * FKV_BYTES, g2 + go);
    }
}

__global__ __launch_bounds__(256, 1) void flash_mma(
    const __nv_bfloat16* __restrict__ Qh, const __nv_bfloat16* __restrict__ Ql,
    const __nv_bfloat16* __restrict__ Kh, const __nv_bfloat16* __restrict__ Kl,
    const __half* __restrict__ Vh,
    __half* __restrict__ AOs)
{
    extern __shared__ char smem[];
    const uint32_t sb = smem_u32(smem);
    const int tid = threadIdx.x, wid = tid >> 5, lane = tid & 31;
    const int h = blockIdx.y, hk = h / GROUPS;
    const int qbase = ((int)gridDim.x - 1 - (int)blockIdx.x) * FBM;  // heavy first
    const int nb = qbase / FBN + 2;

    const uint32_t sQh_ = sb, sQl_ = sb + FQ_BYTES;
    const uint32_t st0 = sb + 2 * FQ_BYTES;

    {
        const char* gqh = (const char*)(Qh + (size_t)qbase * QDIM + h * FD);
        const char* gql = (const char*)(Ql + (size_t)qbase * QDIM + h * FD);
#pragma unroll
        for (int i = 0; i < 6; i++) {
            int idx = tid + i * 256;
            int row = idx / 12, seg = idx - row * 12;
            uint32_t d = row * FROW + seg * 16;
            size_t go = (size_t)row * (QDIM * 2) + seg * 16;
            CP_ASYNC16(sQh_ + d, gqh + go);
            CP_ASYNC16(sQl_ + d, gql + go);
        }
        flash_load_kv(st0, Kh, Kl, Vh, 0, hk, tid);
        CP_COMMIT();
    }

    float oacc[12][4];
#pragma unroll
    for (int j = 0; j < 12; j++)
#pragma unroll
        for (int q = 0; q < 4; q++) oacc[j][q] = 0.f;
    float m0 = -CUDART_INF_F, m1 = -CUDART_INF_F, l0 = 0.f, l1 = 0.f;

    const int a_row = (lane & 7) + ((lane >> 3) & 1) * 8;
    const int a_cs  = ((lane >> 4) & 1) * 16;
    const int b_row = (lane & 7) + ((lane >> 4) & 1) * 8;
    const int b_cs  = ((lane >> 3) & 1) * 16;
    const int t_row = (lane & 7) + ((lane >> 3) & 1) * 8;
    const int t_cs  = ((lane >> 4) & 1) * 16;

    const int qr_lo = qbase + wid * 16;
    const int row0  = qr_lo + (lane >> 2);

    for (int kb = 0; kb < nb; kb++) {
        if (kb + 1 < nb) {
            flash_load_kv(st0 + ((kb + 1) & 1) * STG_BYTES, Kh, Kl, Vh,
                          (kb + 1) * FBN, hk, tid);
            CP_COMMIT();
            CP_WAIT(1);
        } else {
            CP_WAIT(0);
        }
        __syncthreads();

        const int key0 = kb * FBN;
        if (key0 <= qr_lo + 15) {
            const uint32_t sKh_ = st0 + (kb & 1) * STG_BYTES;
            const uint32_t sKl_ = sKh_ + FKV_BYTES;
            const uint32_t sVh_ = sKh_ + 2 * FKV_BYTES;

            float sacc[8][4];
#pragma unroll
            for (int j = 0; j < 8; j++)
#pragma unroll
                for (int q = 0; q < 4; q++) sacc[j][q] = 0.f;

#pragma unroll
            for (int pass = 0; pass < 3; pass++) {
                const uint32_t sa = (pass == 1) ? sQl_ : sQh_;
                const uint32_t sk = (pass == 2) ? sKl_ : sKh_;
#pragma unroll
                for (int ks = 0; ks < 6; ks++) {
                    uint32_t a0, a1, a2, a3;
                    LDSM_X4(a0, a1, a2, a3,
                            sa + (wid * 16 + a_row) * FROW + ks * 32 + a_cs);
#pragma unroll
                    for (int p = 0; p < 4; p++) {
                        uint32_t b0, b1, b2, b3;
                        LDSM_X4(b0, b1, b2, b3,
                                sk + (p * 16 + b_row) * FROW + ks * 32 + b_cs);
                        mma_bf16(sacc[2 * p],     a0, a1, a2, a3, b0, b1);
                        mma_bf16(sacc[2 * p + 1], a0, a1, a2, a3, b2, b3);
                    }
                }
            }

            if (key0 + FBN - 1 > qr_lo) {
#pragma unroll
                for (int j = 0; j < 8; j++) {
                    int kcol = key0 + 8 * j + (lane & 3) * 2;
                    if (kcol     > row0)     sacc[j][0] = -CUDART_INF_F;
                    if (kcol + 1 > row0)     sacc[j][1] = -CUDART_INF_F;
                    if (kcol     > row0 + 8) sacc[j][2] = -CUDART_INF_F;
                    if (kcol + 1 > row0 + 8) sacc[j][3] = -CUDART_INF_F;
                }
            }

            float mx0 = sacc[0][0], mx1 = sacc[0][2];
#pragma unroll
            for (int j = 0; j < 8; j++) {
                mx0 = fmaxf(mx0, fmaxf(sacc[j][0], sacc[j][1]));
                mx1 = fmaxf(mx1, fmaxf(sacc[j][2], sacc[j][3]));
            }
            mx0 = fmaxf(mx0, __shfl_xor_sync(0xffffffffu, mx0, 1));
            mx0 = fmaxf(mx0, __shfl_xor_sync(0xffffffffu, mx0, 2));
            mx1 = fmaxf(mx1, __shfl_xor_sync(0xffffffffu, mx1, 1));
            mx1 = fmaxf(mx1, __shfl_xor_sync(0xffffffffu, mx1, 2));

            float mn0 = fmaxf(m0, mx0), mn1 = fmaxf(m1, mx1);
            float al0 = __expf(m0 - mn0), al1 = __expf(m1 - mn1);

            uint32_t ph[8][2], pl[8][2];
            float sum0 = 0.f, sum1 = 0.f;
#pragma unroll
            for (int j = 0; j < 8; j++) {
                float p0 = __expf(sacc[j][0] - mn0), p1 = __expf(sacc[j][1] - mn0);
                float p2 = __expf(sacc[j][2] - mn1), p3 = __expf(sacc[j][3] - mn1);
                sum0 += p0 + p1; sum1 += p2 + p3;
                __half2 h01 = __floats2half2_rn(p0, p1);
                __half2 h23 = __floats2half2_rn(p2, p3);
                ph[j][0] = *(uint32_t*)&h01;
                ph[j][1] = *(uint32_t*)&h23;
                float2 f01 = __half22float2(h01);
                float2 f23 = __half22float2(h23);
                __half2 l01 = __floats2half2_rn(p0 - f01.x, p1 - f01.y);
                __half2 l23 = __floats2half2_rn(p2 - f23.x, p3 - f23.y);
                pl[j][0] = *(uint32_t*)&l01;
                pl[j][1] = *(uint32_t*)&l23;
            }
            sum0 += __shfl_xor_sync(0xffffffffu, sum0, 1);
            sum0 += __shfl_xor_sync(0xffffffffu, sum0, 2);
            sum1 += __shfl_xor_sync(0xffffffffu, sum1, 1);
            sum1 += __shfl_xor_sync(0xffffffffu, sum1, 2);

            l0 = l0 * al0 + sum0;  l1 = l1 * al1 + sum1;
            m0 = mn0;              m1 = mn1;
#pragma unroll
            for (int j = 0; j < 12; j++) {
                oacc[j][0] *= al0; oacc[j][1] *= al0;
                oacc[j][2] *= al1; oacc[j][3] *= al1;
            }

            // O += Ph*Vh + Pl*Vh  (fp16)
#pragma unroll
            for (int kk = 0; kk < 4; kk++) {
                uint32_t a0 = ph[2 * kk][0], a1 = ph[2 * kk][1];
                uint32_t a2 = ph[2 * kk + 1][0], a3 = ph[2 * kk + 1][1];
                uint32_t c0 = pl[2 * kk][0], c1 = pl[2 * kk][1];
                uint32_t c2 = pl[2 * kk + 1][0], c3 = pl[2 * kk + 1][1];
#pragma unroll
                for (int p = 0; p < 6; p++) {
                    uint32_t vaddr = (16 * kk + t_row) * FROW + p * 32 + t_cs;
                    uint32_t b0, b1, b2, b3;
                    LDSM_X4_T(b0, b1, b2, b3, sVh_ + vaddr);
                    mma_f16(oacc[2 * p],     a0, a1, a2, a3, b0, b1);
                    mma_f16(oacc[2 * p + 1], a0, a1, a2, a3, b2, b3);
                    mma_f16(oacc[2 * p],     c0, c1, c2, c3, b0, b1);
                    mma_f16(oacc[2 * p + 1], c0, c1, c2, c3, b2, b3);
                }
            }
        }
        __syncthreads();
    }

    // epilogue: normalize + fp16 hi/lo split into [h|l] layout (row = 2*QDIM)
    const float inv0 = 1.f / l0, inv1 = 1.f / l1;
    __half* ob0 = AOs + (size_t)row0 * KP_O + h * FD + (lane & 3) * 2;
    __half* ob1 = AOs + (size_t)(row0 + 8) * KP_O + h * FD + (lane & 3) * 2;
#pragma unroll
    for (int j = 0; j < 12; j++) {
        float v0 = oacc[j][0] * inv0, v1 = oacc[j][1] * inv0;
        float v2 = oacc[j][2] * inv1, v3 = oacc[j][3] * inv1;
        __half2 h01 = __floats2half2_rn(v0, v1);
        float2 f01 = __half22float2(h01);
        __half2 l01 = __floats2half2_rn(v0 - f01.x, v1 - f01.y);
        __half2 h23 = __floats2half2_rn(v2, v3);
        float2 f23 = __half22float2(h23);
        __half2 l23 = __floats2half2_rn(v2 - f23.x, v3 - f23.y);
        *(__half2*)(ob0 + j * 8)        = h01;
        *(__half2*)(ob0 + QDIM + j * 8) = l01;
        *(__half2*)(ob1 + j * 8)        = h23;
        *(__half2*)(ob1 + QDIM + j * 8) = l23;
    }
}

// ---------------------------------------------------------------------------
extern "C" void kernel_launch(void* const* d_in, const int* in_sizes, int n_in,
                              void* d_out, int out_size)
{
    const float* hs  = (const float*)d_in[0];
    const float* cs  = (const float*)d_in[1];
    const float* sn  = (const float*)d_in[2];
    const int*   idx = (const int*)  d_in[3];
    const float* Wq  = (const float*)d_in[4];
    const float* Wk  = (const float*)d_in[5];
    const float* Wv  = (const float*)d_in[6];
    const float* Wo  = (const float*)d_in[7];
    float* out = (float*)d_out;

    float *Qb, *Kb, *Vb;
    __nv_bfloat16 *hsb, *wqb, *wkb, *wvb;
    __half *aob, *wob, *vh;
    __nv_bfloat16 *qh, *ql, *kh, *kl;
    cudaGetSymbolAddress((void**)&Qb,  g_Q);
    cudaGetSymbolAddress((void**)&Kb,  g_K);
    cudaGetSymbolAddress((void**)&Vb,  g_V);
    cudaGetSymbolAddress((void**)&hsb, g_hsb);
    cudaGetSymbolAddress((void**)&wqb, g_wqb);
    cudaGetSymbolAddress((void**)&wkb, g_wkb);
    cudaGetSymbolAddress((void**)&wvb, g_wvb);
    cudaGetSymbolAddress((void**)&aob, g_aob);
    cudaGetSymbolAddress((void**)&wob, g_wob);
    cudaGetSymbolAddress((void**)&qh,  g_Qh);
    cudaGetSymbolAddress((void**)&ql,  g_Ql);
    cudaGetSymbolAddress((void**)&kh,  g_Kh);
    cudaGetSymbolAddress((void**)&kl,  g_Kl);
    cudaGetSymbolAddress((void**)&vh,  g_Vh);

    static bool attr_set = false;
    if (!attr_set) {
        cudaFuncSetAttribute(gemm_mma<0>, cudaFuncAttributeMaxDynamicSharedMemorySize, GEMM_SMEM);
        cudaFuncSetAttribute(gemm_mma<1>, cudaFuncAttributeMaxDynamicSharedMemorySize, GEMM_SMEM);
        cudaFuncSetAttribute(flash_mma,   cudaFuncAttributeMaxDynamicSharedMemorySize, FLASH_SMEM);
        attr_set = true;
    }

    // fused splits (one launch: hs + 3 QKV weights bf16-tripled, Wo fp16-dup)
    {
        const int n0 = S_LEN * HIDDEN / 2, c0 = HIDDEN / 2;
        const int n1 = QDIM  * HIDDEN / 2, c1 = HIDDEN / 2;
        const int n2 = KVDIM * HIDDEN / 2, c2 = HIDDEN / 2;
        const int n3 = KVDIM * HIDDEN / 2, c3 = HIDDEN / 2;
        const int n4 = HIDDEN * QDIM  / 2, c4 = QDIM / 2;
        const int tot = n0 + n1 + n2 + n3 + n4;
        split_all<<<(tot + 255) / 256, 256>>>(
            hs, hsb, n0, c0,
            Wq, wqb, n1, c1,
            Wk, wkb, n2, c2,
            Wv, wvb, n3, c3,
            Wo, wob, n4, c4);
    }

    // fused QKV projection (bf16 3-term, tripled-K layout)
    gemm_mma<0><<<dim3(36, S_LEN / BM), 128, GEMM_SMEM>>>(
        hsb,
        wqb, Qb, QDIM / BN,  QDIM,
        wkb, Kb, KVDIM / BN, KVDIM,
        wvb, Vb,             KVDIM,
        KP_QKV);

    // fused RoPE+split (Q, K bf16 hi/lo) + V fp16 convert, one launch
    {
        const int totQ = S_LEN * NH  * 48;
        const int totK = S_LEN * NKV * 48;
        const int totV = S_LEN * KVDIM / 2;
        const int tot = totQ + totK + totV;
        rope_split_all<<<(tot + 255) / 256, 256>>>(
            Qb, qh, ql, Kb, kh, kl, Vb, vh, cs, sn, idx, totQ, totK, totV);
    }

    // causal GQA attention — writes fp16 [h|l] AO layout directly
    flash_mma<<<dim3(S_LEN / FBM, NH), 256, FLASH_SMEM>>>(qh, ql, kh, kl, vh, aob);

    // output projection (fp16 2-term) -> d_out
    gemm_mma<1><<<dim3(HIDDEN / BN, S_LEN / BM), 128, GEMM_SMEM>>>(
        (const __nv_bfloat16*)aob,
        (const __nv_bfloat16*)wob, out, HIDDEN / BN, HIDDEN,
        (const __nv_bfloat16*)wob, out, 0,           HIDDEN,
        (const __nv_bfloat16*)wob, out,              HIDDEN,
        KP_O);
}

// round 12
// speedup vs baseline: 1.6088x; 1.2454x over previous
#include <cuda_runtime.h>
#include <cuda_bf16.h>
#include <cuda_fp16.h>
#include <math_constants.h>
#include <cstdint>

#define S_LEN  2048
#define HIDDEN 4096
#define NH     32
#define NKV    8
#define HD     96
#define GROUPS 4
#define QDIM   (NH * HD)    // 3072
#define KVDIM  (NKV * HD)   // 768
#define DFULL  128
#define ATT_SCALE 0.08838834764831845f  // 128^-0.5

#define KP_QKV (2 * HIDDEN)   // 8192 (fp16 2-term)
#define KP_O   (2 * QDIM)     // 6144 (fp16 2-term)

// ---------------- scratch (allocation-free: device globals) ----------------
static __device__ __align__(256) float g_Q [S_LEN * QDIM];
static __device__ __align__(256) float g_K [S_LEN * KVDIM];
static __device__ __align__(256) float g_V [S_LEN * KVDIM];

static __device__ __align__(256) __half g_hsb[S_LEN * KP_QKV];   // [Ah|Al]
static __device__ __align__(256) __half g_wqb[QDIM * KP_QKV];    // [Wh|Wh]
static __device__ __align__(256) __half g_wkb[KVDIM * KP_QKV];
static __device__ __align__(256) __half g_wvb[KVDIM * KP_QKV];
static __device__ __align__(256) __half g_aob[S_LEN * KP_O];     // [h|l]
static __device__ __align__(256) __half g_wob[HIDDEN * KP_O];    // [h|h]

// flash operands (all fp16)
static __device__ __align__(256) __half g_Qh[S_LEN * QDIM];
static __device__ __align__(256) __half g_Ql[S_LEN * QDIM];
static __device__ __align__(256) __half g_Kh[S_LEN * KVDIM];
static __device__ __align__(256) __half g_Vh[S_LEN * KVDIM];

// ---------------------------------------------------------------------------
// PTX helpers
// ---------------------------------------------------------------------------
__device__ __forceinline__ uint32_t smem_u32(const void* p) {
    uint32_t a;
    asm("{ .reg .u64 t; cvta.to.shared.u64 t, %1; cvt.u32.u64 %0, t; }" : "=r"(a) : "l"(p));
    return a;
}
#define CP_ASYNC16(dst, src) asm volatile("cp.async.cg.shared.global [%0], [%1], 16;" :: "r"(dst), "l"(src))
#define CP_COMMIT()          asm volatile("cp.async.commit_group;" ::: "memory")
#define CP_WAIT(n)           asm volatile("cp.async.wait_group %0;" :: "n"(n) : "memory")

#define LDSM_X4(r0, r1, r2, r3, addr)                                            \
    asm volatile("ldmatrix.sync.aligned.m8n8.x4.shared.b16 {%0,%1,%2,%3}, [%4];" \
        : "=r"(r0), "=r"(r1), "=r"(r2), "=r"(r3) : "r"(addr))

#define LDSM_X4_T(r0, r1, r2, r3, addr)                                                \
    asm volatile("ldmatrix.sync.aligned.m8n8.x4.trans.shared.b16 {%0,%1,%2,%3}, [%4];" \
        : "=r"(r0), "=r"(r1), "=r"(r2), "=r"(r3) : "r"(addr))

__device__ __forceinline__ void mma_f16(float* c, uint32_t a0, uint32_t a1,
                                        uint32_t a2, uint32_t a3,
                                        uint32_t b0, uint32_t b1) {
    asm volatile(
        "mma.sync.aligned.m16n8k16.row.col.f32.f16.f16.f32 "
        "{%0,%1,%2,%3}, {%4,%5,%6,%7}, {%8,%9}, {%0,%1,%2,%3};"
        : "+f"(c[0]), "+f"(c[1]), "+f"(c[2]), "+f"(c[3])
        : "r"(a0), "r"(a1), "r"(a2), "r"(a3), "r"(b0), "r"(b1));
}

// ---------------------------------------------------------------------------
// fp16 HMMA GEMM over concatenated-K layout.
// BM=128, BN=128, BK=64, 2-stage cp.async pipeline, 4 warps, warp tile 64x64.
// launch_bounds(128,3) -> 3 CTAs/SM. Segmented over N (up to 3 segments).
// ---------------------------------------------------------------------------
#define BM 128
#define BN 128
#define BKE 64
#define ROW_B 144
#define TILE_BYTES (128 * ROW_B)
#define STAGE_BYTES (2 * TILE_BYTES)
#define NSTAGE 2
#define GEMM_SMEM (NSTAGE * STAGE_BYTES)   // 73728

__device__ __forceinline__ void load_tiles(uint32_t stage_base,
    const __half* __restrict__ A, const __half* __restrict__ B,
    int bm, int bn, int kc, int Kp, int tid)
{
    const char* Ag = (const char*)(A + (size_t)bm * Kp + kc * BKE);
    const char* Bg = (const char*)(B + (size_t)bn * Kp + kc * BKE);
    const size_t rowb = (size_t)Kp * 2;
    const uint32_t sA = stage_base;
    const uint32_t sB = stage_base + TILE_BYTES;
#pragma unroll
    for (int i = 0; i < 8; i++) {
        int idx = tid + i * 128;
        int row = idx >> 3, seg = idx & 7;
        CP_ASYNC16(sA + row * ROW_B + seg * 16, Ag + (size_t)row * rowb + seg * 16);
    }
#pragma unroll
    for (int i = 0; i < 8; i++) {
        int idx = tid + i * 128;
        int row = idx >> 3, seg = idx & 7;
        CP_ASYNC16(sB + row * ROW_B + seg * 16, Bg + (size_t)row * rowb + seg * 16);
    }
}

__global__ __launch_bounds__(128, 3) void gemm_mma(
    const __half* __restrict__ A,
    const __half* __restrict__ B0, float* __restrict__ C0, int nt0, int N0,
    const __half* __restrict__ B1, float* __restrict__ C1, int nt1, int N1,
    const __half* __restrict__ B2, float* __restrict__ C2, int N2,
    int Kp)
{
    extern __shared__ char smem[];
    const uint32_t sbase = smem_u32(smem);
    const int tid  = threadIdx.x;
    const int wid  = tid >> 5;
    const int lane = tid & 31;
    const int bm   = blockIdx.y * BM;
    const int NC   = Kp / BKE;

    int bnt = blockIdx.x;
    const __half* B;
    float* C; int N;
    if (bnt < nt0)            { B = B0; C = C0; N = N0; }
    else if (bnt < nt0 + nt1) { B = B1; C = C1; N = N1; bnt -= nt0; }
    else                      { B = B2; C = C2; N = N2; bnt -= nt0 + nt1; }
    const int bn = bnt * BN;

    const int wm = (wid >> 1) * 64;
    const int wn = (wid & 1) * 64;

    float acc[4][8][4];
#pragma unroll
    for (int t = 0; t < 4; t++)
#pragma unroll
        for (int j = 0; j < 8; j++)
#pragma unroll
            for (int q = 0; q < 4; q++) acc[t][j][q] = 0.f;

    const int a_row    = ((lane >> 3) & 1) * 8 + (lane & 7);
    const int a_cshift = ((lane >> 4) & 1) * 16;
    const int b_row    = ((lane >> 4) & 1) * 8 + (lane & 7);
    const int b_cshift = ((lane >> 3) & 1) * 16;

    load_tiles(sbase, A, B, bm, bn, 0, Kp, tid); CP_COMMIT();

    for (int c = 0; c < NC; c++) {
        CP_WAIT(0);
        __syncthreads();

        if (c + 1 < NC) {
            load_tiles(sbase + ((c + 1) & 1) * STAGE_BYTES, A, B, bm, bn, c + 1, Kp, tid);
            CP_COMMIT();
        }

        const uint32_t sA = sbase + (c & 1) * STAGE_BYTES;
        const uint32_t sB = sA + TILE_BYTES;
#pragma unroll
        for (int ks = 0; ks < 4; ks++) {
            uint32_t a[4][4];
#pragma unroll
            for (int t = 0; t < 4; t++) {
                uint32_t addr = sA + (wm + t * 16 + a_row) * ROW_B + ks * 32 + a_cshift;
                LDSM_X4(a[t][0], a[t][1], a[t][2], a[t][3], addr);
            }
#pragma unroll
            for (int p = 0; p < 4; p++) {
                uint32_t b0, b1, b2, b3;
                uint32_t addr = sB + (wn + p * 16 + b_row) * ROW_B + ks * 32 + b_cshift;
                LDSM_X4(b0, b1, b2, b3, addr);
#pragma unroll
                for (int t = 0; t < 4; t++) {
                    mma_f16(acc[t][2 * p],     a[t][0], a[t][1], a[t][2], a[t][3], b0, b1);
                    mma_f16(acc[t][2 * p + 1], a[t][0], a[t][1], a[t][2], a[t][3], b2, b3);
                }
            }
        }
    }

#pragma unroll
    for (int t = 0; t < 4; t++) {
        const int r0 = bm + wm + t * 16 + (lane >> 2);
#pragma unroll
        for (int j = 0; j < 8; j++) {
            const int col = bn + wn + j * 8 + (lane & 3) * 2;
            float* c0 = C + (size_t)r0 * N + col;
            float* c1 = C + (size_t)(r0 + 8) * N + col;
            *(float2*)c0 = make_float2(acc[t][j][0], acc[t][j][1]);
            *(float2*)c1 = make_float2(acc[t][j][2], acc[t][j][3]);
        }
    }
}

// ---------------------------------------------------------------------------
// Fused fp16 splits (one launch): mode 0 -> [h|l], mode 1 -> [h|h].
// ---------------------------------------------------------------------------
__device__ __forceinline__ void do_split_h2(const float* X, __half* Y,
                                            int t, int Cpairs, int mode)
{
    int r = t / Cpairs, c = t - r * Cpairs;
    float2 x = ((const float2*)X)[t];
    __half2 h = __floats2half2_rn(x.x, x.y);
    uint32_t hv = *(uint32_t*)&h;
    uint32_t* row = (uint32_t*)(Y + (size_t)r * 4 * Cpairs);
    if (mode == 0) {
        float2 f = __half22float2(h);
        __half2 l = __floats2half2_rn(x.x - f.x, x.y - f.y);
        row[c] = hv; row[Cpairs + c] = *(uint32_t*)&l;
    } else {
        row[c] = hv; row[Cpairs + c] = hv;
    }
}

__global__ void split_all(const float* __restrict__ x0, __half* y0, int n0, int c0,
                          const float* __restrict__ x1, __half* y1, int n1, int c1,
                          const float* __restrict__ x2, __half* y2, int n2, int c2,
                          const float* __restrict__ x3, __half* y3, int n3, int c3,
                          const float* __restrict__ x4, __half* y4, int n4, int c4)
{
    int t = blockIdx.x * blockDim.x + threadIdx.x;
    if      (t < n0)         { do_split_h2(x0, y0, t, c0, 0); }
    else if ((t -= n0) < n1) { do_split_h2(x1, y1, t, c1, 1); }
    else if ((t -= n1) < n2) { do_split_h2(x2, y2, t, c2, 1); }
    else if ((t -= n2) < n3) { do_split_h2(x3, y3, t, c3, 1); }
    else if ((t -= n3) < n4) { do_split_h2(x4, y4, t, c4, 1); }
}

// ---------------------------------------------------------------------------
// Fused indexed RoPE (fp16 out) + V fp16 convert, one launch.
// Q: hi/lo fp16 split (scaled); K: hi only.
// ---------------------------------------------------------------------------
__device__ __forceinline__ void do_rope(const float* X,
                                        __half* Xh, __half* Xl, bool write_lo,
                                        const float* cosT, const float* sinT,
                                        const int* idx, int nheads, int group,
                                        float scale, int t)
{
    int d = t % 48;
    int h = (t / 48) % nheads;
    int s = t / (48 * nheads);
    int hk = h / group;

    const float* base = X + (size_t)s * (nheads * HD) + h * HD;
    float x1 = base[d];
    float x2 = base[d + 48];

    int i1 = idx[hk * HD + d];
    int i2 = idx[hk * HD + d + 48];
    float c1 = cosT[s * DFULL + i1], s1 = sinT[s * DFULL + i1];
    float c2 = cosT[s * DFULL + i2], s2 = sinT[s * DFULL + i2];

    float lo = (x1 * c1 - x2 * s1) * scale;
    float hi = (x2 * c2 + x1 * s2) * scale;

    size_t o = (size_t)s * (nheads * HD) + h * HD;
    __half bh = __float2half_rn(lo);
    Xh[o + d] = bh;
    if (write_lo) Xl[o + d] = __float2half_rn(lo - __half2float(bh));
    bh = __float2half_rn(hi);
    Xh[o + d + 48] = bh;
    if (write_lo) Xl[o + d + 48] = __float2half_rn(hi - __half2float(bh));
}

__global__ void rope_split_all(
    const float* __restrict__ Qs, __half* Qh, __half* Ql,
    const float* __restrict__ Ks, __half* Kh,
    const float* __restrict__ Vs, __half* Vh,
    const float* __restrict__ cosT, const float* __restrict__ sinT,
    const int* __restrict__ idx, int totQ, int totK, int totVpairs)
{
    int t = blockIdx.x * blockDim.x + threadIdx.x;
    if (t < totQ) {
        do_rope(Qs, Qh, Ql, true, cosT, sinT, idx, NH, GROUPS, ATT_SCALE, t);
        return;
    }
    t -= totQ;
    if (t < totK) {
        do_rope(Ks, Kh, nullptr, false, cosT, sinT, idx, NKV, 1, 1.0f, t);
        return;
    }
    t -= totK;
    if (t < totVpairs) {
        float2 x = ((const float2*)Vs)[t];
        __half2 h = __floats2half2_rn(x.x, x.y);
        ((uint32_t*)Vh)[t] = *(uint32_t*)&h;
    }
}

// ---------------------------------------------------------------------------
// fp16 HMMA flash attention, causal GQA. CTA = 128 q-rows x 1 head, 8 warps.
// 64-key blocks, double-buffered cp.async KV stages (Kh + Vh fp16).
// S = QhKh + QlKh;  O += PhVh + PlVh.  Epilogue writes fp16 [h|l] AO.
// ---------------------------------------------------------------------------
#define FD   96
#define FBM  128
#define FBN  64
#define FROW 208
#define FQ_BYTES  (FBM * FROW)
#define FKV_BYTES (FBN * FROW)
#define STG_BYTES (2 * FKV_BYTES)
#define FLASH_SMEM (2 * FQ_BYTES + 2 * STG_BYTES)   // 106496

__device__ __forceinline__ void flash_load_kv(uint32_t st_base,
    const __half* Kh, const __half* Vh, int key0, int hk, int tid)
{
    const size_t goff = (size_t)key0 * (KVDIM * 2) + hk * (FD * 2);
    const char* g0 = (const char*)Kh + goff;
    const char* g1 = (const char*)Vh + goff;
#pragma unroll
    for (int i = 0; i < 3; i++) {
        int idx = tid + i * 256;
        int row = idx / 12, seg = idx - row * 12;
        uint32_t d = st_base + row * FROW + seg * 16;
        size_t go = (size_t)row * (KVDIM * 2) + seg * 16;
        CP_ASYNC16(d,             g0 + go);
        CP_ASYNC16(d + FKV_BYTES, g1 + go);
    }
}

__global__ __launch_bounds__(256, 1) void flash_mma(
    const __half* __restrict__ Qh, const __half* __restrict__ Ql,
    const __half* __restrict__ Kh, const __half* __restrict__ Vh,
    __half* __restrict__ AOs)
{
    extern __shared__ char smem[];
    const uint32_t sb = smem_u32(smem);
    const int tid = threadIdx.x, wid = tid >> 5, lane = tid & 31;
    const int h = blockIdx.y, hk = h / GROUPS;
    const int qbase = ((int)gridDim.x - 1 - (int)blockIdx.x) * FBM;  // heavy first
    const int nb = qbase / FBN + 2;

    const uint32_t sQh_ = sb, sQl_ = sb + FQ_BYTES;
    const uint32_t st0 = sb + 2 * FQ_BYTES;

    {
        const char* gqh = (const char*)(Qh + (size_t)qbase * QDIM + h * FD);
        const char* gql = (const char*)(Ql + (size_t)qbase * QDIM + h * FD);
#pragma unroll
        for (int i = 0; i < 6; i++) {
            int idx = tid + i * 256;
            int row = idx / 12, seg = idx - row * 12;
            uint32_t d = row * FROW + seg * 16;
            size_t go = (size_t)row * (QDIM * 2) + seg * 16;
            CP_ASYNC16(sQh_ + d, gqh + go);
            CP_ASYNC16(sQl_ + d, gql + go);
        }
        flash_load_kv(st0, Kh, Vh, 0, hk, tid);
        CP_COMMIT();
    }

    float oacc[12][4];
#pragma unroll
    for (int j = 0; j < 12; j++)
#pragma unroll
        for (int q = 0; q < 4; q++) oacc[j][q] = 0.f;
    float m0 = -CUDART_INF_F, m1 = -CUDART_INF_F, l0 = 0.f, l1 = 0.f;

    const int a_row = (lane & 7) + ((lane >> 3) & 1) * 8;
    const int a_cs  = ((lane >> 4) & 1) * 16;
    const int b_row = (lane & 7) + ((lane >> 4) & 1) * 8;
    const int b_cs  = ((lane >> 3) & 1) * 16;
    const int t_row = (lane & 7) + ((lane >> 3) & 1) * 8;
    const int t_cs  = ((lane >> 4) & 1) * 16;

    const int qr_lo = qbase + wid * 16;
    const int row0  = qr_lo + (lane >> 2);

    for (int kb = 0; kb < nb; kb++) {
        if (kb + 1 < nb) {
            flash_load_kv(st0 + ((kb + 1) & 1) * STG_BYTES, Kh, Vh,
                          (kb + 1) * FBN, hk, tid);
            CP_COMMIT();
            CP_WAIT(1);
        } else {
            CP_WAIT(0);
        }
        __syncthreads();

        const int key0 = kb * FBN;
        if (key0 <= qr_lo + 15) {
            const uint32_t sKh_ = st0 + (kb & 1) * STG_BYTES;
            const uint32_t sVh_ = sKh_ + FKV_BYTES;

            float sacc[8][4];
#pragma unroll
            for (int j = 0; j < 8; j++)
#pragma unroll
                for (int q = 0; q < 4; q++) sacc[j][q] = 0.f;

            // S = Qh*Kh + Ql*Kh
#pragma unroll
            for (int pass = 0; pass < 2; pass++) {
                const uint32_t sa = pass ? sQl_ : sQh_;
#pragma unroll
                for (int ks = 0; ks < 6; ks++) {
                    uint32_t a0, a1, a2, a3;
                    LDSM_X4(a0, a1, a2, a3,
                            sa + (wid * 16 + a_row) * FROW + ks * 32 + a_cs);
#pragma unroll
                    for (int p = 0; p < 4; p++) {
                        uint32_t b0, b1, b2, b3;
                        LDSM_X4(b0, b1, b2, b3,
                                sKh_ + (p * 16 + b_row) * FROW + ks * 32 + b_cs);
                        mma_f16(sacc[2 * p],     a0, a1, a2, a3, b0, b1);
                        mma_f16(sacc[2 * p + 1], a0, a1, a2, a3, b2, b3);
                    }
                }
            }

            if (key0 + FBN - 1 > qr_lo) {
#pragma unroll
                for (int j = 0; j < 8; j++) {
                    int kcol = key0 + 8 * j + (lane & 3) * 2;
                    if (kcol     > row0)     sacc[j][0] = -CUDART_INF_F;
                    if (kcol + 1 > row0)     sacc[j][1] = -CUDART_INF_F;
                    if (kcol     > row0 + 8) sacc[j][2] = -CUDART_INF_F;
                    if (kcol + 1 > row0 + 8) sacc[j][3] = -CUDART_INF_F;
                }
            }

            float mx0 = sacc[0][0], mx1 = sacc[0][2];
#pragma unroll
            for (int j = 0; j < 8; j++) {
                mx0 = fmaxf(mx0, fmaxf(sacc[j][0], sacc[j][1]));
                mx1 = fmaxf(mx1, fmaxf(sacc[j][2], sacc[j][3]));
            }
            mx0 = fmaxf(mx0, __shfl_xor_sync(0xffffffffu, mx0, 1));
            mx0 = fmaxf(mx0, __shfl_xor_sync(0xffffffffu, mx0, 2));
            mx1 = fmaxf(mx1, __shfl_xor_sync(0xffffffffu, mx1, 1));
            mx1 = fmaxf(mx1, __shfl_xor_sync(0xffffffffu, mx1, 2));

            float mn0 = fmaxf(m0, mx0), mn1 = fmaxf(m1, mx1);
            float al0 = __expf(m0 - mn0), al1 = __expf(m1 - mn1);

            uint32_t ph[8][2], pl[8][2];
            float sum0 = 0.f, sum1 = 0.f;
#pragma unroll
            for (int j = 0; j < 8; j++) {
                float p0 = __expf(sacc[j][0] - mn0), p1 = __expf(sacc[j][1] - mn0);
                float p2 = __expf(sacc[j][2] - mn1), p3 = __expf(sacc[j][3] - mn1);
                sum0 += p0 + p1; sum1 += p2 + p3;
                __half2 h01 = __floats2half2_rn(p0, p1);
                __half2 h23 = __floats2half2_rn(p2, p3);
                ph[j][0] = *(uint32_t*)&h01;
                ph[j][1] = *(uint32_t*)&h23;
                float2 f01 = __half22float2(h01);
                float2 f23 = __half22float2(h23);
                __half2 l01 = __floats2half2_rn(p0 - f01.x, p1 - f01.y);
                __half2 l23 = __floats2half2_rn(p2 - f23.x, p3 - f23.y);
                pl[j][0] = *(uint32_t*)&l01;
                pl[j][1] = *(uint32_t*)&l23;
            }
            sum0 += __shfl_xor_sync(0xffffffffu, sum0, 1);
            sum0 += __shfl_xor_sync(0xffffffffu, sum0, 2);
            sum1 += __shfl_xor_sync(0xffffffffu, sum1, 1);
            sum1 += __shfl_xor_sync(0xffffffffu, sum1, 2);

            l0 = l0 * al0 + sum0;  l1 = l1 * al1 + sum1;
            m0 = mn0;              m1 = mn1;
#pragma unroll
            for (int j = 0; j < 12; j++) {
                oacc[j][0] *= al0; oacc[j][1] *= al0;
                oacc[j][2] *= al1; oacc[j][3] *= al1;
            }

            // O += Ph*Vh + Pl*Vh
#pragma unroll
            for (int kk = 0; kk < 4; kk++) {
                uint32_t a0 = ph[2 * kk][0], a1 = ph[2 * kk][1];
                uint32_t a2 = ph[2 * kk + 1][0], a3 = ph[2 * kk + 1][1];
                uint32_t c0 = pl[2 * kk][0], c1 = pl[2 * kk][1];
                uint32_t c2 = pl[2 * kk + 1][0], c3 = pl[2 * kk + 1][1];
#pragma unroll
                for (int p = 0; p < 6; p++) {
                    uint32_t vaddr = (16 * kk + t_row) * FROW + p * 32 + t_cs;
                    uint32_t b0, b1, b2, b3;
                    LDSM_X4_T(b0, b1, b2, b3, sVh_ + vaddr);
                    mma_f16(oacc[2 * p],     a0, a1, a2, a3, b0, b1);
                    mma_f16(oacc[2 * p + 1], a0, a1, a2, a3, b2, b3);
                    mma_f16(oacc[2 * p],     c0, c1, c2, c3, b0, b1);
                    mma_f16(oacc[2 * p + 1], c0, c1, c2, c3, b2, b3);
                }
            }
        }
        __syncthreads();
    }

    // epilogue: normalize + fp16 hi/lo split into [h|l] layout (row = 2*QDIM)
    const float inv0 = 1.f / l0, inv1 = 1.f / l1;
    __half* ob0 = AOs + (size_t)row0 * KP_O + h * FD + (lane & 3) * 2;
    __half* ob1 = AOs + (size_t)(row0 + 8) * KP_O + h * FD + (lane & 3) * 2;
#pragma unroll
    for (int j = 0; j < 12; j++) {
        float v0 = oacc[j][0] * inv0, v1 = oacc[j][1] * inv0;
        float v2 = oacc[j][2] * inv1, v3 = oacc[j][3] * inv1;
        __half2 h01 = __floats2half2_rn(v0, v1);
        float2 f01 = __half22float2(h01);
        __half2 l01 = __floats2half2_rn(v0 - f01.x, v1 - f01.y);
        __half2 h23 = __floats2half2_rn(v2, v3);
        float2 f23 = __half22float2(h23);
        __half2 l23 = __floats2half2_rn(v2 - f23.x, v3 - f23.y);
        *(__half2*)(ob0 + j * 8)        = h01;
        *(__half2*)(ob0 + QDIM + j * 8) = l01;
        *(__half2*)(ob1 + j * 8)        = h23;
        *(__half2*)(ob1 + QDIM + j * 8) = l23;
    }
}

// ---------------------------------------------------------------------------
extern "C" void kernel_launch(void* const* d_in, const int* in_sizes, int n_in,
                              void* d_out, int out_size)
{
    const float* hs  = (const float*)d_in[0];
    const float* cs  = (const float*)d_in[1];
    const float* sn  = (const float*)d_in[2];
    const int*   idx = (const int*)  d_in[3];
    const float* Wq  = (const float*)d_in[4];
    const float* Wk  = (const float*)d_in[5];
    const float* Wv  = (const float*)d_in[6];
    const float* Wo  = (const float*)d_in[7];
    float* out = (float*)d_out;

    float *Qb, *Kb, *Vb;
    __half *hsb, *wqb, *wkb, *wvb, *aob, *wob;
    __half *qh, *ql, *kh, *vh;
    cudaGetSymbolAddress((void**)&Qb,  g_Q);
    cudaGetSymbolAddress((void**)&Kb,  g_K);
    cudaGetSymbolAddress((void**)&Vb,  g_V);
    cudaGetSymbolAddress((void**)&hsb, g_hsb);
    cudaGetSymbolAddress((void**)&wqb, g_wqb);
    cudaGetSymbolAddress((void**)&wkb, g_wkb);
    cudaGetSymbolAddress((void**)&wvb, g_wvb);
    cudaGetSymbolAddress((void**)&aob, g_aob);
    cudaGetSymbolAddress((void**)&wob, g_wob);
    cudaGetSymbolAddress((void**)&qh,  g_Qh);
    cudaGetSymbolAddress((void**)&ql,  g_Ql);
    cudaGetSymbolAddress((void**)&kh,  g_Kh);
    cudaGetSymbolAddress((void**)&vh,  g_Vh);

    static bool attr_set = false;
    if (!attr_set) {
        cudaFuncSetAttribute(gemm_mma,  cudaFuncAttributeMaxDynamicSharedMemorySize, GEMM_SMEM);
        cudaFuncSetAttribute(flash_mma, cudaFuncAttributeMaxDynamicSharedMemorySize, FLASH_SMEM);
        attr_set = true;
    }

    // fused fp16 splits (one launch: hs [h|l] + 4 weights [h|h])
    {
        const int n0 = S_LEN * HIDDEN / 2, c0 = HIDDEN / 2;
        const int n1 = QDIM  * HIDDEN / 2, c1 = HIDDEN / 2;
        const int n2 = KVDIM * HIDDEN / 2, c2 = HIDDEN / 2;
        const int n3 = KVDIM * HIDDEN / 2, c3 = HIDDEN / 2;
        const int n4 = HIDDEN * QDIM  / 2, c4 = QDIM / 2;
        const int tot = n0 + n1 + n2 + n3 + n4;
        split_all<<<(tot + 255) / 256, 256>>>(
            hs, hsb, n0, c0,
            Wq, wqb, n1, c1,
            Wk, wkb, n2, c2,
            Wv, wvb, n3, c3,
            Wo, wob, n4, c4);
    }

    // fused QKV projection (fp16 2-term)
    gemm_mma<<<dim3(36, S_LEN / BM), 128, GEMM_SMEM>>>(
        hsb,
        wqb, Qb, QDIM / BN,  QDIM,
        wkb, Kb, KVDIM / BN, KVDIM,
        wvb, Vb,             KVDIM,
        KP_QKV);

    // fused RoPE+split (Q h/l, K h) + V fp16 convert, one launch
    {
        const int totQ = S_LEN * NH  * 48;
        const int totK = S_LEN * NKV * 48;
        const int totV = S_LEN * KVDIM / 2;
        const int tot = totQ + totK + totV;
        rope_split_all<<<(tot + 255) / 256, 256>>>(
            Qb, qh, ql, Kb, kh, Vb, vh, cs, sn, idx, totQ, totK, totV);
    }

    // causal GQA attention — writes fp16 [h|l] AO layout directly
    flash_mma<<<dim3(S_LEN / FBM, NH), 256, FLASH_SMEM>>>(qh, ql, kh, vh, aob);

    // output projection (fp16 2-term) -> d_out
    gemm_mma<<<dim3(HIDDEN / BN, S_LEN / BM), 128, GEMM_SMEM>>>(
        aob,
        wob, out, HIDDEN / BN, HIDDEN,
        wob, out, 0,           HIDDEN,
        wob, out,              HIDDEN,
        KP_O);
}

// round 13
// speedup vs baseline: 1.9825x; 1.2323x over previous
#include <cuda_runtime.h>
#include <cuda_bf16.h>
#include <cuda_fp16.h>
#include <math_constants.h>
#include <cstdint>

#define S_LEN  2048
#define HIDDEN 4096
#define NH     32
#define NKV    8
#define HD     96
#define GROUPS 4
#define QDIM   (NH * HD)    // 3072
#define KVDIM  (NKV * HD)   // 768
#define DFULL  128
#define ATT_SCALE 0.08838834764831845f  // 128^-0.5

#define KP_QKV (2 * HIDDEN)   // 8192 (fp16 2-term)
#define KP_O   QDIM           // 3072 (fp16 1-term)

// ---------------- scratch (allocation-free: device globals) ----------------
static __device__ __align__(256) float g_Q [S_LEN * QDIM];
static __device__ __align__(256) float g_K [S_LEN * KVDIM];
static __device__ __align__(256) float g_V [S_LEN * KVDIM];

static __device__ __align__(256) __half g_hsb[S_LEN * KP_QKV];   // [Ah|Al]
static __device__ __align__(256) __half g_wqb[QDIM * KP_QKV];    // [Wh|Wh]
static __device__ __align__(256) __half g_wkb[KVDIM * KP_QKV];
static __device__ __align__(256) __half g_wvb[KVDIM * KP_QKV];
static __device__ __align__(256) __half g_aob[S_LEN * KP_O];     // [h]
static __device__ __align__(256) __half g_wob[HIDDEN * KP_O];    // [h]

// flash operands (all fp16)
static __device__ __align__(256) __half g_Qh[S_LEN * QDIM];
static __device__ __align__(256) __half g_Ql[S_LEN * QDIM];
static __device__ __align__(256) __half g_Kh[S_LEN * KVDIM];
static __device__ __align__(256) __half g_Vh[S_LEN * KVDIM];

// ---------------------------------------------------------------------------
// PTX helpers
// ---------------------------------------------------------------------------
__device__ __forceinline__ uint32_t smem_u32(const void* p) {
    uint32_t a;
    asm("{ .reg .u64 t; cvta.to.shared.u64 t, %1; cvt.u32.u64 %0, t; }" : "=r"(a) : "l"(p));
    return a;
}
#define CP_ASYNC16(dst, src) asm volatile("cp.async.cg.shared.global [%0], [%1], 16;" :: "r"(dst), "l"(src))
#define CP_COMMIT()          asm volatile("cp.async.commit_group;" ::: "memory")
#define CP_WAIT(n)           asm volatile("cp.async.wait_group %0;" :: "n"(n) : "memory")

#define LDSM_X4(r0, r1, r2, r3, addr)                                            \
    asm volatile("ldmatrix.sync.aligned.m8n8.x4.shared.b16 {%0,%1,%2,%3}, [%4];" \
        : "=r"(r0), "=r"(r1), "=r"(r2), "=r"(r3) : "r"(addr))

#define LDSM_X4_T(r0, r1, r2, r3, addr)                                                \
    asm volatile("ldmatrix.sync.aligned.m8n8.x4.trans.shared.b16 {%0,%1,%2,%3}, [%4];" \
        : "=r"(r0), "=r"(r1), "=r"(r2), "=r"(r3) : "r"(addr))

__device__ __forceinline__ void mma_f16(float* c, uint32_t a0, uint32_t a1,
                                        uint32_t a2, uint32_t a3,
                                        uint32_t b0, uint32_t b1) {
    asm volatile(
        "mma.sync.aligned.m16n8k16.row.col.f32.f16.f16.f32 "
        "{%0,%1,%2,%3}, {%4,%5,%6,%7}, {%8,%9}, {%0,%1,%2,%3};"
        : "+f"(c[0]), "+f"(c[1]), "+f"(c[2]), "+f"(c[3])
        : "r"(a0), "r"(a1), "r"(a2), "r"(a3), "r"(b0), "r"(b1));
}

// ---------------------------------------------------------------------------
// fp16 HMMA GEMM over concatenated-K layout.
// BM=128, BN=128, BK=64, 2-stage cp.async pipeline, 4 warps, warp tile 64x64.
// launch_bounds(128,3) -> 3 CTAs/SM. Segmented over N (up to 3 segments).
// ---------------------------------------------------------------------------
#define BM 128
#define BN 128
#define BKE 64
#define ROW_B 144
#define TILE_BYTES (128 * ROW_B)
#define STAGE_BYTES (2 * TILE_BYTES)
#define NSTAGE 2
#define GEMM_SMEM (NSTAGE * STAGE_BYTES)   // 73728

__device__ __forceinline__ void load_tiles(uint32_t stage_base,
    const __half* __restrict__ A, const __half* __restrict__ B,
    int bm, int bn, int kc, int Kp, int tid)
{
    const char* Ag = (const char*)(A + (size_t)bm * Kp + kc * BKE);
    const char* Bg = (const char*)(B + (size_t)bn * Kp + kc * BKE);
    const size_t rowb = (size_t)Kp * 2;
    const uint32_t sA = stage_base;
    const uint32_t sB = stage_base + TILE_BYTES;
#pragma unroll
    for (int i = 0; i < 8; i++) {
        int idx = tid + i * 128;
        int row = idx >> 3, seg = idx & 7;
        CP_ASYNC16(sA + row * ROW_B + seg * 16, Ag + (size_t)row * rowb + seg * 16);
    }
#pragma unroll
    for (int i = 0; i < 8; i++) {
        int idx = tid + i * 128;
        int row = idx >> 3, seg = idx & 7;
        CP_ASYNC16(sB + row * ROW_B + seg * 16, Bg + (size_t)row * rowb + seg * 16);
    }
}

__global__ __launch_bounds__(128, 3) void gemm_mma(
    const __half* __restrict__ A,
    const __half* __restrict__ B0, float* __restrict__ C0, int nt0, int N0,
    const __half* __restrict__ B1, float* __restrict__ C1, int nt1, int N1,
    const __half* __restrict__ B2, float* __restrict__ C2, int N2,
    int Kp)
{
    extern __shared__ char smem[];
    const uint32_t sbase = smem_u32(smem);
    const int tid  = threadIdx.x;
    const int wid  = tid >> 5;
    const int lane = tid & 31;
    const int bm   = blockIdx.y * BM;
    const int NC   = Kp / BKE;

    int bnt = blockIdx.x;
    const __half* B;
    float* C; int N;
    if (bnt < nt0)            { B = B0; C = C0; N = N0; }
    else if (bnt < nt0 + nt1) { B = B1; C = C1; N = N1; bnt -= nt0; }
    else                      { B = B2; C = C2; N = N2; bnt -= nt0 + nt1; }
    const int bn = bnt * BN;

    const int wm = (wid >> 1) * 64;
    const int wn = (wid & 1) * 64;

    float acc[4][8][4];
#pragma unroll
    for (int t = 0; t < 4; t++)
#pragma unroll
        for (int j = 0; j < 8; j++)
#pragma unroll
            for (int q = 0; q < 4; q++) acc[t][j][q] = 0.f;

    const int a_row    = ((lane >> 3) & 1) * 8 + (lane & 7);
    const int a_cshift = ((lane >> 4) & 1) * 16;
    const int b_row    = ((lane >> 4) & 1) * 8 + (lane & 7);
    const int b_cshift = ((lane >> 3) & 1) * 16;

    load_tiles(sbase, A, B, bm, bn, 0, Kp, tid); CP_COMMIT();

    for (int c = 0; c < NC; c++) {
        CP_WAIT(0);
        __syncthreads();

        if (c + 1 < NC) {
            load_tiles(sbase + ((c + 1) & 1) * STAGE_BYTES, A, B, bm, bn, c + 1, Kp, tid);
            CP_COMMIT();
        }

        const uint32_t sA = sbase + (c & 1) * STAGE_BYTES;
        const uint32_t sB = sA + TILE_BYTES;
#pragma unroll
        for (int ks = 0; ks < 4; ks++) {
            uint32_t a[4][4];
#pragma unroll
            for (int t = 0; t < 4; t++) {
                uint32_t addr = sA + (wm + t * 16 + a_row) * ROW_B + ks * 32 + a_cshift;
                LDSM_X4(a[t][0], a[t][1], a[t][2], a[t][3], addr);
            }
#pragma unroll
            for (int p = 0; p < 4; p++) {
                uint32_t b0, b1, b2, b3;
                uint32_t addr = sB + (wn + p * 16 + b_row) * ROW_B + ks * 32 + b_cshift;
                LDSM_X4(b0, b1, b2, b3, addr);
#pragma unroll
                for (int t = 0; t < 4; t++) {
                    mma_f16(acc[t][2 * p],     a[t][0], a[t][1], a[t][2], a[t][3], b0, b1);
                    mma_f16(acc[t][2 * p + 1], a[t][0], a[t][1], a[t][2], a[t][3], b2, b3);
                }
            }
        }
    }

#pragma unroll
    for (int t = 0; t < 4; t++) {
        const int r0 = bm + wm + t * 16 + (lane >> 2);
#pragma unroll
        for (int j = 0; j < 8; j++) {
            const int col = bn + wn + j * 8 + (lane & 3) * 2;
            float* c0 = C + (size_t)r0 * N + col;
            float* c1 = C + (size_t)(r0 + 8) * N + col;
            *(float2*)c0 = make_float2(acc[t][j][0], acc[t][j][1]);
            *(float2*)c1 = make_float2(acc[t][j][2], acc[t][j][3]);
        }
    }
}

// ---------------------------------------------------------------------------
// Fused fp16 splits (one launch):
//   mode 0 -> [h|l] (2 segments), mode 1 -> [h|h] (2 segments), mode 2 -> flat h.
// ---------------------------------------------------------------------------
__device__ __forceinline__ void do_split_h2(const float* X, __half* Y,
                                            int t, int Cpairs, int mode)
{
    float2 x = ((const float2*)X)[t];
    __half2 h = __floats2half2_rn(x.x, x.y);
    uint32_t hv = *(uint32_t*)&h;
    if (mode == 2) { ((uint32_t*)Y)[t] = hv; return; }
    int r = t / Cpairs, c = t - r * Cpairs;
    uint32_t* row = (uint32_t*)(Y + (size_t)r * 4 * Cpairs);
    if (mode == 0) {
        float2 f = __half22float2(h);
        __half2 l = __floats2half2_rn(x.x - f.x, x.y - f.y);
        row[c] = hv; row[Cpairs + c] = *(uint32_t*)&l;
    } else {
        row[c] = hv; row[Cpairs + c] = hv;
    }
}

__global__ void split_all(const float* __restrict__ x0, __half* y0, int n0, int c0,
                          const float* __restrict__ x1, __half* y1, int n1, int c1,
                          const float* __restrict__ x2, __half* y2, int n2, int c2,
                          const float* __restrict__ x3, __half* y3, int n3, int c3,
                          const float* __restrict__ x4, __half* y4, int n4, int c4)
{
    int t = blockIdx.x * blockDim.x + threadIdx.x;
    if      (t < n0)         { do_split_h2(x0, y0, t, c0, 0); }
    else if ((t -= n0) < n1) { do_split_h2(x1, y1, t, c1, 1); }
    else if ((t -= n1) < n2) { do_split_h2(x2, y2, t, c2, 1); }
    else if ((t -= n2) < n3) { do_split_h2(x3, y3, t, c3, 1); }
    else if ((t -= n3) < n4) { do_split_h2(x4, y4, t, c4, 2); }
}

// ---------------------------------------------------------------------------
// Fused indexed RoPE (fp16 out) + V fp16 convert, one launch.
// Q: hi/lo fp16 split (scaled); K: hi only.
// ---------------------------------------------------------------------------
__device__ __forceinline__ void do_rope(const float* X,
                                        __half* Xh, __half* Xl, bool write_lo,
                                        const float* cosT, const float* sinT,
                                        const int* idx, int nheads, int group,
                                        float scale, int t)
{
    int d = t % 48;
    int h = (t / 48) % nheads;
    int s = t / (48 * nheads);
    int hk = h / group;

    const float* base = X + (size_t)s * (nheads * HD) + h * HD;
    float x1 = base[d];
    float x2 = base[d + 48];

    int i1 = idx[hk * HD + d];
    int i2 = idx[hk * HD + d + 48];
    float c1 = cosT[s * DFULL + i1], s1 = sinT[s * DFULL + i1];
    float c2 = cosT[s * DFULL + i2], s2 = sinT[s * DFULL + i2];

    float lo = (x1 * c1 - x2 * s1) * scale;
    float hi = (x2 * c2 + x1 * s2) * scale;

    size_t o = (size_t)s * (nheads * HD) + h * HD;
    __half bh = __float2half_rn(lo);
    Xh[o + d] = bh;
    if (write_lo) Xl[o + d] = __float2half_rn(lo - __half2float(bh));
    bh = __float2half_rn(hi);
    Xh[o + d + 48] = bh;
    if (write_lo) Xl[o + d + 48] = __float2half_rn(hi - __half2float(bh));
}

__global__ void rope_split_all(
    const float* __restrict__ Qs, __half* Qh, __half* Ql,
    const float* __restrict__ Ks, __half* Kh,
    const float* __restrict__ Vs, __half* Vh,
    const float* __restrict__ cosT, const float* __restrict__ sinT,
    const int* __restrict__ idx, int totQ, int totK, int totVpairs)
{
    int t = blockIdx.x * blockDim.x + threadIdx.x;
    if (t < totQ) {
        do_rope(Qs, Qh, Ql, true, cosT, sinT, idx, NH, GROUPS, ATT_SCALE, t);
        return;
    }
    t -= totQ;
    if (t < totK) {
        do_rope(Ks, Kh, nullptr, false, cosT, sinT, idx, NKV, 1, 1.0f, t);
        return;
    }
    t -= totK;
    if (t < totVpairs) {
        float2 x = ((const float2*)Vs)[t];
        __half2 h = __floats2half2_rn(x.x, x.y);
        ((uint32_t*)Vh)[t] = *(uint32_t*)&h;
    }
}

// ---------------------------------------------------------------------------
// fp16 HMMA flash attention, causal GQA. CTA = 128 q-rows x 1 head, 8 warps.
// 64-key blocks, double-buffered cp.async KV stages (Kh + Vh fp16).
// S = QhKh + QlKh;  O += PhVh (P 1-term).  Epilogue writes flat fp16 AO.
// ---------------------------------------------------------------------------
#define FD   96
#define FBM  128
#define FBN  64
#define FROW 208
#define FQ_BYTES  (FBM * FROW)
#define FKV_BYTES (FBN * FROW)
#define STG_BYTES (2 * FKV_BYTES)
#define FLASH_SMEM (2 * FQ_BYTES + 2 * STG_BYTES)   // 106496

__device__ __forceinline__ void flash_load_kv(uint32_t st_base,
    const __half* Kh, const __half* Vh, int key0, int hk, int tid)
{
    const size_t goff = (size_t)key0 * (KVDIM * 2) + hk * (FD * 2);
    const char* g0 = (const char*)Kh + goff;
    const char* g1 = (const char*)Vh + goff;
#pragma unroll
    for (int i = 0; i < 3; i++) {
        int idx = tid + i * 256;
        int row = idx / 12, seg = idx - row * 12;
        uint32_t d = st_base + row * FROW + seg * 16;
        size_t go = (size_t)row * (KVDIM * 2) + seg * 16;
        CP_ASYNC16(d,             g0 + go);
        CP_ASYNC16(d + FKV_BYTES, g1 + go);
    }
}

__global__ __launch_bounds__(256, 1) void flash_mma(
    const __half* __restrict__ Qh, const __half* __restrict__ Ql,
    const __half* __restrict__ Kh, const __half* __restrict__ Vh,
    __half* __restrict__ AOs)
{
    extern __shared__ char smem[];
    const uint32_t sb = smem_u32(smem);
    const int tid = threadIdx.x, wid = tid >> 5, lane = tid & 31;
    const int h = blockIdx.y, hk = h / GROUPS;
    const int qbase = ((int)gridDim.x - 1 - (int)blockIdx.x) * FBM;  // heavy first
    const int nb = qbase / FBN + 2;

    const uint32_t sQh_ = sb, sQl_ = sb + FQ_BYTES;
    const uint32_t st0 = sb + 2 * FQ_BYTES;

    {
        const char* gqh = (const char*)(Qh + (size_t)qbase * QDIM + h * FD);
        const char* gql = (const char*)(Ql + (size_t)qbase * QDIM + h * FD);
#pragma unroll
        for (int i = 0; i < 6; i++) {
            int idx = tid + i * 256;
            int row = idx / 12, seg = idx - row * 12;
            uint32_t d = row * FROW + seg * 16;
            size_t go = (size_t)row * (QDIM * 2) + seg * 16;
            CP_ASYNC16(sQh_ + d, gqh + go);
            CP_ASYNC16(sQl_ + d, gql + go);
        }
        flash_load_kv(st0, Kh, Vh, 0, hk, tid);
        CP_COMMIT();
    }

    float oacc[12][4];
#pragma unroll
    for (int j = 0; j < 12; j++)
#pragma unroll
        for (int q = 0; q < 4; q++) oacc[j][q] = 0.f;
    float m0 = -CUDART_INF_F, m1 = -CUDART_INF_F, l0 = 0.f, l1 = 0.f;

    const int a_row = (lane & 7) + ((lane >> 3) & 1) * 8;
    const int a_cs  = ((lane >> 4) & 1) * 16;
    const int b_row = (lane & 7) + ((lane >> 4) & 1) * 8;
    const int b_cs  = ((lane >> 3) & 1) * 16;
    const int t_row = (lane & 7) + ((lane >> 3) & 1) * 8;
    const int t_cs  = ((lane >> 4) & 1) * 16;

    const int qr_lo = qbase + wid * 16;
    const int row0  = qr_lo + (lane >> 2);

    for (int kb = 0; kb < nb; kb++) {
        if (kb + 1 < nb) {
            flash_load_kv(st0 + ((kb + 1) & 1) * STG_BYTES, Kh, Vh,
                          (kb + 1) * FBN, hk, tid);
            CP_COMMIT();
            CP_WAIT(1);
        } else {
            CP_WAIT(0);
        }
        __syncthreads();

        const int key0 = kb * FBN;
        if (key0 <= qr_lo + 15) {
            const uint32_t sKh_ = st0 + (kb & 1) * STG_BYTES;
            const uint32_t sVh_ = sKh_ + FKV_BYTES;

            float sacc[8][4];
#pragma unroll
            for (int j = 0; j < 8; j++)
#pragma unroll
                for (int q = 0; q < 4; q++) sacc[j][q] = 0.f;

            // S = Qh*Kh + Ql*Kh
#pragma unroll
            for (int pass = 0; pass < 2; pass++) {
                const uint32_t sa = pass ? sQl_ : sQh_;
#pragma unroll
                for (int ks = 0; ks < 6; ks++) {
                    uint32_t a0, a1, a2, a3;
                    LDSM_X4(a0, a1, a2, a3,
                            sa + (wid * 16 + a_row) * FROW + ks * 32 + a_cs);
#pragma unroll
                    for (int p = 0; p < 4; p++) {
                        uint32_t b0, b1, b2, b3;
                        LDSM_X4(b0, b1, b2, b3,
                                sKh_ + (p * 16 + b_row) * FROW + ks * 32 + b_cs);
                        mma_f16(sacc[2 * p],     a0, a1, a2, a3, b0, b1);
                        mma_f16(sacc[2 * p + 1], a0, a1, a2, a3, b2, b3);
                    }
                }
            }

            if (key0 + FBN - 1 > qr_lo) {
#pragma unroll
                for (int j = 0; j < 8; j++) {
                    int kcol = key0 + 8 * j + (lane & 3) * 2;
                    if (kcol     > row0)     sacc[j][0] = -CUDART_INF_F;
                    if (kcol + 1 > row0)     sacc[j][1] = -CUDART_INF_F;
                    if (kcol     > row0 + 8) sacc[j][2] = -CUDART_INF_F;
                    if (kcol + 1 > row0 + 8) sacc[j][3] = -CUDART_INF_F;
                }
            }

            float mx0 = sacc[0][0], mx1 = sacc[0][2];
#pragma unroll
            for (int j = 0; j < 8; j++) {
                mx0 = fmaxf(mx0, fmaxf(sacc[j][0], sacc[j][1]));
                mx1 = fmaxf(mx1, fmaxf(sacc[j][2], sacc[j][3]));
            }
            mx0 = fmaxf(mx0, __shfl_xor_sync(0xffffffffu, mx0, 1));
            mx0 = fmaxf(mx0, __shfl_xor_sync(0xffffffffu, mx0, 2));
            mx1 = fmaxf(mx1, __shfl_xor_sync(0xffffffffu, mx1, 1));
            mx1 = fmaxf(mx1, __shfl_xor_sync(0xffffffffu, mx1, 2));

            float mn0 = fmaxf(m0, mx0), mn1 = fmaxf(m1, mx1);
            float al0 = __expf(m0 - mn0), al1 = __expf(m1 - mn1);

            uint32_t ph[8][2];
            float sum0 = 0.f, sum1 = 0.f;
#pragma unroll
            for (int j = 0; j < 8; j++) {
                float p0 = __expf(sacc[j][0] - mn0), p1 = __expf(sacc[j][1] - mn0);
                float p2 = __expf(sacc[j][2] - mn1), p3 = __expf(sacc[j][3] - mn1);
                sum0 += p0 + p1; sum1 += p2 + p3;
                __half2 h01 = __floats2half2_rn(p0, p1);
                __half2 h23 = __floats2half2_rn(p2, p3);
                ph[j][0] = *(uint32_t*)&h01;
                ph[j][1] = *(uint32_t*)&h23;
            }
            sum0 += __shfl_xor_sync(0xffffffffu, sum0, 1);
            sum0 += __shfl_xor_sync(0xffffffffu, sum0, 2);
            sum1 += __shfl_xor_sync(0xffffffffu, sum1, 1);
            sum1 += __shfl_xor_sync(0xffffffffu, sum1, 2);

            l0 = l0 * al0 + sum0;  l1 = l1 * al1 + sum1;
            m0 = mn0;              m1 = mn1;
#pragma unroll
            for (int j = 0; j < 12; j++) {
                oacc[j][0] *= al0; oacc[j][1] *= al0;
                oacc[j][2] *= al1; oacc[j][3] *= al1;
            }

            // O += Ph*Vh
#pragma unroll
            for (int kk = 0; kk < 4; kk++) {
                uint32_t a0 = ph[2 * kk][0], a1 = ph[2 * kk][1];
                uint32_t a2 = ph[2 * kk + 1][0], a3 = ph[2 * kk + 1][1];
#pragma unroll
                for (int p = 0; p < 6; p++) {
                    uint32_t vaddr = (16 * kk + t_row) * FROW + p * 32 + t_cs;
                    uint32_t b0, b1, b2, b3;
                    LDSM_X4_T(b0, b1, b2, b3, sVh_ + vaddr);
                    mma_f16(oacc[2 * p],     a0, a1, a2, a3, b0, b1);
                    mma_f16(oacc[2 * p + 1], a0, a1, a2, a3, b2, b3);
                }
            }
        }
        __syncthreads();
    }

    // epilogue: normalize + flat fp16 store (row = KP_O = QDIM)
    const float inv0 = 1.f / l0, inv1 = 1.f / l1;
    __half* ob0 = AOs + (size_t)row0 * KP_O + h * FD + (lane & 3) * 2;
    __half* ob1 = AOs + (size_t)(row0 + 8) * KP_O + h * FD + (lane & 3) * 2;
#pragma unroll
    for (int j = 0; j < 12; j++) {
        *(__half2*)(ob0 + j * 8) = __floats2half2_rn(oacc[j][0] * inv0, oacc[j][1] * inv0);
        *(__half2*)(ob1 + j * 8) = __floats2half2_rn(oacc[j][2] * inv1, oacc[j][3] * inv1);
    }
}

// ---------------------------------------------------------------------------
extern "C" void kernel_launch(void* const* d_in, const int* in_sizes, int n_in,
                              void* d_out, int out_size)
{
    const float* hs  = (const float*)d_in[0];
    const float* cs  = (const float*)d_in[1];
    const float* sn  = (const float*)d_in[2];
    const int*   idx = (const int*)  d_in[3];
    const float* Wq  = (const float*)d_in[4];
    const float* Wk  = (const float*)d_in[5];
    const float* Wv  = (const float*)d_in[6];
    const float* Wo  = (const float*)d_in[7];
    float* out = (float*)d_out;

    float *Qb, *Kb, *Vb;
    __half *hsb, *wqb, *wkb, *wvb, *aob, *wob;
    __half *qh, *ql, *kh, *vh;
    cudaGetSymbolAddress((void**)&Qb,  g_Q);
    cudaGetSymbolAddress((void**)&Kb,  g_K);
    cudaGetSymbolAddress((void**)&Vb,  g_V);
    cudaGetSymbolAddress((void**)&hsb, g_hsb);
    cudaGetSymbolAddress((void**)&wqb, g_wqb);
    cudaGetSymbolAddress((void**)&wkb, g_wkb);
    cudaGetSymbolAddress((void**)&wvb, g_wvb);
    cudaGetSymbolAddress((void**)&aob, g_aob);
    cudaGetSymbolAddress((void**)&wob, g_wob);
    cudaGetSymbolAddress((void**)&qh,  g_Qh);
    cudaGetSymbolAddress((void**)&ql,  g_Ql);
    cudaGetSymbolAddress((void**)&kh,  g_Kh);
    cudaGetSymbolAddress((void**)&vh,  g_Vh);

    static bool attr_set = false;
    if (!attr_set) {
        cudaFuncSetAttribute(gemm_mma,  cudaFuncAttributeMaxDynamicSharedMemorySize, GEMM_SMEM);
        cudaFuncSetAttribute(flash_mma, cudaFuncAttributeMaxDynamicSharedMemorySize, FLASH_SMEM);
        attr_set = true;
    }

    // fused fp16 splits (one launch: hs [h|l], QKV weights [h|h], Wo flat h)
    {
        const int n0 = S_LEN * HIDDEN / 2, c0 = HIDDEN / 2;
        const int n1 = QDIM  * HIDDEN / 2, c1 = HIDDEN / 2;
        const int n2 = KVDIM * HIDDEN / 2, c2 = HIDDEN / 2;
        const int n3 = KVDIM * HIDDEN / 2, c3 = HIDDEN / 2;
        const int n4 = HIDDEN * QDIM  / 2, c4 = QDIM / 2;
        const int tot = n0 + n1 + n2 + n3 + n4;
        split_all<<<(tot + 255) / 256, 256>>>(
            hs, hsb, n0, c0,
            Wq, wqb, n1, c1,
            Wk, wkb, n2, c2,
            Wv, wvb, n3, c3,
            Wo, wob, n4, c4);
    }

    // fused QKV projection (fp16 2-term)
    gemm_mma<<<dim3(36, S_LEN / BM), 128, GEMM_SMEM>>>(
        hsb,
        wqb, Qb, QDIM / BN,  QDIM,
        wkb, Kb, KVDIM / BN, KVDIM,
        wvb, Vb,             KVDIM,
        KP_QKV);

    // fused RoPE+split (Q h/l, K h) + V fp16 convert, one launch
    {
        const int totQ = S_LEN * NH  * 48;
        const int totK = S_LEN * NKV * 48;
        const int totV = S_LEN * KVDIM / 2;
        const int tot = totQ + totK + totV;
        rope_split_all<<<(tot + 255) / 256, 256>>>(
            Qb, qh, ql, Kb, kh, Vb, vh, cs, sn, idx, totQ, totK, totV);
    }

    // causal GQA attention — writes flat fp16 AO
    flash_mma<<<dim3(S_LEN / FBM, NH), 256, FLASH_SMEM>>>(qh, ql, kh, vh, aob);

    // output projection (fp16 1-term) -> d_out
    gemm_mma<<<dim3(HIDDEN / BN, S_LEN / BM), 128, GEMM_SMEM>>>(
        aob,
        wob, out, HIDDEN / BN, HIDDEN,
        wob, out, 0,           HIDDEN,
        wob, out,              HIDDEN,
        KP_O);
}

// round 14
// speedup vs baseline: 2.6388x; 1.3310x over previous
#include <cuda_runtime.h>
#include <cuda_bf16.h>
#include <cuda_fp16.h>
#include <math_constants.h>
#include <cstdint>

#define S_LEN  2048
#define HIDDEN 4096
#define NH     32
#define NKV    8
#define HD     96
#define GROUPS 4
#define QDIM   (NH * HD)    // 3072
#define KVDIM  (NKV * HD)   // 768
#define DFULL  128
#define ATT_SCALE 0.08838834764831845f  // 128^-0.5

#define KP_QKV HIDDEN         // 4096 (fp16 1-term)
#define KP_O   QDIM           // 3072 (fp16 1-term)

// ---------------- scratch (allocation-free: device globals) ----------------
static __device__ __align__(256) float g_Q [S_LEN * QDIM];
static __device__ __align__(256) float g_K [S_LEN * KVDIM];
static __device__ __align__(256) float g_V [S_LEN * KVDIM];

static __device__ __align__(256) __half g_hsb[S_LEN * KP_QKV];   // flat h
static __device__ __align__(256) __half g_wqb[QDIM * KP_QKV];    // flat h
static __device__ __align__(256) __half g_wkb[KVDIM * KP_QKV];
static __device__ __align__(256) __half g_wvb[KVDIM * KP_QKV];
static __device__ __align__(256) __half g_aob[S_LEN * KP_O];     // flat h
static __device__ __align__(256) __half g_wob[HIDDEN * KP_O];    // flat h

// flash operands (all fp16; Q keeps hi/lo)
static __device__ __align__(256) __half g_Qh[S_LEN * QDIM];
static __device__ __align__(256) __half g_Ql[S_LEN * QDIM];
static __device__ __align__(256) __half g_Kh[S_LEN * KVDIM];
static __device__ __align__(256) __half g_Vh[S_LEN * KVDIM];

// ---------------------------------------------------------------------------
// PTX helpers
// ---------------------------------------------------------------------------
__device__ __forceinline__ uint32_t smem_u32(const void* p) {
    uint32_t a;
    asm("{ .reg .u64 t; cvta.to.shared.u64 t, %1; cvt.u32.u64 %0, t; }" : "=r"(a) : "l"(p));
    return a;
}
#define CP_ASYNC16(dst, src) asm volatile("cp.async.cg.shared.global [%0], [%1], 16;" :: "r"(dst), "l"(src))
#define CP_COMMIT()          asm volatile("cp.async.commit_group;" ::: "memory")
#define CP_WAIT(n)           asm volatile("cp.async.wait_group %0;" :: "n"(n) : "memory")

#define LDSM_X4(r0, r1, r2, r3, addr)                                            \
    asm volatile("ldmatrix.sync.aligned.m8n8.x4.shared.b16 {%0,%1,%2,%3}, [%4];" \
        : "=r"(r0), "=r"(r1), "=r"(r2), "=r"(r3) : "r"(addr))

#define LDSM_X4_T(r0, r1, r2, r3, addr)                                                \
    asm volatile("ldmatrix.sync.aligned.m8n8.x4.trans.shared.b16 {%0,%1,%2,%3}, [%4];" \
        : "=r"(r0), "=r"(r1), "=r"(r2), "=r"(r3) : "r"(addr))

__device__ __forceinline__ void mma_f16(float* c, uint32_t a0, uint32_t a1,
                                        uint32_t a2, uint32_t a3,
                                        uint32_t b0, uint32_t b1) {
    asm volatile(
        "mma.sync.aligned.m16n8k16.row.col.f32.f16.f16.f32 "
        "{%0,%1,%2,%3}, {%4,%5,%6,%7}, {%8,%9}, {%0,%1,%2,%3};"
        : "+f"(c[0]), "+f"(c[1]), "+f"(c[2]), "+f"(c[3])
        : "r"(a0), "r"(a1), "r"(a2), "r"(a3), "r"(b0), "r"(b1));
}

// ---------------------------------------------------------------------------
// fp16 HMMA GEMM.
// BM=128, BN=128, BK=64, 2-stage cp.async pipeline, 4 warps, warp tile 64x64.
// launch_bounds(128,3) -> 3 CTAs/SM. Segmented over N (up to 3 segments).
// ---------------------------------------------------------------------------
#define BM 128
#define BN 128
#define BKE 64
#define ROW_B 144
#define TILE_BYTES (128 * ROW_B)
#define STAGE_BYTES (2 * TILE_BYTES)
#define NSTAGE 2
#define GEMM_SMEM (NSTAGE * STAGE_BYTES)   // 73728

__device__ __forceinline__ void load_tiles(uint32_t stage_base,
    const __half* __restrict__ A, const __half* __restrict__ B,
    int bm, int bn, int kc, int Kp, int tid)
{
    const char* Ag = (const char*)(A + (size_t)bm * Kp + kc * BKE);
    const char* Bg = (const char*)(B + (size_t)bn * Kp + kc * BKE);
    const size_t rowb = (size_t)Kp * 2;
    const uint32_t sA = stage_base;
    const uint32_t sB = stage_base + TILE_BYTES;
#pragma unroll
    for (int i = 0; i < 8; i++) {
        int idx = tid + i * 128;
        int row = idx >> 3, seg = idx & 7;
        CP_ASYNC16(sA + row * ROW_B + seg * 16, Ag + (size_t)row * rowb + seg * 16);
    }
#pragma unroll
    for (int i = 0; i < 8; i++) {
        int idx = tid + i * 128;
        int row = idx >> 3, seg = idx & 7;
        CP_ASYNC16(sB + row * ROW_B + seg * 16, Bg + (size_t)row * rowb + seg * 16);
    }
}

__global__ __launch_bounds__(128, 3) void gemm_mma(
    const __half* __restrict__ A,
    const __half* __restrict__ B0, float* __restrict__ C0, int nt0, int N0,
    const __half* __restrict__ B1, float* __restrict__ C1, int nt1, int N1,
    const __half* __restrict__ B2, float* __restrict__ C2, int N2,
    int Kp)
{
    extern __shared__ char smem[];
    const uint32_t sbase = smem_u32(smem);
    const int tid  = threadIdx.x;
    const int wid  = tid >> 5;
    const int lane = tid & 31;
    const int bm   = blockIdx.y * BM;
    const int NC   = Kp / BKE;

    int bnt = blockIdx.x;
    const __half* B;
    float* C; int N;
    if (bnt < nt0)            { B = B0; C = C0; N = N0; }
    else if (bnt < nt0 + nt1) { B = B1; C = C1; N = N1; bnt -= nt0; }
    else                      { B = B2; C = C2; N = N2; bnt -= nt0 + nt1; }
    const int bn = bnt * BN;

    const int wm = (wid >> 1) * 64;
    const int wn = (wid & 1) * 64;

    float acc[4][8][4];
#pragma unroll
    for (int t = 0; t < 4; t++)
#pragma unroll
        for (int j = 0; j < 8; j++)
#pragma unroll
            for (int q = 0; q < 4; q++) acc[t][j][q] = 0.f;

    const int a_row    = ((lane >> 3) & 1) * 8 + (lane & 7);
    const int a_cshift = ((lane >> 4) & 1) * 16;
    const int b_row    = ((lane >> 4) & 1) * 8 + (lane & 7);
    const int b_cshift = ((lane >> 3) & 1) * 16;

    load_tiles(sbase, A, B, bm, bn, 0, Kp, tid); CP_COMMIT();

    for (int c = 0; c < NC; c++) {
        CP_WAIT(0);
        __syncthreads();

        if (c + 1 < NC) {
            load_tiles(sbase + ((c + 1) & 1) * STAGE_BYTES, A, B, bm, bn, c + 1, Kp, tid);
            CP_COMMIT();
        }

        const uint32_t sA = sbase + (c & 1) * STAGE_BYTES;
        const uint32_t sB = sA + TILE_BYTES;
#pragma unroll
        for (int ks = 0; ks < 4; ks++) {
            uint32_t a[4][4];
#pragma unroll
            for (int t = 0; t < 4; t++) {
                uint32_t addr = sA + (wm + t * 16 + a_row) * ROW_B + ks * 32 + a_cshift;
                LDSM_X4(a[t][0], a[t][1], a[t][2], a[t][3], addr);
            }
#pragma unroll
            for (int p = 0; p < 4; p++) {
                uint32_t b0, b1, b2, b3;
                uint32_t addr = sB + (wn + p * 16 + b_row) * ROW_B + ks * 32 + b_cshift;
                LDSM_X4(b0, b1, b2, b3, addr);
#pragma unroll
                for (int t = 0; t < 4; t++) {
                    mma_f16(acc[t][2 * p],     a[t][0], a[t][1], a[t][2], a[t][3], b0, b1);
                    mma_f16(acc[t][2 * p + 1], a[t][0], a[t][1], a[t][2], a[t][3], b2, b3);
                }
            }
        }
    }

#pragma unroll
    for (int t = 0; t < 4; t++) {
        const int r0 = bm + wm + t * 16 + (lane >> 2);
#pragma unroll
        for (int j = 0; j < 8; j++) {
            const int col = bn + wn + j * 8 + (lane & 3) * 2;
            float* c0 = C + (size_t)r0 * N + col;
            float* c1 = C + (size_t)(r0 + 8) * N + col;
            *(float2*)c0 = make_float2(acc[t][j][0], acc[t][j][1]);
            *(float2*)c1 = make_float2(acc[t][j][2], acc[t][j][3]);
        }
    }
}

// ---------------------------------------------------------------------------
// Fused flat fp32 -> fp16 conversions over 5 regions, one launch.
// ---------------------------------------------------------------------------
__global__ void split_all(const float* __restrict__ x0, __half* y0, int n0,
                          const float* __restrict__ x1, __half* y1, int n1,
                          const float* __restrict__ x2, __half* y2, int n2,
                          const float* __restrict__ x3, __half* y3, int n3,
                          const float* __restrict__ x4, __half* y4, int n4)
{
    int t = blockIdx.x * blockDim.x + threadIdx.x;
    const float* X; __half* Y;
    if      (t < n0)         { X = x0; Y = y0; }
    else if ((t -= n0) < n1) { X = x1; Y = y1; }
    else if ((t -= n1) < n2) { X = x2; Y = y2; }
    else if ((t -= n2) < n3) { X = x3; Y = y3; }
    else if ((t -= n3) < n4) { X = x4; Y = y4; }
    else return;
    float2 x = ((const float2*)X)[t];
    __half2 h = __floats2half2_rn(x.x, x.y);
    ((uint32_t*)Y)[t] = *(uint32_t*)&h;
}

// ---------------------------------------------------------------------------
// Fused indexed RoPE (fp16 out) + V fp16 convert, one launch.
// Q: hi/lo fp16 split (scaled); K: hi only.
// ---------------------------------------------------------------------------
__device__ __forceinline__ void do_rope(const float* X,
                                        __half* Xh, __half* Xl, bool write_lo,
                                        const float* cosT, const float* sinT,
                                        const int* idx, int nheads, int group,
                                        float scale, int t)
{
    int d = t % 48;
    int h = (t / 48) % nheads;
    int s = t / (48 * nheads);
    int hk = h / group;

    const float* base = X + (size_t)s * (nheads * HD) + h * HD;
    float x1 = base[d];
    float x2 = base[d + 48];

    int i1 = idx[hk * HD + d];
    int i2 = idx[hk * HD + d + 48];
    float c1 = cosT[s * DFULL + i1], s1 = sinT[s * DFULL + i1];
    float c2 = cosT[s * DFULL + i2], s2 = sinT[s * DFULL + i2];

    float lo = (x1 * c1 - x2 * s1) * scale;
    float hi = (x2 * c2 + x1 * s2) * scale;

    size_t o = (size_t)s * (nheads * HD) + h * HD;
    __half bh = __float2half_rn(lo);
    Xh[o + d] = bh;
    if (write_lo) Xl[o + d] = __float2half_rn(lo - __half2float(bh));
    bh = __float2half_rn(hi);
    Xh[o + d + 48] = bh;
    if (write_lo) Xl[o + d + 48] = __float2half_rn(hi - __half2float(bh));
}

__global__ void rope_split_all(
    const float* __restrict__ Qs, __half* Qh, __half* Ql,
    const float* __restrict__ Ks, __half* Kh,
    const float* __restrict__ Vs, __half* Vh,
    const float* __restrict__ cosT, const float* __restrict__ sinT,
    const int* __restrict__ idx, int totQ, int totK, int totVpairs)
{
    int t = blockIdx.x * blockDim.x + threadIdx.x;
    if (t < totQ) {
        do_rope(Qs, Qh, Ql, true, cosT, sinT, idx, NH, GROUPS, ATT_SCALE, t);
        return;
    }
    t -= totQ;
    if (t < totK) {
        do_rope(Ks, Kh, nullptr, false, cosT, sinT, idx, NKV, 1, 1.0f, t);
        return;
    }
    t -= totK;
    if (t < totVpairs) {
        float2 x = ((const float2*)Vs)[t];
        __half2 h = __floats2half2_rn(x.x, x.y);
        ((uint32_t*)Vh)[t] = *(uint32_t*)&h;
    }
}

// ---------------------------------------------------------------------------
// fp16 HMMA flash attention, causal GQA. CTA = 128 q-rows x 1 head, 8 warps.
// 64-key blocks, double-buffered cp.async KV stages (Kh + Vh fp16).
// S = QhKh + QlKh;  O += PhVh.  Epilogue writes flat fp16 AO.
// ---------------------------------------------------------------------------
#define FD   96
#define FBM  128
#define FBN  64
#define FROW 208
#define FQ_BYTES  (FBM * FROW)
#define FKV_BYTES (FBN * FROW)
#define STG_BYTES (2 * FKV_BYTES)
#define FLASH_SMEM (2 * FQ_BYTES + 2 * STG_BYTES)   // 106496

__device__ __forceinline__ void flash_load_kv(uint32_t st_base,
    const __half* Kh, const __half* Vh, int key0, int hk, int tid)
{
    const size_t goff = (size_t)key0 * (KVDIM * 2) + hk * (FD * 2);
    const char* g0 = (const char*)Kh + goff;
    const char* g1 = (const char*)Vh + goff;
#pragma unroll
    for (int i = 0; i < 3; i++) {
        int idx = tid + i * 256;
        int row = idx / 12, seg = idx - row * 12;
        uint32_t d = st_base + row * FROW + seg * 16;
        size_t go = (size_t)row * (KVDIM * 2) + seg * 16;
        CP_ASYNC16(d,             g0 + go);
        CP_ASYNC16(d + FKV_BYTES, g1 + go);
    }
}

__global__ __launch_bounds__(256, 1) void flash_mma(
    const __half* __restrict__ Qh, const __half* __restrict__ Ql,
    const __half* __restrict__ Kh, const __half* __restrict__ Vh,
    __half* __restrict__ AOs)
{
    extern __shared__ char smem[];
    const uint32_t sb = smem_u32(smem);
    const int tid = threadIdx.x, wid = tid >> 5, lane = tid & 31;
    const int h = blockIdx.y, hk = h / GROUPS;
    const int qbase = ((int)gridDim.x - 1 - (int)blockIdx.x) * FBM;  // heavy first
    const int nb = qbase / FBN + 2;

    const uint32_t sQh_ = sb, sQl_ = sb + FQ_BYTES;
    const uint32_t st0 = sb + 2 * FQ_BYTES;

    {
        const char* gqh = (const char*)(Qh + (size_t)qbase * QDIM + h * FD);
        const char* gql = (const char*)(Ql + (size_t)qbase * QDIM + h * FD);
#pragma unroll
        for (int i = 0; i < 6; i++) {
            int idx = tid + i * 256;
            int row = idx / 12, seg = idx - row * 12;
            uint32_t d = row * FROW + seg * 16;
            size_t go = (size_t)row * (QDIM * 2) + seg * 16;
            CP_ASYNC16(sQh_ + d, gqh + go);
            CP_ASYNC16(sQl_ + d, gql + go);
        }
        flash_load_kv(st0, Kh, Vh, 0, hk, tid);
        CP_COMMIT();
    }

    float oacc[12][4];
#pragma unroll
    for (int j = 0; j < 12; j++)
#pragma unroll
        for (int q = 0; q < 4; q++) oacc[j][q] = 0.f;
    float m0 = -CUDART_INF_F, m1 = -CUDART_INF_F, l0 = 0.f, l1 = 0.f;

    const int a_row = (lane & 7) + ((lane >> 3) & 1) * 8;
    const int a_cs  = ((lane >> 4) & 1) * 16;
    const int b_row = (lane & 7) + ((lane >> 4) & 1) * 8;
    const int b_cs  = ((lane >> 3) & 1) * 16;
    const int t_row = (lane & 7) + ((lane >> 3) & 1) * 8;
    const int t_cs  = ((lane >> 4) & 1) * 16;

    const int qr_lo = qbase + wid * 16;
    const int row0  = qr_lo + (lane >> 2);

    for (int kb = 0; kb < nb; kb++) {
        if (kb + 1 < nb) {
            flash_load_kv(st0 + ((kb + 1) & 1) * STG_BYTES, Kh, Vh,
                          (kb + 1) * FBN, hk, tid);
            CP_COMMIT();
            CP_WAIT(1);
        } else {
            CP_WAIT(0);
        }
        __syncthreads();

        const int key0 = kb * FBN;
        if (key0 <= qr_lo + 15) {
            const uint32_t sKh_ = st0 + (kb & 1) * STG_BYTES;
            const uint32_t sVh_ = sKh_ + FKV_BYTES;

            float sacc[8][4];
#pragma unroll
            for (int j = 0; j < 8; j++)
#pragma unroll
                for (int q = 0; q < 4; q++) sacc[j][q] = 0.f;

            // S = Qh*Kh + Ql*Kh
#pragma unroll
            for (int pass = 0; pass < 2; pass++) {
                const uint32_t sa = pass ? sQl_ : sQh_;
#pragma unroll
                for (int ks = 0; ks < 6; ks++) {
                    uint32_t a0, a1, a2, a3;
                    LDSM_X4(a0, a1, a2, a3,
                            sa + (wid * 16 + a_row) * FROW + ks * 32 + a_cs);
#pragma unroll
                    for (int p = 0; p < 4; p++) {
                        uint32_t b0, b1, b2, b3;
                        LDSM_X4(b0, b1, b2, b3,
                                sKh_ + (p * 16 + b_row) * FROW + ks * 32 + b_cs);
                        mma_f16(sacc[2 * p],     a0, a1, a2, a3, b0, b1);
                        mma_f16(sacc[2 * p + 1], a0, a1, a2, a3, b2, b3);
                    }
                }
            }

            if (key0 + FBN - 1 > qr_lo) {
#pragma unroll
                for (int j = 0; j < 8; j++) {
                    int kcol = key0 + 8 * j + (lane & 3) * 2;
                    if (kcol     > row0)     sacc[j][0] = -CUDART_INF_F;
                    if (kcol + 1 > row0)     sacc[j][1] = -CUDART_INF_F;
                    if (kcol     > row0 + 8) sacc[j][2] = -CUDART_INF_F;
                    if (kcol + 1 > row0 + 8) sacc[j][3] = -CUDART_INF_F;
                }
            }

            float mx0 = sacc[0][0], mx1 = sacc[0][2];
#pragma unroll
            for (int j = 0; j < 8; j++) {
                mx0 = fmaxf(mx0, fmaxf(sacc[j][0], sacc[j][1]));
                mx1 = fmaxf(mx1, fmaxf(sacc[j][2], sacc[j][3]));
            }
            mx0 = fmaxf(mx0, __shfl_xor_sync(0xffffffffu, mx0, 1));
            mx0 = fmaxf(mx0, __shfl_xor_sync(0xffffffffu, mx0, 2));
            mx1 = fmaxf(mx1, __shfl_xor_sync(0xffffffffu, mx1, 1));
            mx1 = fmaxf(mx1, __shfl_xor_sync(0xffffffffu, mx1, 2));

            float mn0 = fmaxf(m0, mx0), mn1 = fmaxf(m1, mx1);
            float al0 = __expf(m0 - mn0), al1 = __expf(m1 - mn1);

            uint32_t ph[8][2];
            float sum0 = 0.f, sum1 = 0.f;
#pragma unroll
            for (int j = 0; j < 8; j++) {
                float p0 = __expf(sacc[j][0] - mn0), p1 = __expf(sacc[j][1] - mn0);
                float p2 = __expf(sacc[j][2] - mn1), p3 = __expf(sacc[j][3] - mn1);
                sum0 += p0 + p1; sum1 += p2 + p3;
                __half2 h01 = __floats2half2_rn(p0, p1);
                __half2 h23 = __floats2half2_rn(p2, p3);
                ph[j][0] = *(uint32_t*)&h01;
                ph[j][1] = *(uint32_t*)&h23;
            }
            sum0 += __shfl_xor_sync(0xffffffffu, sum0, 1);
            sum0 += __shfl_xor_sync(0xffffffffu, sum0, 2);
            sum1 += __shfl_xor_sync(0xffffffffu, sum1, 1);
            sum1 += __shfl_xor_sync(0xffffffffu, sum1, 2);

            l0 = l0 * al0 + sum0;  l1 = l1 * al1 + sum1;
            m0 = mn0;              m1 = mn1;
#pragma unroll
            for (int j = 0; j < 12; j++) {
                oacc[j][0] *= al0; oacc[j][1] *= al0;
                oacc[j][2] *= al1; oacc[j][3] *= al1;
            }

            // O += Ph*Vh
#pragma unroll
            for (int kk = 0; kk < 4; kk++) {
                uint32_t a0 = ph[2 * kk][0], a1 = ph[2 * kk][1];
                uint32_t a2 = ph[2 * kk + 1][0], a3 = ph[2 * kk + 1][1];
#pragma unroll
                for (int p = 0; p < 6; p++) {
                    uint32_t vaddr = (16 * kk + t_row) * FROW + p * 32 + t_cs;
                    uint32_t b0, b1, b2, b3;
                    LDSM_X4_T(b0, b1, b2, b3, sVh_ + vaddr);
                    mma_f16(oacc[2 * p],     a0, a1, a2, a3, b0, b1);
                    mma_f16(oacc[2 * p + 1], a0, a1, a2, a3, b2, b3);
                }
            }
        }
        __syncthreads();
    }

    // epilogue: normalize + flat fp16 store (row = KP_O = QDIM)
    const float inv0 = 1.f / l0, inv1 = 1.f / l1;
    __half* ob0 = AOs + (size_t)row0 * KP_O + h * FD + (lane & 3) * 2;
    __half* ob1 = AOs + (size_t)(row0 + 8) * KP_O + h * FD + (lane & 3) * 2;
#pragma unroll
    for (int j = 0; j < 12; j++) {
        *(__half2*)(ob0 + j * 8) = __floats2half2_rn(oacc[j][0] * inv0, oacc[j][1] * inv0);
        *(__half2*)(ob1 + j * 8) = __floats2half2_rn(oacc[j][2] * inv1, oacc[j][3] * inv1);
    }
}

// ---------------------------------------------------------------------------
extern "C" void kernel_launch(void* const* d_in, const int* in_sizes, int n_in,
                              void* d_out, int out_size)
{
    const float* hs  = (const float*)d_in[0];
    const float* cs  = (const float*)d_in[1];
    const float* sn  = (const float*)d_in[2];
    const int*   idx = (const int*)  d_in[3];
    const float* Wq  = (const float*)d_in[4];
    const float* Wk  = (const float*)d_in[5];
    const float* Wv  = (const float*)d_in[6];
    const float* Wo  = (const float*)d_in[7];
    float* out = (float*)d_out;

    float *Qb, *Kb, *Vb;
    __half *hsb, *wqb, *wkb, *wvb, *aob, *wob;
    __half *qh, *ql, *kh, *vh;
    cudaGetSymbolAddress((void**)&Qb,  g_Q);
    cudaGetSymbolAddress((void**)&Kb,  g_K);
    cudaGetSymbolAddress((void**)&Vb,  g_V);
    cudaGetSymbolAddress((void**)&hsb, g_hsb);
    cudaGetSymbolAddress((void**)&wqb, g_wqb);
    cudaGetSymbolAddress((void**)&wkb, g_wkb);
    cudaGetSymbolAddress((void**)&wvb, g_wvb);
    cudaGetSymbolAddress((void**)&aob, g_aob);
    cudaGetSymbolAddress((void**)&wob, g_wob);
    cudaGetSymbolAddress((void**)&qh,  g_Qh);
    cudaGetSymbolAddress((void**)&ql,  g_Ql);
    cudaGetSymbolAddress((void**)&kh,  g_Kh);
    cudaGetSymbolAddress((void**)&vh,  g_Vh);

    static bool attr_set = false;
    if (!attr_set) {
        cudaFuncSetAttribute(gemm_mma,  cudaFuncAttributeMaxDynamicSharedMemorySize, GEMM_SMEM);
        cudaFuncSetAttribute(flash_mma, cudaFuncAttributeMaxDynamicSharedMemorySize, FLASH_SMEM);
        attr_set = true;
    }

    // fused flat fp16 conversions (one launch: hs + 4 weights)
    {
        const int n0 = S_LEN * HIDDEN / 2;
        const int n1 = QDIM  * HIDDEN / 2;
        const int n2 = KVDIM * HIDDEN / 2;
        const int n3 = KVDIM * HIDDEN / 2;
        const int n4 = HIDDEN * QDIM  / 2;
        const int tot = n0 + n1 + n2 + n3 + n4;
        split_all<<<(tot + 255) / 256, 256>>>(
            hs, hsb, n0,
            Wq, wqb, n1,
            Wk, wkb, n2,
            Wv, wvb, n3,
            Wo, wob, n4);
    }

    // fused QKV projection (fp16 1-term, K = HIDDEN)
    gemm_mma<<<dim3(36, S_LEN / BM), 128, GEMM_SMEM>>>(
        hsb,
        wqb, Qb, QDIM / BN,  QDIM,
        wkb, Kb, KVDIM / BN, KVDIM,
        wvb, Vb,             KVDIM,
        KP_QKV);

    // fused RoPE+split (Q h/l, K h) + V fp16 convert, one launch
    {
        const int totQ = S_LEN * NH  * 48;
        const int totK = S_LEN * NKV * 48;
        const int totV = S_LEN * KVDIM / 2;
        const int tot = totQ + totK + totV;
        rope_split_all<<<(tot + 255) / 256, 256>>>(
            Qb, qh, ql, Kb, kh, Vb, vh, cs, sn, idx, totQ, totK, totV);
    }

    // causal GQA attention — writes flat fp16 AO
    flash_mma<<<dim3(S_LEN / FBM, NH), 256, FLASH_SMEM>>>(qh, ql, kh, vh, aob);

    // output projection (fp16 1-term) -> d_out
    gemm_mma<<<dim3(HIDDEN / BN, S_LEN / BM), 128, GEMM_SMEM>>>(
        aob,
        wob, out, HIDDEN / BN, HIDDEN,
        wob, out, 0,           HIDDEN,
        wob, out,              HIDDEN,
        KP_O);
}

// round 15
// speedup vs baseline: 2.7811x; 1.0539x over previous
#include <cuda_runtime.h>
#include <cuda_bf16.h>
#include <cuda_fp16.h>
#include <math_constants.h>
#include <cstdint>

#define S_LEN  2048
#define HIDDEN 4096
#define NH     32
#define NKV    8
#define HD     96
#define GROUPS 4
#define QDIM   (NH * HD)    // 3072
#define KVDIM  (NKV * HD)   // 768
#define DFULL  128
#define ATT_SCALE 0.08838834764831845f  // 128^-0.5

#define KP_QKV HIDDEN         // 4096 (fp16 1-term)
#define KP_O   QDIM           // 3072 (fp16 1-term)

// ---------------- scratch (allocation-free: device globals) ----------------
static __device__ __align__(256) float g_Q [S_LEN * QDIM];
static __device__ __align__(256) float g_K [S_LEN * KVDIM];
static __device__ __align__(256) float g_V [S_LEN * KVDIM];

static __device__ __align__(256) __half g_hsb[S_LEN * KP_QKV];   // flat h
static __device__ __align__(256) __half g_wqb[QDIM * KP_QKV];    // flat h
static __device__ __align__(256) __half g_wkb[KVDIM * KP_QKV];
static __device__ __align__(256) __half g_wvb[KVDIM * KP_QKV];
static __device__ __align__(256) __half g_aob[S_LEN * KP_O];     // flat h
static __device__ __align__(256) __half g_wob[HIDDEN * KP_O];    // flat h

// flash operands (all fp16; Q keeps hi/lo)
static __device__ __align__(256) __half g_Qh[S_LEN * QDIM];
static __device__ __align__(256) __half g_Ql[S_LEN * QDIM];
static __device__ __align__(256) __half g_Kh[S_LEN * KVDIM];
static __device__ __align__(256) __half g_Vh[S_LEN * KVDIM];

// ---------------------------------------------------------------------------
// PTX helpers
// ---------------------------------------------------------------------------
__device__ __forceinline__ uint32_t smem_u32(const void* p) {
    uint32_t a;
    asm("{ .reg .u64 t; cvta.to.shared.u64 t, %1; cvt.u32.u64 %0, t; }" : "=r"(a) : "l"(p));
    return a;
}
#define CP_ASYNC16(dst, src) asm volatile("cp.async.cg.shared.global [%0], [%1], 16;" :: "r"(dst), "l"(src))
#define CP_COMMIT()          asm volatile("cp.async.commit_group;" ::: "memory")
#define CP_WAIT(n)           asm volatile("cp.async.wait_group %0;" :: "n"(n) : "memory")

#define LDSM_X4(r0, r1, r2, r3, addr)                                            \
    asm volatile("ldmatrix.sync.aligned.m8n8.x4.shared.b16 {%0,%1,%2,%3}, [%4];" \
        : "=r"(r0), "=r"(r1), "=r"(r2), "=r"(r3) : "r"(addr))

#define LDSM_X4_T(r0, r1, r2, r3, addr)                                                \
    asm volatile("ldmatrix.sync.aligned.m8n8.x4.trans.shared.b16 {%0,%1,%2,%3}, [%4];" \
        : "=r"(r0), "=r"(r1), "=r"(r2), "=r"(r3) : "r"(addr))

__device__ __forceinline__ void mma_f16(float* c, uint32_t a0, uint32_t a1,
                                        uint32_t a2, uint32_t a3,
                                        uint32_t b0, uint32_t b1) {
    asm volatile(
        "mma.sync.aligned.m16n8k16.row.col.f32.f16.f16.f32 "
        "{%0,%1,%2,%3}, {%4,%5,%6,%7}, {%8,%9}, {%0,%1,%2,%3};"
        : "+f"(c[0]), "+f"(c[1]), "+f"(c[2]), "+f"(c[3])
        : "r"(a0), "r"(a1), "r"(a2), "r"(a3), "r"(b0), "r"(b1));
}

// ---------------------------------------------------------------------------
// fp16 HMMA GEMM.
// BM=128, BN=128, BK=64, 2-stage cp.async pipeline, 4 warps, warp tile 64x64.
// launch_bounds(128,3) -> 3 CTAs/SM. Segmented over N (up to 3 segments).
// ---------------------------------------------------------------------------
#define BM 128
#define BN 128
#define BKE 64
#define ROW_B 144
#define TILE_BYTES (128 * ROW_B)
#define STAGE_BYTES (2 * TILE_BYTES)
#define NSTAGE 2
#define GEMM_SMEM (NSTAGE * STAGE_BYTES)   // 73728

__device__ __forceinline__ void load_tiles(uint32_t stage_base,
    const __half* __restrict__ A, const __half* __restrict__ B,
    int bm, int bn, int kc, int Kp, int tid)
{
    const char* Ag = (const char*)(A + (size_t)bm * Kp + kc * BKE);
    const char* Bg = (const char*)(B + (size_t)bn * Kp + kc * BKE);
    const size_t rowb = (size_t)Kp * 2;
    const uint32_t sA = stage_base;
    const uint32_t sB = stage_base + TILE_BYTES;
#pragma unroll
    for (int i = 0; i < 8; i++) {
        int idx = tid + i * 128;
        int row = idx >> 3, seg = idx & 7;
        CP_ASYNC16(sA + row * ROW_B + seg * 16, Ag + (size_t)row * rowb + seg * 16);
    }
#pragma unroll
    for (int i = 0; i < 8; i++) {
        int idx = tid + i * 128;
        int row = idx >> 3, seg = idx & 7;
        CP_ASYNC16(sB + row * ROW_B + seg * 16, Bg + (size_t)row * rowb + seg * 16);
    }
}

__global__ __launch_bounds__(128, 3) void gemm_mma(
    const __half* __restrict__ A,
    const __half* __restrict__ B0, float* __restrict__ C0, int nt0, int N0,
    const __half* __restrict__ B1, float* __restrict__ C1, int nt1, int N1,
    const __half* __restrict__ B2, float* __restrict__ C2, int N2,
    int Kp)
{
    extern __shared__ char smem[];
    const uint32_t sbase = smem_u32(smem);
    const int tid  = threadIdx.x;
    const int wid  = tid >> 5;
    const int lane = tid & 31;
    const int bm   = blockIdx.y * BM;
    const int NC   = Kp / BKE;

    int bnt = blockIdx.x;
    const __half* B;
    float* C; int N;
    if (bnt < nt0)            { B = B0; C = C0; N = N0; }
    else if (bnt < nt0 + nt1) { B = B1; C = C1; N = N1; bnt -= nt0; }
    else                      { B = B2; C = C2; N = N2; bnt -= nt0 + nt1; }
    const int bn = bnt * BN;

    const int wm = (wid >> 1) * 64;
    const int wn = (wid & 1) * 64;

    float acc[4][8][4];
#pragma unroll
    for (int t = 0; t < 4; t++)
#pragma unroll
        for (int j = 0; j < 8; j++)
#pragma unroll
            for (int q = 0; q < 4; q++) acc[t][j][q] = 0.f;

    const int a_row    = ((lane >> 3) & 1) * 8 + (lane & 7);
    const int a_cshift = ((lane >> 4) & 1) * 16;
    const int b_row    = ((lane >> 4) & 1) * 8 + (lane & 7);
    const int b_cshift = ((lane >> 3) & 1) * 16;

    load_tiles(sbase, A, B, bm, bn, 0, Kp, tid); CP_COMMIT();

    for (int c = 0; c < NC; c++) {
        CP_WAIT(0);
        __syncthreads();

        if (c + 1 < NC) {
            load_tiles(sbase + ((c + 1) & 1) * STAGE_BYTES, A, B, bm, bn, c + 1, Kp, tid);
            CP_COMMIT();
        }

        const uint32_t sA = sbase + (c & 1) * STAGE_BYTES;
        const uint32_t sB = sA + TILE_BYTES;
#pragma unroll
        for (int ks = 0; ks < 4; ks++) {
            uint32_t a[4][4];
#pragma unroll
            for (int t = 0; t < 4; t++) {
                uint32_t addr = sA + (wm + t * 16 + a_row) * ROW_B + ks * 32 + a_cshift;
                LDSM_X4(a[t][0], a[t][1], a[t][2], a[t][3], addr);
            }
#pragma unroll
            for (int p = 0; p < 4; p++) {
                uint32_t b0, b1, b2, b3;
                uint32_t addr = sB + (wn + p * 16 + b_row) * ROW_B + ks * 32 + b_cshift;
                LDSM_X4(b0, b1, b2, b3, addr);
#pragma unroll
                for (int t = 0; t < 4; t++) {
                    mma_f16(acc[t][2 * p],     a[t][0], a[t][1], a[t][2], a[t][3], b0, b1);
                    mma_f16(acc[t][2 * p + 1], a[t][0], a[t][1], a[t][2], a[t][3], b2, b3);
                }
            }
        }
    }

#pragma unroll
    for (int t = 0; t < 4; t++) {
        const int r0 = bm + wm + t * 16 + (lane >> 2);
#pragma unroll
        for (int j = 0; j < 8; j++) {
            const int col = bn + wn + j * 8 + (lane & 3) * 2;
            float* c0 = C + (size_t)r0 * N + col;
            float* c1 = C + (size_t)(r0 + 8) * N + col;
            *(float2*)c0 = make_float2(acc[t][j][0], acc[t][j][1]);
            *(float2*)c1 = make_float2(acc[t][j][2], acc[t][j][3]);
        }
    }
}

// ---------------------------------------------------------------------------
// Fused flat fp32 -> fp16 conversions over 5 regions, float4-vectorized
// (4 elements per thread), one launch. All region sizes divisible by 4.
// ---------------------------------------------------------------------------
__global__ void split_all(const float* __restrict__ x0, __half* y0, int n0,
                          const float* __restrict__ x1, __half* y1, int n1,
                          const float* __restrict__ x2, __half* y2, int n2,
                          const float* __restrict__ x3, __half* y3, int n3,
                          const float* __restrict__ x4, __half* y4, int n4)
{
    int t = blockIdx.x * blockDim.x + threadIdx.x;   // quad index
    const float* X; __half* Y;
    if      (t < n0)         { X = x0; Y = y0; }
    else if ((t -= n0) < n1) { X = x1; Y = y1; }
    else if ((t -= n1) < n2) { X = x2; Y = y2; }
    else if ((t -= n2) < n3) { X = x3; Y = y3; }
    else if ((t -= n3) < n4) { X = x4; Y = y4; }
    else return;
    float4 x = ((const float4*)X)[t];
    __half2 h0 = __floats2half2_rn(x.x, x.y);
    __half2 h1 = __floats2half2_rn(x.z, x.w);
    uint2 v;
    v.x = *(uint32_t*)&h0;
    v.y = *(uint32_t*)&h1;
    ((uint2*)Y)[t] = v;
}

// ---------------------------------------------------------------------------
// Fused indexed RoPE (fp16 out) + V fp16 convert, one launch.
// Q: hi/lo fp16 split (scaled); K: hi only.
// ---------------------------------------------------------------------------
__device__ __forceinline__ void do_rope(const float* X,
                                        __half* Xh, __half* Xl, bool write_lo,
                                        const float* cosT, const float* sinT,
                                        const int* idx, int nheads, int group,
                                        float scale, int t)
{
    int d = t % 48;
    int h = (t / 48) % nheads;
    int s = t / (48 * nheads);
    int hk = h / group;

    const float* base = X + (size_t)s * (nheads * HD) + h * HD;
    float x1 = base[d];
    float x2 = base[d + 48];

    int i1 = idx[hk * HD + d];
    int i2 = idx[hk * HD + d + 48];
    float c1 = cosT[s * DFULL + i1], s1 = sinT[s * DFULL + i1];
    float c2 = cosT[s * DFULL + i2], s2 = sinT[s * DFULL + i2];

    float lo = (x1 * c1 - x2 * s1) * scale;
    float hi = (x2 * c2 + x1 * s2) * scale;

    size_t o = (size_t)s * (nheads * HD) + h * HD;
    __half bh = __float2half_rn(lo);
    Xh[o + d] = bh;
    if (write_lo) Xl[o + d] = __float2half_rn(lo - __half2float(bh));
    bh = __float2half_rn(hi);
    Xh[o + d + 48] = bh;
    if (write_lo) Xl[o + d + 48] = __float2half_rn(hi - __half2float(bh));
}

__global__ void rope_split_all(
    const float* __restrict__ Qs, __half* Qh, __half* Ql,
    const float* __restrict__ Ks, __half* Kh,
    const float* __restrict__ Vs, __half* Vh,
    const float* __restrict__ cosT, const float* __restrict__ sinT,
    const int* __restrict__ idx, int totQ, int totK, int totVpairs)
{
    int t = blockIdx.x * blockDim.x + threadIdx.x;
    if (t < totQ) {
        do_rope(Qs, Qh, Ql, true, cosT, sinT, idx, NH, GROUPS, ATT_SCALE, t);
        return;
    }
    t -= totQ;
    if (t < totK) {
        do_rope(Ks, Kh, nullptr, false, cosT, sinT, idx, NKV, 1, 1.0f, t);
        return;
    }
    t -= totK;
    if (t < totVpairs) {
        float2 x = ((const float2*)Vs)[t];
        __half2 h = __floats2half2_rn(x.x, x.y);
        ((uint32_t*)Vh)[t] = *(uint32_t*)&h;
    }
}

// ---------------------------------------------------------------------------
// fp16 HMMA flash attention, causal GQA. CTA = 128 q-rows x 1 head, 8 warps.
// 64-key blocks, double-buffered cp.async KV stages (Kh + Vh fp16).
// S = QhKh + QlKh with MERGED passes (each K b-tile loaded once, feeds both
// Qh and Ql MMAs);  O += PhVh.  Epilogue writes flat fp16 AO.
// ---------------------------------------------------------------------------
#define FD   96
#define FBM  128
#define FBN  64
#define FROW 208
#define FQ_BYTES  (FBM * FROW)
#define FKV_BYTES (FBN * FROW)
#define STG_BYTES (2 * FKV_BYTES)
#define FLASH_SMEM (2 * FQ_BYTES + 2 * STG_BYTES)   // 106496

__device__ __forceinline__ void flash_load_kv(uint32_t st_base,
    const __half* Kh, const __half* Vh, int key0, int hk, int tid)
{
    const size_t goff = (size_t)key0 * (KVDIM * 2) + hk * (FD * 2);
    const char* g0 = (const char*)Kh + goff;
    const char* g1 = (const char*)Vh + goff;
#pragma unroll
    for (int i = 0; i < 3; i++) {
        int idx = tid + i * 256;
        int row = idx / 12, seg = idx - row * 12;
        uint32_t d = st_base + row * FROW + seg * 16;
        size_t go = (size_t)row * (KVDIM * 2) + seg * 16;
        CP_ASYNC16(d,             g0 + go);
        CP_ASYNC16(d + FKV_BYTES, g1 + go);
    }
}

__global__ __launch_bounds__(256, 1) void flash_mma(
    const __half* __restrict__ Qh, const __half* __restrict__ Ql,
    const __half* __restrict__ Kh, const __half* __restrict__ Vh,
    __half* __restrict__ AOs)
{
    extern __shared__ char smem[];
    const uint32_t sb = smem_u32(smem);
    const int tid = threadIdx.x, wid = tid >> 5, lane = tid & 31;
    const int h = blockIdx.y, hk = h / GROUPS;
    const int qbase = ((int)gridDim.x - 1 - (int)blockIdx.x) * FBM;  // heavy first
    const int nb = qbase / FBN + 2;

    const uint32_t sQh_ = sb, sQl_ = sb + FQ_BYTES;
    const uint32_t st0 = sb + 2 * FQ_BYTES;

    {
        const char* gqh = (const char*)(Qh + (size_t)qbase * QDIM + h * FD);
        const char* gql = (const char*)(Ql + (size_t)qbase * QDIM + h * FD);
#pragma unroll
        for (int i = 0; i < 6; i++) {
            int idx = tid + i * 256;
            int row = idx / 12, seg = idx - row * 12;
            uint32_t d = row * FROW + seg * 16;
            size_t go = (size_t)row * (QDIM * 2) + seg * 16;
            CP_ASYNC16(sQh_ + d, gqh + go);
            CP_ASYNC16(sQl_ + d, gql + go);
        }
        flash_load_kv(st0, Kh, Vh, 0, hk, tid);
        CP_COMMIT();
    }

    float oacc[12][4];
#pragma unroll
    for (int j = 0; j < 12; j++)
#pragma unroll
        for (int q = 0; q < 4; q++) oacc[j][q] = 0.f;
    float m0 = -CUDART_INF_F, m1 = -CUDART_INF_F, l0 = 0.f, l1 = 0.f;

    const int a_row = (lane & 7) + ((lane >> 3) & 1) * 8;
    const int a_cs  = ((lane >> 4) & 1) * 16;
    const int b_row = (lane & 7) + ((lane >> 4) & 1) * 8;
    const int b_cs  = ((lane >> 3) & 1) * 16;
    const int t_row = (lane & 7) + ((lane >> 3) & 1) * 8;
    const int t_cs  = ((lane >> 4) & 1) * 16;

    const int qr_lo = qbase + wid * 16;
    const int row0  = qr_lo + (lane >> 2);

    for (int kb = 0; kb < nb; kb++) {
        if (kb + 1 < nb) {
            flash_load_kv(st0 + ((kb + 1) & 1) * STG_BYTES, Kh, Vh,
                          (kb + 1) * FBN, hk, tid);
            CP_COMMIT();
            CP_WAIT(1);
        } else {
            CP_WAIT(0);
        }
        __syncthreads();

        const int key0 = kb * FBN;
        if (key0 <= qr_lo + 15) {
            const uint32_t sKh_ = st0 + (kb & 1) * STG_BYTES;
            const uint32_t sVh_ = sKh_ + FKV_BYTES;

            float sacc[8][4];
#pragma unroll
            for (int j = 0; j < 8; j++)
#pragma unroll
                for (int q = 0; q < 4; q++) sacc[j][q] = 0.f;

            // S = Qh*Kh + Ql*Kh, merged: each b-tile loaded once
#pragma unroll
            for (int ks = 0; ks < 6; ks++) {
                uint32_t ah0, ah1, ah2, ah3, al0, al1, al2, al3;
                const uint32_t arow_off = (wid * 16 + a_row) * FROW + ks * 32 + a_cs;
                LDSM_X4(ah0, ah1, ah2, ah3, sQh_ + arow_off);
                LDSM_X4(al0, al1, al2, al3, sQl_ + arow_off);
#pragma unroll
                for (int p = 0; p < 4; p++) {
                    uint32_t b0, b1, b2, b3;
                    LDSM_X4(b0, b1, b2, b3,
                            sKh_ + (p * 16 + b_row) * FROW + ks * 32 + b_cs);
                    mma_f16(sacc[2 * p],     ah0, ah1, ah2, ah3, b0, b1);
                    mma_f16(sacc[2 * p + 1], ah0, ah1, ah2, ah3, b2, b3);
                    mma_f16(sacc[2 * p],     al0, al1, al2, al3, b0, b1);
                    mma_f16(sacc[2 * p + 1], al0, al1, al2, al3, b2, b3);
                }
            }

            if (key0 + FBN - 1 > qr_lo) {
#pragma unroll
                for (int j = 0; j < 8; j++) {
                    int kcol = key0 + 8 * j + (lane & 3) * 2;
                    if (kcol     > row0)     sacc[j][0] = -CUDART_INF_F;
                    if (kcol + 1 > row0)     sacc[j][1] = -CUDART_INF_F;
                    if (kcol     > row0 + 8) sacc[j][2] = -CUDART_INF_F;
                    if (kcol + 1 > row0 + 8) sacc[j][3] = -CUDART_INF_F;
                }
            }

            float mx0 = sacc[0][0], mx1 = sacc[0][2];
#pragma unroll
            for (int j = 0; j < 8; j++) {
                mx0 = fmaxf(mx0, fmaxf(sacc[j][0], sacc[j][1]));
                mx1 = fmaxf(mx1, fmaxf(sacc[j][2], sacc[j][3]));
            }
            mx0 = fmaxf(mx0, __shfl_xor_sync(0xffffffffu, mx0, 1));
            mx0 = fmaxf(mx0, __shfl_xor_sync(0xffffffffu, mx0, 2));
            mx1 = fmaxf(mx1, __shfl_xor_sync(0xffffffffu, mx1, 1));
            mx1 = fmaxf(mx1, __shfl_xor_sync(0xffffffffu, mx1, 2));

            float mn0 = fmaxf(m0, mx0), mn1 = fmaxf(m1, mx1);
            float al0 = __expf(m0 - mn0), al1 = __expf(m1 - mn1);

            uint32_t ph[8][2];
            float sum0 = 0.f, sum1 = 0.f;
#pragma unroll
            for (int j = 0; j < 8; j++) {
                float p0 = __expf(sacc[j][0] - mn0), p1 = __expf(sacc[j][1] - mn0);
                float p2 = __expf(sacc[j][2] - mn1), p3 = __expf(sacc[j][3] - mn1);
                sum0 += p0 + p1; sum1 += p2 + p3;
                __half2 h01 = __floats2half2_rn(p0, p1);
                __half2 h23 = __floats2half2_rn(p2, p3);
                ph[j][0] = *(uint32_t*)&h01;
                ph[j][1] = *(uint32_t*)&h23;
            }
            sum0 += __shfl_xor_sync(0xffffffffu, sum0, 1);
            sum0 += __shfl_xor_sync(0xffffffffu, sum0, 2);
            sum1 += __shfl_xor_sync(0xffffffffu, sum1, 1);
            sum1 += __shfl_xor_sync(0xffffffffu, sum1, 2);

            l0 = l0 * al0 + sum0;  l1 = l1 * al1 + sum1;
            m0 = mn0;              m1 = mn1;
#pragma unroll
            for (int j = 0; j < 12; j++) {
                oacc[j][0] *= al0; oacc[j][1] *= al0;
                oacc[j][2] *= al1; oacc[j][3] *= al1;
            }

            // O += Ph*Vh
#pragma unroll
            for (int kk = 0; kk < 4; kk++) {
                uint32_t a0 = ph[2 * kk][0], a1 = ph[2 * kk][1];
                uint32_t a2 = ph[2 * kk + 1][0], a3 = ph[2 * kk + 1][1];
#pragma unroll
                for (int p = 0; p < 6; p++) {
                    uint32_t vaddr = (16 * kk + t_row) * FROW + p * 32 + t_cs;
                    uint32_t b0, b1, b2, b3;
                    LDSM_X4_T(b0, b1, b2, b3, sVh_ + vaddr);
                    mma_f16(oacc[2 * p],     a0, a1, a2, a3, b0, b1);
                    mma_f16(oacc[2 * p + 1], a0, a1, a2, a3, b2, b3);
                }
            }
        }
        __syncthreads();
    }

    // epilogue: normalize + flat fp16 store (row = KP_O = QDIM)
    const float inv0 = 1.f / l0, inv1 = 1.f / l1;
    __half* ob0 = AOs + (size_t)row0 * KP_O + h * FD + (lane & 3) * 2;
    __half* ob1 = AOs + (size_t)(row0 + 8) * KP_O + h * FD + (lane & 3) * 2;
#pragma unroll
    for (int j = 0; j < 12; j++) {
        *(__half2*)(ob0 + j * 8) = __floats2half2_rn(oacc[j][0] * inv0, oacc[j][1] * inv0);
        *(__half2*)(ob1 + j * 8) = __floats2half2_rn(oacc[j][2] * inv1, oacc[j][3] * inv1);
    }
}

// ---------------------------------------------------------------------------
extern "C" void kernel_launch(void* const* d_in, const int* in_sizes, int n_in,
                              void* d_out, int out_size)
{
    const float* hs  = (const float*)d_in[0];
    const float* cs  = (const float*)d_in[1];
    const float* sn  = (const float*)d_in[2];
    const int*   idx = (const int*)  d_in[3];
    const float* Wq  = (const float*)d_in[4];
    const float* Wk  = (const float*)d_in[5];
    const float* Wv  = (const float*)d_in[6];
    const float* Wo  = (const float*)d_in[7];
    float* out = (float*)d_out;

    float *Qb, *Kb, *Vb;
    __half *hsb, *wqb, *wkb, *wvb, *aob, *wob;
    __half *qh, *ql, *kh, *vh;
    cudaGetSymbolAddress((void**)&Qb,  g_Q);
    cudaGetSymbolAddress((void**)&Kb,  g_K);
    cudaGetSymbolAddress((void**)&Vb,  g_V);
    cudaGetSymbolAddress((void**)&hsb, g_hsb);
    cudaGetSymbolAddress((void**)&wqb, g_wqb);
    cudaGetSymbolAddress((void**)&wkb, g_wkb);
    cudaGetSymbolAddress((void**)&wvb, g_wvb);
    cudaGetSymbolAddress((void**)&aob, g_aob);
    cudaGetSymbolAddress((void**)&wob, g_wob);
    cudaGetSymbolAddress((void**)&qh,  g_Qh);
    cudaGetSymbolAddress((void**)&ql,  g_Ql);
    cudaGetSymbolAddress((void**)&kh,  g_Kh);
    cudaGetSymbolAddress((void**)&vh,  g_Vh);

    static bool attr_set = false;
    if (!attr_set) {
        cudaFuncSetAttribute(gemm_mma,  cudaFuncAttributeMaxDynamicSharedMemorySize, GEMM_SMEM);
        cudaFuncSetAttribute(flash_mma, cudaFuncAttributeMaxDynamicSharedMemorySize, FLASH_SMEM);
        attr_set = true;
    }

    // fused flat fp16 conversions (one launch, float4-vectorized)
    {
        const int n0 = S_LEN * HIDDEN / 4;
        const int n1 = QDIM  * HIDDEN / 4;
        const int n2 = KVDIM * HIDDEN / 4;
        const int n3 = KVDIM * HIDDEN / 4;
        const int n4 = HIDDEN * QDIM  / 4;
        const int tot = n0 + n1 + n2 + n3 + n4;
        split_all<<<(tot + 255) / 256, 256>>>(
            hs, hsb, n0,
            Wq, wqb, n1,
            Wk, wkb, n2,
            Wv, wvb, n3,
            Wo, wob, n4);
    }

    // fused QKV projection (fp16 1-term, K = HIDDEN)
    gemm_mma<<<dim3(36, S_LEN / BM), 128, GEMM_SMEM>>>(
        hsb,
        wqb, Qb, QDIM / BN,  QDIM,
        wkb, Kb, KVDIM / BN, KVDIM,
        wvb, Vb,             KVDIM,
        KP_QKV);

    // fused RoPE+split (Q h/l, K h) + V fp16 convert, one launch
    {
        const int totQ = S_LEN * NH  * 48;
        const int totK = S_LEN * NKV * 48;
        const int totV = S_LEN * KVDIM / 2;
        const int tot = totQ + totK + totV;
        rope_split_all<<<(tot + 255) / 256, 256>>>(
            Qb, qh, ql, Kb, kh, Vb, vh, cs, sn, idx, totQ, totK, totV);
    }

    // causal GQA attention — writes flat fp16 AO
    flash_mma<<<dim3(S_LEN / FBM, NH), 256, FLASH_SMEM>>>(qh, ql, kh, vh, aob);

    // output projection (fp16 1-term) -> d_out
    gemm_mma<<<dim3(HIDDEN / BN, S_LEN / BM), 128, GEMM_SMEM>>>(
        aob,
        wob, out, HIDDEN / BN, HIDDEN,
        wob, out, 0,           HIDDEN,
        wob, out,              HIDDEN,
        KP_O);
}